// round 1
// baseline (speedup 1.0000x reference)
#include <cuda_runtime.h>
#include <math.h>

#define BB   4
#define SS   2048
#define DIMM 1024
#define HH   16
#define KVHH 4
#define HDD  64
#define KVD  256
#define MROWS (BB*SS)   // 8192

// Scratch (device globals — no allocations allowed)
__device__ float g_q[(size_t)MROWS * DIMM];   // 32 MB
__device__ float g_k[(size_t)MROWS * KVD];    //  8 MB
__device__ float g_v[(size_t)MROWS * KVD];    //  8 MB
__device__ float g_y[(size_t)MROWS * DIMM];   // 32 MB

// ---------------------------------------------------------------------------
// Generic GEMM: C[M,N] = A[M,K] @ W[N,K]^T   (A,W,C row-major, fp32)
// 64x64 tile, BK=16, 256 threads, 4x4 micro-tile per thread.
// M,N multiples of 64; K multiple of 16.
// ---------------------------------------------------------------------------
__global__ void __launch_bounds__(256)
gemm_kernel(const float* __restrict__ A, const float* __restrict__ W,
            float* __restrict__ C, int M, int N, int K)
{
    __shared__ float As[16][65];
    __shared__ float Ws[16][65];

    const int tid = threadIdx.x;
    const int tx = tid & 15;       // 0..15 -> N
    const int ty = tid >> 4;       // 0..15 -> M
    const int bm = blockIdx.y * 64;
    const int bn = blockIdx.x * 64;

    float acc[4][4];
#pragma unroll
    for (int i = 0; i < 4; i++)
#pragma unroll
        for (int j = 0; j < 4; j++) acc[i][j] = 0.f;

    for (int k0 = 0; k0 < K; k0 += 16) {
#pragma unroll
        for (int r = 0; r < 4; r++) {
            int i = tid + r * 256;
            int m = i >> 4, kk = i & 15;
            As[kk][m] = A[(size_t)(bm + m) * K + k0 + kk];
        }
#pragma unroll
        for (int r = 0; r < 4; r++) {
            int i = tid + r * 256;
            int n = i >> 4, kk = i & 15;
            Ws[kk][n] = W[(size_t)(bn + n) * K + k0 + kk];
        }
        __syncthreads();

#pragma unroll
        for (int kk = 0; kk < 16; kk++) {
            float a0 = As[kk][ty * 4 + 0];
            float a1 = As[kk][ty * 4 + 1];
            float a2 = As[kk][ty * 4 + 2];
            float a3 = As[kk][ty * 4 + 3];
            float w0 = Ws[kk][tx * 4 + 0];
            float w1 = Ws[kk][tx * 4 + 1];
            float w2 = Ws[kk][tx * 4 + 2];
            float w3 = Ws[kk][tx * 4 + 3];
            acc[0][0] = fmaf(a0, w0, acc[0][0]);
            acc[0][1] = fmaf(a0, w1, acc[0][1]);
            acc[0][2] = fmaf(a0, w2, acc[0][2]);
            acc[0][3] = fmaf(a0, w3, acc[0][3]);
            acc[1][0] = fmaf(a1, w0, acc[1][0]);
            acc[1][1] = fmaf(a1, w1, acc[1][1]);
            acc[1][2] = fmaf(a1, w2, acc[1][2]);
            acc[1][3] = fmaf(a1, w3, acc[1][3]);
            acc[2][0] = fmaf(a2, w0, acc[2][0]);
            acc[2][1] = fmaf(a2, w1, acc[2][1]);
            acc[2][2] = fmaf(a2, w2, acc[2][2]);
            acc[2][3] = fmaf(a2, w3, acc[2][3]);
            acc[3][0] = fmaf(a3, w0, acc[3][0]);
            acc[3][1] = fmaf(a3, w1, acc[3][1]);
            acc[3][2] = fmaf(a3, w2, acc[3][2]);
            acc[3][3] = fmaf(a3, w3, acc[3][3]);
        }
        __syncthreads();
    }

#pragma unroll
    for (int i = 0; i < 4; i++) {
        float4 o = make_float4(acc[i][0], acc[i][1], acc[i][2], acc[i][3]);
        *(float4*)(&C[(size_t)(bm + ty * 4 + i) * N + bn + tx * 4]) = o;
    }
}

// ---------------------------------------------------------------------------
// Fused per-head RMSNorm + RoPE + optional gain.  In-place.
// t: [MROWS, nheads*64].  One warp per (row, head); lane d handles (d, d+32).
// ---------------------------------------------------------------------------
__global__ void norm_rope_kernel(float* __restrict__ t, int nheads,
                                 const float* __restrict__ gain)
{
    const int row = blockIdx.x;
    const int h = blockIdx.y * blockDim.y + threadIdx.y;
    const int s = row & (SS - 1);
    const int d = threadIdx.x;   // 0..31

    float* p = t + (size_t)row * (nheads * 64) + h * 64;
    float t1 = p[d];
    float t2 = p[d + 32];

    float ss = t1 * t1 + t2 * t2;
#pragma unroll
    for (int o = 16; o; o >>= 1) ss += __shfl_xor_sync(0xffffffffu, ss, o);
    float r = rsqrtf(ss * (1.0f / 64.0f) + 1e-6f);
    t1 *= r; t2 *= r;

    // inv_freq = 10000^(-d/32) = exp2(-d * log2(10000)/32)
    float inv_freq = exp2f(-(float)d * (13.287712379549449f / 32.0f));
    float th = (float)s * inv_freq;
    float c, sn;
    sincosf(th, &sn, &c);

    float g = gain ? gain[h] : 1.0f;
    p[d]      = ( t1 * c + t2 * sn) * g;
    p[d + 32] = (-t1 * sn + t2 * c) * g;
}

// ---------------------------------------------------------------------------
// Causal GQA flash attention.
// grid: (S/64, H, B); 64 threads, one query row per thread.
// K/V tiles 64x64 fp32 in SMEM; online softmax in 16-key chunks.
// ---------------------------------------------------------------------------
__global__ void __launch_bounds__(64)
attn_kernel(const float* __restrict__ q, const float* __restrict__ k,
            const float* __restrict__ v, float* __restrict__ y)
{
    __shared__ float Ks[64][64];
    __shared__ float Vs[64][64];

    const int qb = blockIdx.x;
    const int h  = blockIdx.y;
    const int b  = blockIdx.z;
    const int kvh = h >> 2;     // H/KVH = 4
    const int t = threadIdx.x;
    const int qi = qb * 64 + t;

    const size_t qoff = ((size_t)b * SS + qi) * DIMM + h * 64;
    float qr[64];
#pragma unroll
    for (int d4 = 0; d4 < 16; d4++) {
        float4 qq = *(const float4*)(q + qoff + 4 * d4);
        qr[4 * d4 + 0] = qq.x * 0.125f;  // 1/sqrt(64)
        qr[4 * d4 + 1] = qq.y * 0.125f;
        qr[4 * d4 + 2] = qq.z * 0.125f;
        qr[4 * d4 + 3] = qq.w * 0.125f;
    }

    float m = -INFINITY, l = 0.f;
    float acc[64];
#pragma unroll
    for (int d = 0; d < 64; d++) acc[d] = 0.f;

    for (int kb = 0; kb <= qb; kb++) {
        const float* kbase = k + ((size_t)b * SS + kb * 64) * KVD + kvh * 64;
        const float* vbase = v + ((size_t)b * SS + kb * 64) * KVD + kvh * 64;
        // cooperative float4 tile load (coalesced: 16 lanes cover one 64-float row)
        for (int i = t; i < 64 * 16; i += 64) {
            int j = i >> 4, d4 = i & 15;
            ((float4*)Ks[j])[d4] = *(const float4*)(kbase + (size_t)j * KVD + 4 * d4);
            ((float4*)Vs[j])[d4] = *(const float4*)(vbase + (size_t)j * KVD + 4 * d4);
        }
        __syncthreads();

        const int jmax = (kb == qb) ? (t + 1) : 64;   // valid keys in this tile
        for (int c0 = 0; c0 < jmax; c0 += 16) {
            float s[16];
#pragma unroll
            for (int jj = 0; jj < 16; jj++) {
                const float4* kr = (const float4*)Ks[c0 + jj];
                float ss = 0.f;
#pragma unroll
                for (int d4 = 0; d4 < 16; d4++) {
                    float4 kk = kr[d4];
                    ss = fmaf(qr[4 * d4 + 0], kk.x, ss);
                    ss = fmaf(qr[4 * d4 + 1], kk.y, ss);
                    ss = fmaf(qr[4 * d4 + 2], kk.z, ss);
                    ss = fmaf(qr[4 * d4 + 3], kk.w, ss);
                }
                s[jj] = (c0 + jj < jmax) ? ss : -INFINITY;
            }
            float mt = m;
#pragma unroll
            for (int jj = 0; jj < 16; jj++) mt = fmaxf(mt, s[jj]);
            float corr = __expf(m - mt);
            l *= corr;
#pragma unroll
            for (int d = 0; d < 64; d++) acc[d] *= corr;
#pragma unroll
            for (int jj = 0; jj < 16; jj++) {
                float p = __expf(s[jj] - mt);
                l += p;
                const float4* vr = (const float4*)Vs[c0 + jj];
#pragma unroll
                for (int d4 = 0; d4 < 16; d4++) {
                    float4 vv = vr[d4];
                    acc[4 * d4 + 0] = fmaf(p, vv.x, acc[4 * d4 + 0]);
                    acc[4 * d4 + 1] = fmaf(p, vv.y, acc[4 * d4 + 1]);
                    acc[4 * d4 + 2] = fmaf(p, vv.z, acc[4 * d4 + 2]);
                    acc[4 * d4 + 3] = fmaf(p, vv.w, acc[4 * d4 + 3]);
                }
            }
            m = mt;
        }
        __syncthreads();
    }

    const float inv = 1.f / l;
    const size_t yoff = ((size_t)b * SS + qi) * DIMM + h * 64;
#pragma unroll
    for (int d4 = 0; d4 < 16; d4++) {
        float4 o;
        o.x = acc[4 * d4 + 0] * inv;
        o.y = acc[4 * d4 + 1] * inv;
        o.z = acc[4 * d4 + 2] * inv;
        o.w = acc[4 * d4 + 3] * inv;
        *(float4*)(y + yoff + 4 * d4) = o;
    }
}

// ---------------------------------------------------------------------------
extern "C" void kernel_launch(void* const* d_in, const int* in_sizes, int n_in,
                              void* d_out, int out_size)
{
    const float* x  = (const float*)d_in[0];
    const float* Wq = (const float*)d_in[1];
    const float* Wk = (const float*)d_in[2];
    const float* Wv = (const float*)d_in[3];
    const float* Wo = (const float*)d_in[4];
    const float* qg = (const float*)d_in[5];
    float* out = (float*)d_out;

    float *qp, *kp, *vp, *yp;
    cudaGetSymbolAddress((void**)&qp, g_q);
    cudaGetSymbolAddress((void**)&kp, g_k);
    cudaGetSymbolAddress((void**)&vp, g_v);
    cudaGetSymbolAddress((void**)&yp, g_y);

    // QKV projections
    gemm_kernel<<<dim3(DIMM / 64, MROWS / 64), 256>>>(x, Wq, qp, MROWS, DIMM, DIMM);
    gemm_kernel<<<dim3(KVD  / 64, MROWS / 64), 256>>>(x, Wk, kp, MROWS, KVD,  DIMM);
    gemm_kernel<<<dim3(KVD  / 64, MROWS / 64), 256>>>(x, Wv, vp, MROWS, KVD,  DIMM);

    // RMSNorm + RoPE (+gain for q)
    norm_rope_kernel<<<dim3(MROWS, HH / 4),  dim3(32, 4)>>>(qp, HH,  qg);
    norm_rope_kernel<<<dim3(MROWS, KVHH / 4), dim3(32, 4)>>>(kp, KVHH, nullptr);

    // Causal GQA attention
    attn_kernel<<<dim3(SS / 64, HH, BB), 64>>>(qp, kp, vp, yp);

    // Output projection
    gemm_kernel<<<dim3(DIMM / 64, MROWS / 64), 256>>>(yp, Wo, out, MROWS, DIMM, DIMM);
}

// round 2
// speedup vs baseline: 1.7057x; 1.7057x over previous
#include <cuda_runtime.h>
#include <math.h>
#include <stdint.h>

#define BB   4
#define SS   2048
#define DIMM 1024
#define HH   16
#define KVHH 4
#define HDD  64
#define KVD  256
#define MROWS (BB*SS)   // 8192

// Scratch (device globals — no allocations allowed)
__device__ float g_q[(size_t)MROWS * DIMM];   // 32 MB
__device__ float g_k[(size_t)MROWS * KVD];    //  8 MB
__device__ float g_v[(size_t)MROWS * KVD];    //  8 MB
__device__ float g_y[(size_t)MROWS * DIMM];   // 32 MB

__device__ __forceinline__ float cvt_tf32(float x) {
    uint32_t u;
    asm("cvt.rna.tf32.f32 %0, %1;" : "=r"(u) : "f"(x));
    return __uint_as_float(u);
}

// ---------------------------------------------------------------------------
// TF32 tensor-core GEMM: C[M,N] = A[M,K] @ W[N,K]^T   (row-major fp32 in/out)
// CTA tile 128x128, BK=16, 256 threads = 8 warps (4x2), warp tile 32x64.
// mma.sync.aligned.m16n8k8.row.col.f32.tf32.tf32.f32
// Smem stride 20 floats: fragment LDS is bank-conflict-free (20*gid mod 32
// spans all 8 distinct 4-banks groups).
// ---------------------------------------------------------------------------
__global__ void __launch_bounds__(256)
gemm_tf32_kernel(const float* __restrict__ A, const float* __restrict__ W,
                 float* __restrict__ C, int M, int N, int K)
{
    __shared__ float As[128][20];
    __shared__ float Bs[128][20];

    const int tid  = threadIdx.x;
    const int lane = tid & 31;
    const int wid  = tid >> 5;
    const int wm   = (wid & 3) * 32;   // warp row offset in tile
    const int wn   = (wid >> 2) * 64;  // warp col offset in tile
    const int gid  = lane >> 2;        // 0..7
    const int tig  = lane & 3;         // 0..3
    const int bm   = blockIdx.y * 128;
    const int bn   = blockIdx.x * 128;

    // loader mapping: thread -> (row lm / lm+64, k-chunk lkc), float4 along K
    const int lm  = tid >> 2;          // 0..63
    const int lkc = (tid & 3) * 4;     // 0,4,8,12

    const float* Arow0 = A + (size_t)(bm + lm) * K + lkc;
    const float* Arow1 = Arow0 + (size_t)64 * K;
    const float* Wrow0 = W + (size_t)(bn + lm) * K + lkc;
    const float* Wrow1 = Wrow0 + (size_t)64 * K;

    float acc[2][8][4];
#pragma unroll
    for (int i = 0; i < 2; i++)
#pragma unroll
        for (int j = 0; j < 8; j++)
#pragma unroll
            for (int c = 0; c < 4; c++) acc[i][j][c] = 0.f;

    const int T = K / 16;
    float4 ra0, ra1, rb0, rb1;

    // prologue: load tile 0
    ra0 = *(const float4*)(Arow0);
    ra1 = *(const float4*)(Arow1);
    rb0 = *(const float4*)(Wrow0);
    rb1 = *(const float4*)(Wrow1);
    {
        float4 t;
        t.x = cvt_tf32(ra0.x); t.y = cvt_tf32(ra0.y); t.z = cvt_tf32(ra0.z); t.w = cvt_tf32(ra0.w);
        *(float4*)&As[lm][lkc] = t;
        t.x = cvt_tf32(ra1.x); t.y = cvt_tf32(ra1.y); t.z = cvt_tf32(ra1.z); t.w = cvt_tf32(ra1.w);
        *(float4*)&As[lm + 64][lkc] = t;
        t.x = cvt_tf32(rb0.x); t.y = cvt_tf32(rb0.y); t.z = cvt_tf32(rb0.z); t.w = cvt_tf32(rb0.w);
        *(float4*)&Bs[lm][lkc] = t;
        t.x = cvt_tf32(rb1.x); t.y = cvt_tf32(rb1.y); t.z = cvt_tf32(rb1.z); t.w = cvt_tf32(rb1.w);
        *(float4*)&Bs[lm + 64][lkc] = t;
    }
    __syncthreads();

    for (int t = 0; t < T; t++) {
        if (t + 1 < T) {
            int k0 = (t + 1) * 16;
            ra0 = *(const float4*)(Arow0 + k0);
            ra1 = *(const float4*)(Arow1 + k0);
            rb0 = *(const float4*)(Wrow0 + k0);
            rb1 = *(const float4*)(Wrow1 + k0);
        }

#pragma unroll
        for (int ks = 0; ks < 2; ks++) {
            const int kk = ks * 8;
            uint32_t a[2][4], b[8][2];
#pragma unroll
            for (int mt = 0; mt < 2; mt++) {
                a[mt][0] = __float_as_uint(As[wm + mt * 16 + gid    ][kk + tig    ]);
                a[mt][1] = __float_as_uint(As[wm + mt * 16 + gid + 8][kk + tig    ]);
                a[mt][2] = __float_as_uint(As[wm + mt * 16 + gid    ][kk + tig + 4]);
                a[mt][3] = __float_as_uint(As[wm + mt * 16 + gid + 8][kk + tig + 4]);
            }
#pragma unroll
            for (int nt = 0; nt < 8; nt++) {
                b[nt][0] = __float_as_uint(Bs[wn + nt * 8 + gid][kk + tig    ]);
                b[nt][1] = __float_as_uint(Bs[wn + nt * 8 + gid][kk + tig + 4]);
            }
#pragma unroll
            for (int mt = 0; mt < 2; mt++)
#pragma unroll
                for (int nt = 0; nt < 8; nt++) {
                    asm volatile(
                        "mma.sync.aligned.m16n8k8.row.col.f32.tf32.tf32.f32 "
                        "{%0,%1,%2,%3}, {%4,%5,%6,%7}, {%8,%9}, {%0,%1,%2,%3};\n"
                        : "+f"(acc[mt][nt][0]), "+f"(acc[mt][nt][1]),
                          "+f"(acc[mt][nt][2]), "+f"(acc[mt][nt][3])
                        : "r"(a[mt][0]), "r"(a[mt][1]), "r"(a[mt][2]), "r"(a[mt][3]),
                          "r"(b[nt][0]), "r"(b[nt][1]));
                }
        }

        if (t + 1 < T) {
            __syncthreads();
            float4 q;
            q.x = cvt_tf32(ra0.x); q.y = cvt_tf32(ra0.y); q.z = cvt_tf32(ra0.z); q.w = cvt_tf32(ra0.w);
            *(float4*)&As[lm][lkc] = q;
            q.x = cvt_tf32(ra1.x); q.y = cvt_tf32(ra1.y); q.z = cvt_tf32(ra1.z); q.w = cvt_tf32(ra1.w);
            *(float4*)&As[lm + 64][lkc] = q;
            q.x = cvt_tf32(rb0.x); q.y = cvt_tf32(rb0.y); q.z = cvt_tf32(rb0.z); q.w = cvt_tf32(rb0.w);
            *(float4*)&Bs[lm][lkc] = q;
            q.x = cvt_tf32(rb1.x); q.y = cvt_tf32(rb1.y); q.z = cvt_tf32(rb1.z); q.w = cvt_tf32(rb1.w);
            *(float4*)&Bs[lm + 64][lkc] = q;
            __syncthreads();
        }
    }

    // epilogue: float2 stores
#pragma unroll
    for (int mt = 0; mt < 2; mt++) {
        const int row0 = bm + wm + mt * 16 + gid;
#pragma unroll
        for (int nt = 0; nt < 8; nt++) {
            const int col = bn + wn + nt * 8 + tig * 2;
            *(float2*)&C[(size_t)row0 * N + col]       = make_float2(acc[mt][nt][0], acc[mt][nt][1]);
            *(float2*)&C[(size_t)(row0 + 8) * N + col] = make_float2(acc[mt][nt][2], acc[mt][nt][3]);
        }
    }
}

// ---------------------------------------------------------------------------
// Fused per-head RMSNorm + RoPE + optional gain.  In-place.
// ---------------------------------------------------------------------------
__global__ void norm_rope_kernel(float* __restrict__ t, int nheads,
                                 const float* __restrict__ gain)
{
    const int row = blockIdx.x;
    const int h = blockIdx.y * blockDim.y + threadIdx.y;
    const int s = row & (SS - 1);
    const int d = threadIdx.x;   // 0..31

    float* p = t + (size_t)row * (nheads * 64) + h * 64;
    float t1 = p[d];
    float t2 = p[d + 32];

    float ss = t1 * t1 + t2 * t2;
#pragma unroll
    for (int o = 16; o; o >>= 1) ss += __shfl_xor_sync(0xffffffffu, ss, o);
    float r = rsqrtf(ss * (1.0f / 64.0f) + 1e-6f);
    t1 *= r; t2 *= r;

    float inv_freq = exp2f(-(float)d * (13.287712379549449f / 32.0f));
    float th = (float)s * inv_freq;
    float c, sn;
    sincosf(th, &sn, &c);

    float g = gain ? gain[h] : 1.0f;
    p[d]      = ( t1 * c + t2 * sn) * g;
    p[d + 32] = (-t1 * sn + t2 * c) * g;
}

// ---------------------------------------------------------------------------
// Causal GQA flash attention (fp32 SIMT).
// grid: (S/64, H, B); 64 threads, one query row per thread.
// ---------------------------------------------------------------------------
__global__ void __launch_bounds__(64)
attn_kernel(const float* __restrict__ q, const float* __restrict__ k,
            const float* __restrict__ v, float* __restrict__ y)
{
    __shared__ float Ks[64][64];
    __shared__ float Vs[64][64];

    const int qb = blockIdx.x;
    const int h  = blockIdx.y;
    const int b  = blockIdx.z;
    const int kvh = h >> 2;
    const int t = threadIdx.x;
    const int qi = qb * 64 + t;

    const size_t qoff = ((size_t)b * SS + qi) * DIMM + h * 64;
    float qr[64];
#pragma unroll
    for (int d4 = 0; d4 < 16; d4++) {
        float4 qq = *(const float4*)(q + qoff + 4 * d4);
        qr[4 * d4 + 0] = qq.x * 0.125f;
        qr[4 * d4 + 1] = qq.y * 0.125f;
        qr[4 * d4 + 2] = qq.z * 0.125f;
        qr[4 * d4 + 3] = qq.w * 0.125f;
    }

    float m = -INFINITY, l = 0.f;
    float acc[64];
#pragma unroll
    for (int d = 0; d < 64; d++) acc[d] = 0.f;

    for (int kb = 0; kb <= qb; kb++) {
        const float* kbase = k + ((size_t)b * SS + kb * 64) * KVD + kvh * 64;
        const float* vbase = v + ((size_t)b * SS + kb * 64) * KVD + kvh * 64;
        for (int i = t; i < 64 * 16; i += 64) {
            int j = i >> 4, d4 = i & 15;
            ((float4*)Ks[j])[d4] = *(const float4*)(kbase + (size_t)j * KVD + 4 * d4);
            ((float4*)Vs[j])[d4] = *(const float4*)(vbase + (size_t)j * KVD + 4 * d4);
        }
        __syncthreads();

        const int jmax = (kb == qb) ? (t + 1) : 64;
        for (int c0 = 0; c0 < jmax; c0 += 16) {
            float s[16];
#pragma unroll
            for (int jj = 0; jj < 16; jj++) {
                const float4* kr = (const float4*)Ks[c0 + jj];
                float ss = 0.f;
#pragma unroll
                for (int d4 = 0; d4 < 16; d4++) {
                    float4 kk = kr[d4];
                    ss = fmaf(qr[4 * d4 + 0], kk.x, ss);
                    ss = fmaf(qr[4 * d4 + 1], kk.y, ss);
                    ss = fmaf(qr[4 * d4 + 2], kk.z, ss);
                    ss = fmaf(qr[4 * d4 + 3], kk.w, ss);
                }
                s[jj] = (c0 + jj < jmax) ? ss : -INFINITY;
            }
            float mt = m;
#pragma unroll
            for (int jj = 0; jj < 16; jj++) mt = fmaxf(mt, s[jj]);
            float corr = __expf(m - mt);
            l *= corr;
#pragma unroll
            for (int d = 0; d < 64; d++) acc[d] *= corr;
#pragma unroll
            for (int jj = 0; jj < 16; jj++) {
                float p = __expf(s[jj] - mt);
                l += p;
                const float4* vr = (const float4*)Vs[c0 + jj];
#pragma unroll
                for (int d4 = 0; d4 < 16; d4++) {
                    float4 vv = vr[d4];
                    acc[4 * d4 + 0] = fmaf(p, vv.x, acc[4 * d4 + 0]);
                    acc[4 * d4 + 1] = fmaf(p, vv.y, acc[4 * d4 + 1]);
                    acc[4 * d4 + 2] = fmaf(p, vv.z, acc[4 * d4 + 2]);
                    acc[4 * d4 + 3] = fmaf(p, vv.w, acc[4 * d4 + 3]);
                }
            }
            m = mt;
        }
        __syncthreads();
    }

    const float inv = 1.f / l;
    const size_t yoff = ((size_t)b * SS + qi) * DIMM + h * 64;
#pragma unroll
    for (int d4 = 0; d4 < 16; d4++) {
        float4 o;
        o.x = acc[4 * d4 + 0] * inv;
        o.y = acc[4 * d4 + 1] * inv;
        o.z = acc[4 * d4 + 2] * inv;
        o.w = acc[4 * d4 + 3] * inv;
        *(float4*)(y + yoff + 4 * d4) = o;
    }
}

// ---------------------------------------------------------------------------
extern "C" void kernel_launch(void* const* d_in, const int* in_sizes, int n_in,
                              void* d_out, int out_size)
{
    const float* x  = (const float*)d_in[0];
    const float* Wq = (const float*)d_in[1];
    const float* Wk = (const float*)d_in[2];
    const float* Wv = (const float*)d_in[3];
    const float* Wo = (const float*)d_in[4];
    const float* qg = (const float*)d_in[5];
    float* out = (float*)d_out;

    float *qp, *kp, *vp, *yp;
    cudaGetSymbolAddress((void**)&qp, g_q);
    cudaGetSymbolAddress((void**)&kp, g_k);
    cudaGetSymbolAddress((void**)&vp, g_v);
    cudaGetSymbolAddress((void**)&yp, g_y);

    // QKV projections (TF32 tensor cores)
    gemm_tf32_kernel<<<dim3(DIMM / 128, MROWS / 128), 256>>>(x, Wq, qp, MROWS, DIMM, DIMM);
    gemm_tf32_kernel<<<dim3(KVD  / 128, MROWS / 128), 256>>>(x, Wk, kp, MROWS, KVD,  DIMM);
    gemm_tf32_kernel<<<dim3(KVD  / 128, MROWS / 128), 256>>>(x, Wv, vp, MROWS, KVD,  DIMM);

    // RMSNorm + RoPE (+gain for q)
    norm_rope_kernel<<<dim3(MROWS, HH / 4),   dim3(32, 4)>>>(qp, HH,   qg);
    norm_rope_kernel<<<dim3(MROWS, KVHH / 4), dim3(32, 4)>>>(kp, KVHH, nullptr);

    // Causal GQA attention
    attn_kernel<<<dim3(SS / 64, HH, BB), 64>>>(qp, kp, vp, yp);

    // Output projection (TF32 tensor cores)
    gemm_tf32_kernel<<<dim3(DIMM / 128, MROWS / 128), 256>>>(yp, Wo, out, MROWS, DIMM, DIMM);
}

// round 5
// speedup vs baseline: 3.0069x; 1.7628x over previous
#include <cuda_runtime.h>
#include <math.h>
#include <stdint.h>

#define BB   4
#define SS   2048
#define DIMM 1024
#define HH   16
#define KVHH 4
#define HDD  64
#define KVD  256
#define MROWS (BB*SS)   // 8192

// Scratch (device globals — no allocations allowed)
__device__ float g_q[(size_t)MROWS * DIMM];   // 32 MB
__device__ float g_k[(size_t)MROWS * KVD];    //  8 MB
__device__ float g_v[(size_t)MROWS * KVD];    //  8 MB
__device__ float g_y[(size_t)MROWS * DIMM];   // 32 MB

__device__ __forceinline__ float cvt_tf32(float x) {
    uint32_t u;
    asm("cvt.rna.tf32.f32 %0, %1;" : "=r"(u) : "f"(x));
    return __uint_as_float(u);
}

__device__ __forceinline__ void mma8(float* c, const float* a, float b0, float b1) {
    asm volatile(
        "mma.sync.aligned.m16n8k8.row.col.f32.tf32.tf32.f32 "
        "{%0,%1,%2,%3}, {%4,%5,%6,%7}, {%8,%9}, {%0,%1,%2,%3};\n"
        : "+f"(c[0]), "+f"(c[1]), "+f"(c[2]), "+f"(c[3])
        : "r"(__float_as_uint(a[0])), "r"(__float_as_uint(a[1])),
          "r"(__float_as_uint(a[2])), "r"(__float_as_uint(a[3])),
          "r"(__float_as_uint(b0)), "r"(__float_as_uint(b1)));
}

// ---------------------------------------------------------------------------
// TF32 tensor-core GEMM: C[M,N] = A[M,K] @ W[N,K]^T   (row-major fp32 in/out)
// ---------------------------------------------------------------------------
__global__ void __launch_bounds__(256)
gemm_tf32_kernel(const float* __restrict__ A, const float* __restrict__ W,
                 float* __restrict__ C, int M, int N, int K)
{
    __shared__ float As[128][20];
    __shared__ float Bs[128][20];

    const int tid  = threadIdx.x;
    const int lane = tid & 31;
    const int wid  = tid >> 5;
    const int wm   = (wid & 3) * 32;
    const int wn   = (wid >> 2) * 64;
    const int gid  = lane >> 2;
    const int tig  = lane & 3;
    const int bm   = blockIdx.y * 128;
    const int bn   = blockIdx.x * 128;

    const int lm  = tid >> 2;
    const int lkc = (tid & 3) * 4;

    const float* Arow0 = A + (size_t)(bm + lm) * K + lkc;
    const float* Arow1 = Arow0 + (size_t)64 * K;
    const float* Wrow0 = W + (size_t)(bn + lm) * K + lkc;
    const float* Wrow1 = Wrow0 + (size_t)64 * K;

    float acc[2][8][4];
#pragma unroll
    for (int i = 0; i < 2; i++)
#pragma unroll
        for (int j = 0; j < 8; j++)
#pragma unroll
            for (int c = 0; c < 4; c++) acc[i][j][c] = 0.f;

    const int T = K / 16;
    float4 ra0, ra1, rb0, rb1;

    ra0 = *(const float4*)(Arow0);
    ra1 = *(const float4*)(Arow1);
    rb0 = *(const float4*)(Wrow0);
    rb1 = *(const float4*)(Wrow1);
    {
        float4 t;
        t.x = cvt_tf32(ra0.x); t.y = cvt_tf32(ra0.y); t.z = cvt_tf32(ra0.z); t.w = cvt_tf32(ra0.w);
        *(float4*)&As[lm][lkc] = t;
        t.x = cvt_tf32(ra1.x); t.y = cvt_tf32(ra1.y); t.z = cvt_tf32(ra1.z); t.w = cvt_tf32(ra1.w);
        *(float4*)&As[lm + 64][lkc] = t;
        t.x = cvt_tf32(rb0.x); t.y = cvt_tf32(rb0.y); t.z = cvt_tf32(rb0.z); t.w = cvt_tf32(rb0.w);
        *(float4*)&Bs[lm][lkc] = t;
        t.x = cvt_tf32(rb1.x); t.y = cvt_tf32(rb1.y); t.z = cvt_tf32(rb1.z); t.w = cvt_tf32(rb1.w);
        *(float4*)&Bs[lm + 64][lkc] = t;
    }
    __syncthreads();

    for (int t = 0; t < T; t++) {
        if (t + 1 < T) {
            int k0 = (t + 1) * 16;
            ra0 = *(const float4*)(Arow0 + k0);
            ra1 = *(const float4*)(Arow1 + k0);
            rb0 = *(const float4*)(Wrow0 + k0);
            rb1 = *(const float4*)(Wrow1 + k0);
        }

#pragma unroll
        for (int ks = 0; ks < 2; ks++) {
            const int kk = ks * 8;
            float a[2][4], b[8][2];
#pragma unroll
            for (int mt = 0; mt < 2; mt++) {
                a[mt][0] = As[wm + mt * 16 + gid    ][kk + tig    ];
                a[mt][1] = As[wm + mt * 16 + gid + 8][kk + tig    ];
                a[mt][2] = As[wm + mt * 16 + gid    ][kk + tig + 4];
                a[mt][3] = As[wm + mt * 16 + gid + 8][kk + tig + 4];
            }
#pragma unroll
            for (int nt = 0; nt < 8; nt++) {
                b[nt][0] = Bs[wn + nt * 8 + gid][kk + tig    ];
                b[nt][1] = Bs[wn + nt * 8 + gid][kk + tig + 4];
            }
#pragma unroll
            for (int mt = 0; mt < 2; mt++)
#pragma unroll
                for (int nt = 0; nt < 8; nt++)
                    mma8(acc[mt][nt], a[mt], b[nt][0], b[nt][1]);
        }

        if (t + 1 < T) {
            __syncthreads();
            float4 q;
            q.x = cvt_tf32(ra0.x); q.y = cvt_tf32(ra0.y); q.z = cvt_tf32(ra0.z); q.w = cvt_tf32(ra0.w);
            *(float4*)&As[lm][lkc] = q;
            q.x = cvt_tf32(ra1.x); q.y = cvt_tf32(ra1.y); q.z = cvt_tf32(ra1.z); q.w = cvt_tf32(ra1.w);
            *(float4*)&As[lm + 64][lkc] = q;
            q.x = cvt_tf32(rb0.x); q.y = cvt_tf32(rb0.y); q.z = cvt_tf32(rb0.z); q.w = cvt_tf32(rb0.w);
            *(float4*)&Bs[lm][lkc] = q;
            q.x = cvt_tf32(rb1.x); q.y = cvt_tf32(rb1.y); q.z = cvt_tf32(rb1.z); q.w = cvt_tf32(rb1.w);
            *(float4*)&Bs[lm + 64][lkc] = q;
            __syncthreads();
        }
    }

#pragma unroll
    for (int mt = 0; mt < 2; mt++) {
        const int row0 = bm + wm + mt * 16 + gid;
#pragma unroll
        for (int nt = 0; nt < 8; nt++) {
            const int col = bn + wn + nt * 8 + tig * 2;
            *(float2*)&C[(size_t)row0 * N + col]       = make_float2(acc[mt][nt][0], acc[mt][nt][1]);
            *(float2*)&C[(size_t)(row0 + 8) * N + col] = make_float2(acc[mt][nt][2], acc[mt][nt][3]);
        }
    }
}

// ---------------------------------------------------------------------------
// Fused per-head RMSNorm + RoPE + optional gain.  In-place.
// ---------------------------------------------------------------------------
__global__ void norm_rope_kernel(float* __restrict__ t, int nheads,
                                 const float* __restrict__ gain)
{
    const int row = blockIdx.x;
    const int h = blockIdx.y * blockDim.y + threadIdx.y;
    const int s = row & (SS - 1);
    const int d = threadIdx.x;

    float* p = t + (size_t)row * (nheads * 64) + h * 64;
    float t1 = p[d];
    float t2 = p[d + 32];

    float ss = t1 * t1 + t2 * t2;
#pragma unroll
    for (int o = 16; o; o >>= 1) ss += __shfl_xor_sync(0xffffffffu, ss, o);
    float r = rsqrtf(ss * (1.0f / 64.0f) + 1e-6f);
    t1 *= r; t2 *= r;

    float inv_freq = exp2f(-(float)d * (13.287712379549449f / 32.0f));
    float th = (float)s * inv_freq;
    float c, sn;
    sincosf(th, &sn, &c);

    float g = gain ? gain[h] : 1.0f;
    p[d]      = ( t1 * c + t2 * sn) * g;
    p[d + 32] = (-t1 * sn + t2 * c) * g;
}

// ---------------------------------------------------------------------------
// Causal GQA flash attention on TF32 tensor cores — STATIC smem (35.6 KB).
// grid (S/64, H, B); 128 threads (4 warps); warp w owns query rows w*16..+15.
// Key tiles of 32. QK^T tf32x3; PV tf32x2; PV as Y^T = V^T @ P^T.
// smK: 64 rows x stride 68 — rows 0..31 = K_hi tile, rows 32..63 = K_lo tile;
//      also reused as 64x64 staging for Q (prologue) and output (epilogue).
// ---------------------------------------------------------------------------
#define KST 68
#define PST 36

__global__ void __launch_bounds__(128)
attn_tc_kernel(const float* __restrict__ q, const float* __restrict__ k,
               const float* __restrict__ v, float* __restrict__ y)
{
    __shared__ float smK[64 * KST];   // 17408 B
    __shared__ float smV[32 * KST];   //  8704 B
    __shared__ float smP[64 * PST];   //  9216 B
    __shared__ float RowScale[64];

    const int tid = threadIdx.x, lane = tid & 31, wid = tid >> 5;
    const int gid = lane >> 2, tig = lane & 3;
    const int qb = blockIdx.x, h = blockIdx.y, b = blockIdx.z;
    const int kvh = h >> 2;
    const int wm = wid * 16;

    // ---- stage q tile (64x64) into smK, then build split fragments ----
    const float* qbase = q + ((size_t)(b * SS + qb * 64)) * DIMM + h * 64;
    for (int i = tid; i < 64 * 16; i += 128) {
        int j = i >> 4, d4 = i & 15;
        *(float4*)&smK[j * KST + d4 * 4] = *(const float4*)(qbase + (size_t)j * DIMM + d4 * 4);
    }
    __syncthreads();

    float qhi[8][4], qlo[8][4];
#pragma unroll
    for (int kc = 0; kc < 8; kc++) {
        float r0 = smK[(wm + gid    ) * KST + kc * 8 + tig    ] * 0.125f;
        float r1 = smK[(wm + gid + 8) * KST + kc * 8 + tig    ] * 0.125f;
        float r2 = smK[(wm + gid    ) * KST + kc * 8 + tig + 4] * 0.125f;
        float r3 = smK[(wm + gid + 8) * KST + kc * 8 + tig + 4] * 0.125f;
        qhi[kc][0] = cvt_tf32(r0); qlo[kc][0] = cvt_tf32(r0 - qhi[kc][0]);
        qhi[kc][1] = cvt_tf32(r1); qlo[kc][1] = cvt_tf32(r1 - qhi[kc][1]);
        qhi[kc][2] = cvt_tf32(r2); qlo[kc][2] = cvt_tf32(r2 - qhi[kc][2]);
        qhi[kc][3] = cvt_tf32(r3); qlo[kc][3] = cvt_tf32(r3 - qhi[kc][3]);
    }

    float m0 = -INFINITY, m1 = -INFINITY, l0 = 0.f, l1 = 0.f;
    float yt[4][2][4];   // [d-tile 16][q-tile 8][frag]
#pragma unroll
    for (int mt = 0; mt < 4; mt++)
#pragma unroll
        for (int nt = 0; nt < 2; nt++)
#pragma unroll
            for (int c = 0; c < 4; c++) yt[mt][nt][c] = 0.f;

    const int ntiles = 2 * qb + 2;   // 32-key tiles covering [0, (qb+1)*64)
    for (int kt = 0; kt < ntiles; kt++) {
        __syncthreads();   // previous tile fully consumed (also covers q staging)
        const float* kptr = k + ((size_t)(b * SS + kt * 32)) * KVD + kvh * 64;
        const float* vptr = v + ((size_t)(b * SS + kt * 32)) * KVD + kvh * 64;
        for (int i = tid; i < 32 * 16; i += 128) {
            int j = i >> 4, d4 = (i & 15) * 4;
            float4 kk = *(const float4*)(kptr + (size_t)j * KVD + d4);
            float h0 = cvt_tf32(kk.x), h1 = cvt_tf32(kk.y);
            float h2 = cvt_tf32(kk.z), h3 = cvt_tf32(kk.w);
            smK[j * KST + d4 + 0] = h0; smK[(32 + j) * KST + d4 + 0] = cvt_tf32(kk.x - h0);
            smK[j * KST + d4 + 1] = h1; smK[(32 + j) * KST + d4 + 1] = cvt_tf32(kk.y - h1);
            smK[j * KST + d4 + 2] = h2; smK[(32 + j) * KST + d4 + 2] = cvt_tf32(kk.z - h2);
            smK[j * KST + d4 + 3] = h3; smK[(32 + j) * KST + d4 + 3] = cvt_tf32(kk.w - h3);
            float4 vv = *(const float4*)(vptr + (size_t)j * KVD + d4);
            smV[j * KST + d4 + 0] = cvt_tf32(vv.x);
            smV[j * KST + d4 + 1] = cvt_tf32(vv.y);
            smV[j * KST + d4 + 2] = cvt_tf32(vv.z);
            smV[j * KST + d4 + 3] = cvt_tf32(vv.w);
        }
        __syncthreads();

        // ---- scores: S[16q x 32k], tf32x3 ----
        float sc[4][4];
#pragma unroll
        for (int nt = 0; nt < 4; nt++)
#pragma unroll
            for (int c = 0; c < 4; c++) sc[nt][c] = 0.f;

#pragma unroll
        for (int kc = 0; kc < 8; kc++) {
#pragma unroll
            for (int nt = 0; nt < 4; nt++) {
                float bh0 = smK[(nt * 8 + gid) * KST + kc * 8 + tig];
                float bh1 = smK[(nt * 8 + gid) * KST + kc * 8 + tig + 4];
                float bl0 = smK[(32 + nt * 8 + gid) * KST + kc * 8 + tig];
                float bl1 = smK[(32 + nt * 8 + gid) * KST + kc * 8 + tig + 4];
                mma8(sc[nt], qhi[kc], bh0, bh1);
                mma8(sc[nt], qlo[kc], bh0, bh1);
                mma8(sc[nt], qhi[kc], bl0, bl1);
            }
        }

        // causal mask (last two tiles overlap the diagonal)
        if (kt >= 2 * qb) {
            const int off = (kt - 2 * qb) * 32;
#pragma unroll
            for (int nt = 0; nt < 4; nt++) {
                int c0 = off + nt * 8 + 2 * tig;
                if (c0     > wm + gid)     sc[nt][0] = -INFINITY;
                if (c0 + 1 > wm + gid)     sc[nt][1] = -INFINITY;
                if (c0     > wm + gid + 8) sc[nt][2] = -INFINITY;
                if (c0 + 1 > wm + gid + 8) sc[nt][3] = -INFINITY;
            }
        }

        // row max (quad reduce)
        float mt0 = m0, mt1 = m1;
#pragma unroll
        for (int nt = 0; nt < 4; nt++) {
            mt0 = fmaxf(mt0, fmaxf(sc[nt][0], sc[nt][1]));
            mt1 = fmaxf(mt1, fmaxf(sc[nt][2], sc[nt][3]));
        }
        mt0 = fmaxf(mt0, __shfl_xor_sync(0xffffffffu, mt0, 1));
        mt0 = fmaxf(mt0, __shfl_xor_sync(0xffffffffu, mt0, 2));
        mt1 = fmaxf(mt1, __shfl_xor_sync(0xffffffffu, mt1, 1));
        mt1 = fmaxf(mt1, __shfl_xor_sync(0xffffffffu, mt1, 2));

        float corr0 = __expf(m0 - mt0);
        float corr1 = __expf(m1 - mt1);
        m0 = mt0; m1 = mt1;
        l0 *= corr0; l1 *= corr1;

        if (tig == 0) {
            RowScale[wm + gid]     = corr0;
            RowScale[wm + gid + 8] = corr1;
        }

        // p = exp(s - m); accumulate l; stage P (warp-private rows of smP)
#pragma unroll
        for (int nt = 0; nt < 4; nt++) {
            float p00 = __expf(sc[nt][0] - mt0);
            float p01 = __expf(sc[nt][1] - mt0);
            float p10 = __expf(sc[nt][2] - mt1);
            float p11 = __expf(sc[nt][3] - mt1);
            l0 += p00 + p01;
            l1 += p10 + p11;
            *(float2*)&smP[(wm + gid    ) * PST + nt * 8 + 2 * tig] = make_float2(p00, p01);
            *(float2*)&smP[(wm + gid + 8) * PST + nt * 8 + 2 * tig] = make_float2(p10, p11);
        }
        __syncwarp();

        // rescale yt by per-query corr (query = column of Yt)
#pragma unroll
        for (int nt = 0; nt < 2; nt++) {
            float s0 = RowScale[wm + nt * 8 + 2 * tig];
            float s1 = RowScale[wm + nt * 8 + 2 * tig + 1];
#pragma unroll
            for (int mt = 0; mt < 4; mt++) {
                yt[mt][nt][0] *= s0; yt[mt][nt][1] *= s1;
                yt[mt][nt][2] *= s0; yt[mt][nt][3] *= s1;
            }
        }

        // ---- PV: Yt[64d x 16q] += V^T @ P^T, tf32x2 ----
#pragma unroll
        for (int kc = 0; kc < 4; kc++) {
            float ph[2][2], pl[2][2];
#pragma unroll
            for (int nt = 0; nt < 2; nt++) {
                float r0 = smP[(wm + nt * 8 + gid) * PST + kc * 8 + tig];
                float r1 = smP[(wm + nt * 8 + gid) * PST + kc * 8 + tig + 4];
                ph[nt][0] = cvt_tf32(r0); pl[nt][0] = cvt_tf32(r0 - ph[nt][0]);
                ph[nt][1] = cvt_tf32(r1); pl[nt][1] = cvt_tf32(r1 - ph[nt][1]);
            }
#pragma unroll
            for (int mt = 0; mt < 4; mt++) {
                float a[4];
                a[0] = smV[(kc * 8 + tig    ) * KST + mt * 16 + gid];
                a[1] = smV[(kc * 8 + tig    ) * KST + mt * 16 + gid + 8];
                a[2] = smV[(kc * 8 + tig + 4) * KST + mt * 16 + gid];
                a[3] = smV[(kc * 8 + tig + 4) * KST + mt * 16 + gid + 8];
#pragma unroll
                for (int nt = 0; nt < 2; nt++) {
                    mma8(yt[mt][nt], a, ph[nt][0], ph[nt][1]);
                    mma8(yt[mt][nt], a, pl[nt][0], pl[nt][1]);
                }
            }
        }
    }

    // final 1/l per row
    l0 += __shfl_xor_sync(0xffffffffu, l0, 1);
    l0 += __shfl_xor_sync(0xffffffffu, l0, 2);
    l1 += __shfl_xor_sync(0xffffffffu, l1, 1);
    l1 += __shfl_xor_sync(0xffffffffu, l1, 2);
    if (tig == 0) {
        RowScale[wm + gid]     = 1.f / l0;
        RowScale[wm + gid + 8] = 1.f / l1;
    }
    __syncwarp();

    // transpose yt into smK[q][d] staging (conflict-free), coalesced store
    __syncthreads();
#pragma unroll
    for (int nt = 0; nt < 2; nt++) {
        float i0 = RowScale[wm + nt * 8 + 2 * tig];
        float i1 = RowScale[wm + nt * 8 + 2 * tig + 1];
#pragma unroll
        for (int mt = 0; mt < 4; mt++) {
            smK[(wm + nt * 8 + 2 * tig    ) * KST + mt * 16 + gid]     = yt[mt][nt][0] * i0;
            smK[(wm + nt * 8 + 2 * tig + 1) * KST + mt * 16 + gid]     = yt[mt][nt][1] * i1;
            smK[(wm + nt * 8 + 2 * tig    ) * KST + mt * 16 + gid + 8] = yt[mt][nt][2] * i0;
            smK[(wm + nt * 8 + 2 * tig + 1) * KST + mt * 16 + gid + 8] = yt[mt][nt][3] * i1;
        }
    }
    __syncthreads();

    float* ybase = y + ((size_t)(b * SS + qb * 64)) * DIMM + h * 64;
    for (int i = tid; i < 64 * 16; i += 128) {
        int j = i >> 4, d4 = i & 15;
        *(float4*)(ybase + (size_t)j * DIMM + d4 * 4) = *(float4*)&smK[j * KST + d4 * 4];
    }
}

// ---------------------------------------------------------------------------
extern "C" void kernel_launch(void* const* d_in, const int* in_sizes, int n_in,
                              void* d_out, int out_size)
{
    const float* x  = (const float*)d_in[0];
    const float* Wq = (const float*)d_in[1];
    const float* Wk = (const float*)d_in[2];
    const float* Wv = (const float*)d_in[3];
    const float* Wo = (const float*)d_in[4];
    const float* qg = (const float*)d_in[5];
    float* out = (float*)d_out;

    float *qp, *kp, *vp, *yp;
    cudaGetSymbolAddress((void**)&qp, g_q);
    cudaGetSymbolAddress((void**)&kp, g_k);
    cudaGetSymbolAddress((void**)&vp, g_v);
    cudaGetSymbolAddress((void**)&yp, g_y);

    gemm_tf32_kernel<<<dim3(DIMM / 128, MROWS / 128), 256>>>(x, Wq, qp, MROWS, DIMM, DIMM);
    gemm_tf32_kernel<<<dim3(KVD  / 128, MROWS / 128), 256>>>(x, Wk, kp, MROWS, KVD,  DIMM);
    gemm_tf32_kernel<<<dim3(KVD  / 128, MROWS / 128), 256>>>(x, Wv, vp, MROWS, KVD,  DIMM);

    norm_rope_kernel<<<dim3(MROWS, HH / 4),   dim3(32, 4)>>>(qp, HH,   qg);
    norm_rope_kernel<<<dim3(MROWS, KVHH / 4), dim3(32, 4)>>>(kp, KVHH, nullptr);

    attn_tc_kernel<<<dim3(SS / 64, HH, BB), 128>>>(qp, kp, vp, yp);

    gemm_tf32_kernel<<<dim3(DIMM / 128, MROWS / 128), 256>>>(yp, Wo, out, MROWS, DIMM, DIMM);
}

// round 6
// speedup vs baseline: 4.0227x; 1.3378x over previous
#include <cuda_runtime.h>
#include <cuda_fp16.h>
#include <math.h>
#include <stdint.h>

#define BB   4
#define SS   2048
#define DIMM 1024
#define HH   16
#define KVHH 4
#define HDD  64
#define KVD  256
#define MROWS (BB*SS)   // 8192

// Scratch (device globals — no allocations allowed)
__device__ float g_q[(size_t)MROWS * DIMM];   // 32 MB
__device__ float g_k[(size_t)MROWS * KVD];    //  8 MB
__device__ float g_v[(size_t)MROWS * KVD];    //  8 MB
__device__ float g_y[(size_t)MROWS * DIMM];   // 32 MB

__device__ __forceinline__ float cvt_tf32(float x) {
    uint32_t u;
    asm("cvt.rna.tf32.f32 %0, %1;" : "=r"(u) : "f"(x));
    return __uint_as_float(u);
}

__device__ __forceinline__ void mma8(float* c, const float* a, float b0, float b1) {
    asm volatile(
        "mma.sync.aligned.m16n8k8.row.col.f32.tf32.tf32.f32 "
        "{%0,%1,%2,%3}, {%4,%5,%6,%7}, {%8,%9}, {%0,%1,%2,%3};\n"
        : "+f"(c[0]), "+f"(c[1]), "+f"(c[2]), "+f"(c[3])
        : "r"(__float_as_uint(a[0])), "r"(__float_as_uint(a[1])),
          "r"(__float_as_uint(a[2])), "r"(__float_as_uint(a[3])),
          "r"(__float_as_uint(b0)), "r"(__float_as_uint(b1)));
}

// fp16 m16n8k16 mma, fp32 accumulate
__device__ __forceinline__ void mma16h(float* c, const uint32_t* a, uint32_t b0, uint32_t b1) {
    asm volatile(
        "mma.sync.aligned.m16n8k16.row.col.f32.f16.f16.f32 "
        "{%0,%1,%2,%3}, {%4,%5,%6,%7}, {%8,%9}, {%0,%1,%2,%3};\n"
        : "+f"(c[0]), "+f"(c[1]), "+f"(c[2]), "+f"(c[3])
        : "r"(a[0]), "r"(a[1]), "r"(a[2]), "r"(a[3]), "r"(b0), "r"(b1));
}

__device__ __forceinline__ void ldsm4t(uint32_t& r0, uint32_t& r1, uint32_t& r2, uint32_t& r3,
                                       uint32_t addr) {
    asm volatile("ldmatrix.sync.aligned.m8n8.x4.trans.shared.b16 {%0,%1,%2,%3}, [%4];"
                 : "=r"(r0), "=r"(r1), "=r"(r2), "=r"(r3) : "r"(addr));
}

__device__ __forceinline__ uint32_t pack2h(float x, float y) {
    __half2 t = __floats2half2_rn(x, y);
    return *reinterpret_cast<uint32_t*>(&t);
}
__device__ __forceinline__ uint32_t pack2h_lo(float x, float y, uint32_t hi) {
    __half2 h = *reinterpret_cast<__half2*>(&hi);
    __half2 t = __floats2half2_rn(x - __low2float(h), y - __high2float(h));
    return *reinterpret_cast<uint32_t*>(&t);
}

// ---------------------------------------------------------------------------
// TF32 tensor-core GEMM: C[M,N] = A[M,K] @ W[N,K]^T   (row-major fp32 in/out)
// ---------------------------------------------------------------------------
__global__ void __launch_bounds__(256)
gemm_tf32_kernel(const float* __restrict__ A, const float* __restrict__ W,
                 float* __restrict__ C, int M, int N, int K)
{
    __shared__ float As[128][20];
    __shared__ float Bs[128][20];

    const int tid  = threadIdx.x;
    const int lane = tid & 31;
    const int wid  = tid >> 5;
    const int wm   = (wid & 3) * 32;
    const int wn   = (wid >> 2) * 64;
    const int gid  = lane >> 2;
    const int tig  = lane & 3;
    const int bm   = blockIdx.y * 128;
    const int bn   = blockIdx.x * 128;

    const int lm  = tid >> 2;
    const int lkc = (tid & 3) * 4;

    const float* Arow0 = A + (size_t)(bm + lm) * K + lkc;
    const float* Arow1 = Arow0 + (size_t)64 * K;
    const float* Wrow0 = W + (size_t)(bn + lm) * K + lkc;
    const float* Wrow1 = Wrow0 + (size_t)64 * K;

    float acc[2][8][4];
#pragma unroll
    for (int i = 0; i < 2; i++)
#pragma unroll
        for (int j = 0; j < 8; j++)
#pragma unroll
            for (int c = 0; c < 4; c++) acc[i][j][c] = 0.f;

    const int T = K / 16;
    float4 ra0, ra1, rb0, rb1;

    ra0 = *(const float4*)(Arow0);
    ra1 = *(const float4*)(Arow1);
    rb0 = *(const float4*)(Wrow0);
    rb1 = *(const float4*)(Wrow1);
    {
        float4 t;
        t.x = cvt_tf32(ra0.x); t.y = cvt_tf32(ra0.y); t.z = cvt_tf32(ra0.z); t.w = cvt_tf32(ra0.w);
        *(float4*)&As[lm][lkc] = t;
        t.x = cvt_tf32(ra1.x); t.y = cvt_tf32(ra1.y); t.z = cvt_tf32(ra1.z); t.w = cvt_tf32(ra1.w);
        *(float4*)&As[lm + 64][lkc] = t;
        t.x = cvt_tf32(rb0.x); t.y = cvt_tf32(rb0.y); t.z = cvt_tf32(rb0.z); t.w = cvt_tf32(rb0.w);
        *(float4*)&Bs[lm][lkc] = t;
        t.x = cvt_tf32(rb1.x); t.y = cvt_tf32(rb1.y); t.z = cvt_tf32(rb1.z); t.w = cvt_tf32(rb1.w);
        *(float4*)&Bs[lm + 64][lkc] = t;
    }
    __syncthreads();

    for (int t = 0; t < T; t++) {
        if (t + 1 < T) {
            int k0 = (t + 1) * 16;
            ra0 = *(const float4*)(Arow0 + k0);
            ra1 = *(const float4*)(Arow1 + k0);
            rb0 = *(const float4*)(Wrow0 + k0);
            rb1 = *(const float4*)(Wrow1 + k0);
        }

#pragma unroll
        for (int ks = 0; ks < 2; ks++) {
            const int kk = ks * 8;
            float a[2][4], b[8][2];
#pragma unroll
            for (int mt = 0; mt < 2; mt++) {
                a[mt][0] = As[wm + mt * 16 + gid    ][kk + tig    ];
                a[mt][1] = As[wm + mt * 16 + gid + 8][kk + tig    ];
                a[mt][2] = As[wm + mt * 16 + gid    ][kk + tig + 4];
                a[mt][3] = As[wm + mt * 16 + gid + 8][kk + tig + 4];
            }
#pragma unroll
            for (int nt = 0; nt < 8; nt++) {
                b[nt][0] = Bs[wn + nt * 8 + gid][kk + tig    ];
                b[nt][1] = Bs[wn + nt * 8 + gid][kk + tig + 4];
            }
#pragma unroll
            for (int mt = 0; mt < 2; mt++)
#pragma unroll
                for (int nt = 0; nt < 8; nt++)
                    mma8(acc[mt][nt], a[mt], b[nt][0], b[nt][1]);
        }

        if (t + 1 < T) {
            __syncthreads();
            float4 q;
            q.x = cvt_tf32(ra0.x); q.y = cvt_tf32(ra0.y); q.z = cvt_tf32(ra0.z); q.w = cvt_tf32(ra0.w);
            *(float4*)&As[lm][lkc] = q;
            q.x = cvt_tf32(ra1.x); q.y = cvt_tf32(ra1.y); q.z = cvt_tf32(ra1.z); q.w = cvt_tf32(ra1.w);
            *(float4*)&As[lm + 64][lkc] = q;
            q.x = cvt_tf32(rb0.x); q.y = cvt_tf32(rb0.y); q.z = cvt_tf32(rb0.z); q.w = cvt_tf32(rb0.w);
            *(float4*)&Bs[lm][lkc] = q;
            q.x = cvt_tf32(rb1.x); q.y = cvt_tf32(rb1.y); q.z = cvt_tf32(rb1.z); q.w = cvt_tf32(rb1.w);
            *(float4*)&Bs[lm + 64][lkc] = q;
            __syncthreads();
        }
    }

#pragma unroll
    for (int mt = 0; mt < 2; mt++) {
        const int row0 = bm + wm + mt * 16 + gid;
#pragma unroll
        for (int nt = 0; nt < 8; nt++) {
            const int col = bn + wn + nt * 8 + tig * 2;
            *(float2*)&C[(size_t)row0 * N + col]       = make_float2(acc[mt][nt][0], acc[mt][nt][1]);
            *(float2*)&C[(size_t)(row0 + 8) * N + col] = make_float2(acc[mt][nt][2], acc[mt][nt][3]);
        }
    }
}

// ---------------------------------------------------------------------------
// Fused per-head RMSNorm + RoPE + optional gain.  In-place.
// ---------------------------------------------------------------------------
__global__ void norm_rope_kernel(float* __restrict__ t, int nheads,
                                 const float* __restrict__ gain)
{
    const int row = blockIdx.x;
    const int h = blockIdx.y * blockDim.y + threadIdx.y;
    const int s = row & (SS - 1);
    const int d = threadIdx.x;

    float* p = t + (size_t)row * (nheads * 64) + h * 64;
    float t1 = p[d];
    float t2 = p[d + 32];

    float ss = t1 * t1 + t2 * t2;
#pragma unroll
    for (int o = 16; o; o >>= 1) ss += __shfl_xor_sync(0xffffffffu, ss, o);
    float r = rsqrtf(ss * (1.0f / 64.0f) + 1e-6f);
    t1 *= r; t2 *= r;

    float inv_freq = exp2f(-(float)d * (13.287712379549449f / 32.0f));
    float th = (float)s * inv_freq;
    float c, sn;
    sincosf(th, &sn, &c);

    float g = gain ? gain[h] : 1.0f;
    p[d]      = ( t1 * c + t2 * sn) * g;
    p[d + 32] = (-t1 * sn + t2 * c) * g;
}

// ---------------------------------------------------------------------------
// Causal GQA flash attention — split-FP16 m16n8k16 tensor cores.
// grid (S/64, H, B); 128 threads (4 warps); warp w owns query rows w*16..+15.
// 32-key tiles. QK^T = qh*kh + ql*kh + qh*kl; PV = ph*vh + pl*vh + ph*vl.
// PV is direct P·V (A=P stays in registers); V b-frags via ldmatrix.x4.trans.
// ---------------------------------------------------------------------------
#define QST  68    // floats per qs row
#define KHST 72    // halves per kh/kl/vh/vl row (64 + 8 pad)

__global__ void __launch_bounds__(128)
attn_tc_kernel(const float* __restrict__ q, const float* __restrict__ k,
               const float* __restrict__ v, float* __restrict__ y)
{
    __shared__ float  qs[64 * QST];                      // 17408 B
    __shared__ __half kh[32 * KHST], kl[32 * KHST];      // 4608 B each
    __shared__ __half vh[32 * KHST], vl[32 * KHST];      // 4608 B each

    const int tid = threadIdx.x, lane = tid & 31, wid = tid >> 5;
    const int gid = lane >> 2, tig = lane & 3;
    const int qb = blockIdx.x, h = blockIdx.y, b = blockIdx.z;
    const int kvh = h >> 2;
    const int wm = wid * 16;

    // ---- stage q tile (64x64, coalesced) ----
    const float* qbase = q + ((size_t)(b * SS + qb * 64)) * DIMM + h * 64;
    for (int i = tid; i < 64 * 16; i += 128) {
        int j = i >> 4, d4 = i & 15;
        *(float4*)&qs[j * QST + d4 * 4] = *(const float4*)(qbase + (size_t)j * DIMM + d4 * 4);
    }
    __syncthreads();

    // ---- build Q fragments (hi/lo fp16), scaled by 1/sqrt(64) ----
    uint32_t qh_[4][4], ql_[4][4];
#pragma unroll
    for (int kc = 0; kc < 4; kc++) {
        float2 f0 = *(float2*)&qs[(wm + gid    ) * QST + kc * 16 + 2 * tig];
        float2 f1 = *(float2*)&qs[(wm + gid + 8) * QST + kc * 16 + 2 * tig];
        float2 f2 = *(float2*)&qs[(wm + gid    ) * QST + kc * 16 + 8 + 2 * tig];
        float2 f3 = *(float2*)&qs[(wm + gid + 8) * QST + kc * 16 + 8 + 2 * tig];
        f0.x *= 0.125f; f0.y *= 0.125f; f1.x *= 0.125f; f1.y *= 0.125f;
        f2.x *= 0.125f; f2.y *= 0.125f; f3.x *= 0.125f; f3.y *= 0.125f;
        qh_[kc][0] = pack2h(f0.x, f0.y); ql_[kc][0] = pack2h_lo(f0.x, f0.y, qh_[kc][0]);
        qh_[kc][1] = pack2h(f1.x, f1.y); ql_[kc][1] = pack2h_lo(f1.x, f1.y, qh_[kc][1]);
        qh_[kc][2] = pack2h(f2.x, f2.y); ql_[kc][2] = pack2h_lo(f2.x, f2.y, qh_[kc][2]);
        qh_[kc][3] = pack2h(f3.x, f3.y); ql_[kc][3] = pack2h_lo(f3.x, f3.y, qh_[kc][3]);
    }

    // ldmatrix lane base addresses for V tiles (trans)
    const uint32_t vrow = (lane & 7) + 8 * ((lane >> 3) & 1);   // 0..15
    const uint32_t vcolB = (lane >> 4) * 16;                    // +8 halves
    const uint32_t vh_base = (uint32_t)__cvta_generic_to_shared(vh) + vrow * (KHST * 2) + vcolB;
    const uint32_t vl_base = (uint32_t)__cvta_generic_to_shared(vl) + vrow * (KHST * 2) + vcolB;

    float m0 = -INFINITY, m1 = -INFINITY, l0 = 0.f, l1 = 0.f;
    float acc[8][4];   // Y[q16 x d64]: rows gid/gid+8, cols nd*8 + 2tig..
#pragma unroll
    for (int nd = 0; nd < 8; nd++)
#pragma unroll
        for (int c = 0; c < 4; c++) acc[nd][c] = 0.f;

    const int ntiles = 2 * qb + 2;
    for (int kt = 0; kt < ntiles; kt++) {
        __syncthreads();
        const float* kptr = k + ((size_t)(b * SS + kt * 32)) * KVD + kvh * 64;
        const float* vptr = v + ((size_t)(b * SS + kt * 32)) * KVD + kvh * 64;
        for (int i = tid; i < 32 * 16; i += 128) {
            int j = i >> 4, d4 = (i & 15) * 4;
            float4 kk = *(const float4*)(kptr + (size_t)j * KVD + d4);
            uint32_t h01 = pack2h(kk.x, kk.y), h23 = pack2h(kk.z, kk.w);
            *(uint32_t*)&kh[j * KHST + d4]     = h01;
            *(uint32_t*)&kh[j * KHST + d4 + 2] = h23;
            *(uint32_t*)&kl[j * KHST + d4]     = pack2h_lo(kk.x, kk.y, h01);
            *(uint32_t*)&kl[j * KHST + d4 + 2] = pack2h_lo(kk.z, kk.w, h23);
            float4 vv = *(const float4*)(vptr + (size_t)j * KVD + d4);
            uint32_t g01 = pack2h(vv.x, vv.y), g23 = pack2h(vv.z, vv.w);
            *(uint32_t*)&vh[j * KHST + d4]     = g01;
            *(uint32_t*)&vh[j * KHST + d4 + 2] = g23;
            *(uint32_t*)&vl[j * KHST + d4]     = pack2h_lo(vv.x, vv.y, g01);
            *(uint32_t*)&vl[j * KHST + d4 + 2] = pack2h_lo(vv.z, vv.w, g23);
        }
        __syncthreads();

        // ---- scores: S[16q x 32k], split-fp16 x3 ----
        float sc[4][4];
#pragma unroll
        for (int nt = 0; nt < 4; nt++)
#pragma unroll
            for (int c = 0; c < 4; c++) sc[nt][c] = 0.f;

#pragma unroll
        for (int kc = 0; kc < 4; kc++) {
#pragma unroll
            for (int nt = 0; nt < 4; nt++) {
                const __half* krh = &kh[(nt * 8 + gid) * KHST + kc * 16 + 2 * tig];
                const __half* krl = &kl[(nt * 8 + gid) * KHST + kc * 16 + 2 * tig];
                uint32_t bh0 = *(const uint32_t*)krh;
                uint32_t bh1 = *(const uint32_t*)(krh + 8);
                uint32_t bl0 = *(const uint32_t*)krl;
                uint32_t bl1 = *(const uint32_t*)(krl + 8);
                mma16h(sc[nt], qh_[kc], bh0, bh1);
                mma16h(sc[nt], ql_[kc], bh0, bh1);
                mma16h(sc[nt], qh_[kc], bl0, bl1);
            }
        }

        // causal mask (last two tiles overlap the diagonal)
        if (kt >= 2 * qb) {
            const int off = (kt - 2 * qb) * 32;
#pragma unroll
            for (int nt = 0; nt < 4; nt++) {
                int c0 = off + nt * 8 + 2 * tig;
                if (c0     > wm + gid)     sc[nt][0] = -INFINITY;
                if (c0 + 1 > wm + gid)     sc[nt][1] = -INFINITY;
                if (c0     > wm + gid + 8) sc[nt][2] = -INFINITY;
                if (c0 + 1 > wm + gid + 8) sc[nt][3] = -INFINITY;
            }
        }

        // row max (quad reduce over key columns)
        float mt0 = m0, mt1 = m1;
#pragma unroll
        for (int nt = 0; nt < 4; nt++) {
            mt0 = fmaxf(mt0, fmaxf(sc[nt][0], sc[nt][1]));
            mt1 = fmaxf(mt1, fmaxf(sc[nt][2], sc[nt][3]));
        }
        mt0 = fmaxf(mt0, __shfl_xor_sync(0xffffffffu, mt0, 1));
        mt0 = fmaxf(mt0, __shfl_xor_sync(0xffffffffu, mt0, 2));
        mt1 = fmaxf(mt1, __shfl_xor_sync(0xffffffffu, mt1, 1));
        mt1 = fmaxf(mt1, __shfl_xor_sync(0xffffffffu, mt1, 2));

        float corr0 = __expf(m0 - mt0);
        float corr1 = __expf(m1 - mt1);
        m0 = mt0; m1 = mt1;
        l0 *= corr0; l1 *= corr1;
#pragma unroll
        for (int nd = 0; nd < 8; nd++) {
            acc[nd][0] *= corr0; acc[nd][1] *= corr0;
            acc[nd][2] *= corr1; acc[nd][3] *= corr1;
        }

        // p = exp(s - m) in place; accumulate l
#pragma unroll
        for (int nt = 0; nt < 4; nt++) {
            sc[nt][0] = __expf(sc[nt][0] - mt0);
            sc[nt][1] = __expf(sc[nt][1] - mt0);
            sc[nt][2] = __expf(sc[nt][2] - mt1);
            sc[nt][3] = __expf(sc[nt][3] - mt1);
            l0 += sc[nt][0] + sc[nt][1];
            l1 += sc[nt][2] + sc[nt][3];
        }

        // pack P fragments (hi/lo) — P stays in registers
        uint32_t pfh[2][4], pfl[2][4];
#pragma unroll
        for (int kc = 0; kc < 2; kc++) {
            pfh[kc][0] = pack2h(sc[2 * kc][0],     sc[2 * kc][1]);
            pfl[kc][0] = pack2h_lo(sc[2 * kc][0],  sc[2 * kc][1],     pfh[kc][0]);
            pfh[kc][1] = pack2h(sc[2 * kc][2],     sc[2 * kc][3]);
            pfl[kc][1] = pack2h_lo(sc[2 * kc][2],  sc[2 * kc][3],     pfh[kc][1]);
            pfh[kc][2] = pack2h(sc[2 * kc + 1][0], sc[2 * kc + 1][1]);
            pfl[kc][2] = pack2h_lo(sc[2 * kc + 1][0], sc[2 * kc + 1][1], pfh[kc][2]);
            pfh[kc][3] = pack2h(sc[2 * kc + 1][2], sc[2 * kc + 1][3]);
            pfl[kc][3] = pack2h_lo(sc[2 * kc + 1][2], sc[2 * kc + 1][3], pfh[kc][3]);
        }

        // ---- PV: Y[q][d] += P·V, split-fp16 x3; V b-frags via ldmatrix.trans ----
#pragma unroll
        for (int kc = 0; kc < 2; kc++) {
#pragma unroll
            for (int ndp = 0; ndp < 4; ndp++) {
                uint32_t r0, r1, r2, r3, s0, s1, s2, s3;
                uint32_t off = (uint32_t)(kc * 16 * (KHST * 2) + ndp * 32);
                ldsm4t(r0, r1, r2, r3, vh_base + off);
                ldsm4t(s0, s1, s2, s3, vl_base + off);
                mma16h(acc[ndp * 2],     pfh[kc], r0, r1);
                mma16h(acc[ndp * 2],     pfl[kc], r0, r1);
                mma16h(acc[ndp * 2],     pfh[kc], s0, s1);
                mma16h(acc[ndp * 2 + 1], pfh[kc], r2, r3);
                mma16h(acc[ndp * 2 + 1], pfl[kc], r2, r3);
                mma16h(acc[ndp * 2 + 1], pfh[kc], s2, s3);
            }
        }
    }

    // final 1/l per row (quad reduce)
    l0 += __shfl_xor_sync(0xffffffffu, l0, 1);
    l0 += __shfl_xor_sync(0xffffffffu, l0, 2);
    l1 += __shfl_xor_sync(0xffffffffu, l1, 1);
    l1 += __shfl_xor_sync(0xffffffffu, l1, 2);
    const float inv0 = 1.f / l0;
    const float inv1 = 1.f / l1;

    // direct global stores (rows gid / gid+8, cols nd*8 + 2tig)
    float* yr0 = y + ((size_t)(b * SS + qb * 64 + wm + gid    )) * DIMM + h * 64 + 2 * tig;
    float* yr1 = y + ((size_t)(b * SS + qb * 64 + wm + gid + 8)) * DIMM + h * 64 + 2 * tig;
#pragma unroll
    for (int nd = 0; nd < 8; nd++) {
        *(float2*)(yr0 + nd * 8) = make_float2(acc[nd][0] * inv0, acc[nd][1] * inv0);
        *(float2*)(yr1 + nd * 8) = make_float2(acc[nd][2] * inv1, acc[nd][3] * inv1);
    }
}

// ---------------------------------------------------------------------------
extern "C" void kernel_launch(void* const* d_in, const int* in_sizes, int n_in,
                              void* d_out, int out_size)
{
    const float* x  = (const float*)d_in[0];
    const float* Wq = (const float*)d_in[1];
    const float* Wk = (const float*)d_in[2];
    const float* Wv = (const float*)d_in[3];
    const float* Wo = (const float*)d_in[4];
    const float* qg = (const float*)d_in[5];
    float* out = (float*)d_out;

    float *qp, *kp, *vp, *yp;
    cudaGetSymbolAddress((void**)&qp, g_q);
    cudaGetSymbolAddress((void**)&kp, g_k);
    cudaGetSymbolAddress((void**)&vp, g_v);
    cudaGetSymbolAddress((void**)&yp, g_y);

    gemm_tf32_kernel<<<dim3(DIMM / 128, MROWS / 128), 256>>>(x, Wq, qp, MROWS, DIMM, DIMM);
    gemm_tf32_kernel<<<dim3(KVD  / 128, MROWS / 128), 256>>>(x, Wk, kp, MROWS, KVD,  DIMM);
    gemm_tf32_kernel<<<dim3(KVD  / 128, MROWS / 128), 256>>>(x, Wv, vp, MROWS, KVD,  DIMM);

    norm_rope_kernel<<<dim3(MROWS, HH / 4),   dim3(32, 4)>>>(qp, HH,   qg);
    norm_rope_kernel<<<dim3(MROWS, KVHH / 4), dim3(32, 4)>>>(kp, KVHH, nullptr);

    attn_tc_kernel<<<dim3(SS / 64, HH, BB), 128>>>(qp, kp, vp, yp);

    gemm_tf32_kernel<<<dim3(DIMM / 128, MROWS / 128), 256>>>(yp, Wo, out, MROWS, DIMM, DIMM);
}

// round 7
// speedup vs baseline: 4.2914x; 1.0668x over previous
#include <cuda_runtime.h>
#include <cuda_fp16.h>
#include <math.h>
#include <stdint.h>

#define BB   4
#define SS   2048
#define DIMM 1024
#define HH   16
#define KVHH 4
#define HDD  64
#define KVD  256
#define MROWS (BB*SS)   // 8192

// Scratch (device globals — no allocations allowed)
__device__ float  g_q [(size_t)MROWS * DIMM];   // 32 MB
__device__ float  g_k [(size_t)MROWS * KVD];    //  8 MB
__device__ float  g_v [(size_t)MROWS * KVD];    //  8 MB
__device__ float  g_y [(size_t)MROWS * DIMM];   // 32 MB
__device__ float  g_xr[(size_t)MROWS * DIMM];   // 32 MB (tf32-rounded x)
__device__ float  g_wq[(size_t)DIMM * DIMM];
__device__ float  g_wk[(size_t)KVD  * DIMM];
__device__ float  g_wv[(size_t)KVD  * DIMM];
__device__ float  g_wo[(size_t)DIMM * DIMM];
__device__ __half g_kh[(size_t)MROWS * KVD];    // 4 MB each
__device__ __half g_kl[(size_t)MROWS * KVD];
__device__ __half g_vh[(size_t)MROWS * KVD];
__device__ __half g_vl[(size_t)MROWS * KVD];

__device__ __forceinline__ float cvt_tf32(float x) {
    uint32_t u;
    asm("cvt.rna.tf32.f32 %0, %1;" : "=r"(u) : "f"(x));
    return __uint_as_float(u);
}

__device__ __forceinline__ void mma8(float* c, const float* a, float b0, float b1) {
    asm volatile(
        "mma.sync.aligned.m16n8k8.row.col.f32.tf32.tf32.f32 "
        "{%0,%1,%2,%3}, {%4,%5,%6,%7}, {%8,%9}, {%0,%1,%2,%3};\n"
        : "+f"(c[0]), "+f"(c[1]), "+f"(c[2]), "+f"(c[3])
        : "r"(__float_as_uint(a[0])), "r"(__float_as_uint(a[1])),
          "r"(__float_as_uint(a[2])), "r"(__float_as_uint(a[3])),
          "r"(__float_as_uint(b0)), "r"(__float_as_uint(b1)));
}

__device__ __forceinline__ void mma16h(float* c, const uint32_t* a, uint32_t b0, uint32_t b1) {
    asm volatile(
        "mma.sync.aligned.m16n8k16.row.col.f32.f16.f16.f32 "
        "{%0,%1,%2,%3}, {%4,%5,%6,%7}, {%8,%9}, {%0,%1,%2,%3};\n"
        : "+f"(c[0]), "+f"(c[1]), "+f"(c[2]), "+f"(c[3])
        : "r"(a[0]), "r"(a[1]), "r"(a[2]), "r"(a[3]), "r"(b0), "r"(b1));
}

__device__ __forceinline__ void ldsm4t(uint32_t& r0, uint32_t& r1, uint32_t& r2, uint32_t& r3,
                                       uint32_t addr) {
    asm volatile("ldmatrix.sync.aligned.m8n8.x4.trans.shared.b16 {%0,%1,%2,%3}, [%4];"
                 : "=r"(r0), "=r"(r1), "=r"(r2), "=r"(r3) : "r"(addr));
}

__device__ __forceinline__ uint32_t pack2h(float x, float y) {
    __half2 t = __floats2half2_rn(x, y);
    return *reinterpret_cast<uint32_t*>(&t);
}
__device__ __forceinline__ uint32_t pack2h_lo(float x, float y, uint32_t hi) {
    __half2 h = *reinterpret_cast<__half2*>(&hi);
    __half2 t = __floats2half2_rn(x - __low2float(h), y - __high2float(h));
    return *reinterpret_cast<uint32_t*>(&t);
}

__device__ __forceinline__ void cp16(void* smem, const void* g) {
    uint32_t s = (uint32_t)__cvta_generic_to_shared(smem);
    asm volatile("cp.async.cg.shared.global [%0], [%1], 16;\n" :: "r"(s), "l"(g));
}

// ---------------------------------------------------------------------------
// Elementwise tf32 pre-round (float4 grid-stride single pass)
// ---------------------------------------------------------------------------
__global__ void round_tf32_kernel(const float* __restrict__ in, float* __restrict__ out, int n4)
{
    int i = blockIdx.x * blockDim.x + threadIdx.x;
    if (i < n4) {
        float4 v = ((const float4*)in)[i];
        v.x = cvt_tf32(v.x); v.y = cvt_tf32(v.y);
        v.z = cvt_tf32(v.z); v.w = cvt_tf32(v.w);
        ((float4*)out)[i] = v;
    }
}

// ---------------------------------------------------------------------------
// V split to fp16 hi/lo
// ---------------------------------------------------------------------------
__global__ void split_v_kernel(const float* __restrict__ v,
                               __half* __restrict__ vh, __half* __restrict__ vl, int n2)
{
    int i = blockIdx.x * blockDim.x + threadIdx.x;
    if (i < n2) {
        float2 f = ((const float2*)v)[i];
        uint32_t hi = pack2h(f.x, f.y);
        ((uint32_t*)vh)[i] = hi;
        ((uint32_t*)vl)[i] = pack2h_lo(f.x, f.y, hi);
    }
}

// ---------------------------------------------------------------------------
// TF32 GEMM, cp.async double-buffered.  Inputs MUST be tf32-pre-rounded.
// C[M,N] = A[M,K] @ W[N,K]^T.  128x128 tile, BK=16, 256 thr, warp tile 32x64.
// ---------------------------------------------------------------------------
__global__ void __launch_bounds__(256)
gemm_tf32_db_kernel(const float* __restrict__ A, const float* __restrict__ W,
                    float* __restrict__ C, int M, int N, int K)
{
    __shared__ float As[2][128][20];
    __shared__ float Bs[2][128][20];

    const int tid  = threadIdx.x;
    const int lane = tid & 31;
    const int wid  = tid >> 5;
    const int wm   = (wid & 3) * 32;
    const int wn   = (wid >> 2) * 64;
    const int gid  = lane >> 2;
    const int tig  = lane & 3;
    const int bm   = blockIdx.y * 128;
    const int bn   = blockIdx.x * 128;

    const int lm  = tid >> 2;
    const int lkc = (tid & 3) * 4;

    const float* Arow0 = A + (size_t)(bm + lm) * K + lkc;
    const float* Arow1 = Arow0 + (size_t)64 * K;
    const float* Wrow0 = W + (size_t)(bn + lm) * K + lkc;
    const float* Wrow1 = Wrow0 + (size_t)64 * K;

    float acc[2][8][4];
#pragma unroll
    for (int i = 0; i < 2; i++)
#pragma unroll
        for (int j = 0; j < 8; j++)
#pragma unroll
            for (int c = 0; c < 4; c++) acc[i][j][c] = 0.f;

    const int T = K / 16;

    // prologue: stage 0
    cp16(&As[0][lm][lkc],      Arow0);
    cp16(&As[0][lm + 64][lkc], Arow1);
    cp16(&Bs[0][lm][lkc],      Wrow0);
    cp16(&Bs[0][lm + 64][lkc], Wrow1);
    asm volatile("cp.async.commit_group;\n");

    for (int t = 0; t < T; t++) {
        if (t + 1 < T) {
            const int s = (t + 1) & 1, k0 = (t + 1) * 16;
            cp16(&As[s][lm][lkc],      Arow0 + k0);
            cp16(&As[s][lm + 64][lkc], Arow1 + k0);
            cp16(&Bs[s][lm][lkc],      Wrow0 + k0);
            cp16(&Bs[s][lm + 64][lkc], Wrow1 + k0);
            asm volatile("cp.async.commit_group;\n");
            asm volatile("cp.async.wait_group 1;\n");
        } else {
            asm volatile("cp.async.wait_group 0;\n");
        }
        __syncthreads();

        const int cb = t & 1;
#pragma unroll
        for (int ks = 0; ks < 2; ks++) {
            const int kk = ks * 8;
            float a[2][4], b[8][2];
#pragma unroll
            for (int mt = 0; mt < 2; mt++) {
                a[mt][0] = As[cb][wm + mt * 16 + gid    ][kk + tig    ];
                a[mt][1] = As[cb][wm + mt * 16 + gid + 8][kk + tig    ];
                a[mt][2] = As[cb][wm + mt * 16 + gid    ][kk + tig + 4];
                a[mt][3] = As[cb][wm + mt * 16 + gid + 8][kk + tig + 4];
            }
#pragma unroll
            for (int nt = 0; nt < 8; nt++) {
                b[nt][0] = Bs[cb][wn + nt * 8 + gid][kk + tig    ];
                b[nt][1] = Bs[cb][wn + nt * 8 + gid][kk + tig + 4];
            }
#pragma unroll
            for (int mt = 0; mt < 2; mt++)
#pragma unroll
                for (int nt = 0; nt < 8; nt++)
                    mma8(acc[mt][nt], a[mt], b[nt][0], b[nt][1]);
        }
        __syncthreads();
    }

#pragma unroll
    for (int mt = 0; mt < 2; mt++) {
        const int row0 = bm + wm + mt * 16 + gid;
#pragma unroll
        for (int nt = 0; nt < 8; nt++) {
            const int col = bn + wn + nt * 8 + tig * 2;
            *(float2*)&C[(size_t)row0 * N + col]       = make_float2(acc[mt][nt][0], acc[mt][nt][1]);
            *(float2*)&C[(size_t)(row0 + 8) * N + col] = make_float2(acc[mt][nt][2], acc[mt][nt][3]);
        }
    }
}

// ---------------------------------------------------------------------------
// RMSNorm + RoPE + gain for Q (in-place fp32)
// ---------------------------------------------------------------------------
__global__ void norm_rope_q_kernel(float* __restrict__ t, const float* __restrict__ gain)
{
    const int row = blockIdx.x;
    const int h = blockIdx.y * blockDim.y + threadIdx.y;
    const int s = row & (SS - 1);
    const int d = threadIdx.x;

    float* p = t + (size_t)row * DIMM + h * 64;
    float t1 = p[d];
    float t2 = p[d + 32];

    float ss = t1 * t1 + t2 * t2;
#pragma unroll
    for (int o = 16; o; o >>= 1) ss += __shfl_xor_sync(0xffffffffu, ss, o);
    float r = rsqrtf(ss * (1.0f / 64.0f) + 1e-6f);
    t1 *= r; t2 *= r;

    float inv_freq = exp2f(-(float)d * (13.287712379549449f / 32.0f));
    float th = (float)s * inv_freq;
    float c, sn;
    sincosf(th, &sn, &c);

    float g = gain[h];
    p[d]      = ( t1 * c + t2 * sn) * g;
    p[d + 32] = (-t1 * sn + t2 * c) * g;
}

// ---------------------------------------------------------------------------
// RMSNorm + RoPE for K, emitting split fp16 hi/lo directly
// ---------------------------------------------------------------------------
__global__ void norm_rope_k_kernel(const float* __restrict__ t,
                                   __half* __restrict__ kh, __half* __restrict__ kl)
{
    const int row = blockIdx.x;
    const int h = blockIdx.y * blockDim.y + threadIdx.y;
    const int s = row & (SS - 1);
    const int d = threadIdx.x;

    const float* p = t + (size_t)row * KVD + h * 64;
    float t1 = p[d];
    float t2 = p[d + 32];

    float ss = t1 * t1 + t2 * t2;
#pragma unroll
    for (int o = 16; o; o >>= 1) ss += __shfl_xor_sync(0xffffffffu, ss, o);
    float r = rsqrtf(ss * (1.0f / 64.0f) + 1e-6f);
    t1 *= r; t2 *= r;

    float inv_freq = exp2f(-(float)d * (13.287712379549449f / 32.0f));
    float th = (float)s * inv_freq;
    float c, sn;
    sincosf(th, &sn, &c);

    float o1 =  t1 * c + t2 * sn;
    float o2 = -t1 * sn + t2 * c;

    size_t base = (size_t)row * KVD + h * 64;
    __half h1 = __float2half_rn(o1);
    __half h2 = __float2half_rn(o2);
    kh[base + d]      = h1;  kl[base + d]      = __float2half_rn(o1 - __half2float(h1));
    kh[base + d + 32] = h2;  kl[base + d + 32] = __float2half_rn(o2 - __half2float(h2));
}

// ---------------------------------------------------------------------------
// Causal GQA flash attention — split-FP16 m16n8k16, pre-split K/V inputs.
// grid (S/64, H, B); 128 threads (4 warps); warp w owns query rows w*16..+15.
// Writes tf32-rounded output (feeds the final tf32 GEMM).
// ---------------------------------------------------------------------------
#define QST  68
#define KHST 72

__global__ void __launch_bounds__(128)
attn_tc_kernel(const float* __restrict__ q,
               const __half* __restrict__ gkh, const __half* __restrict__ gkl,
               const __half* __restrict__ gvh, const __half* __restrict__ gvl,
               float* __restrict__ y)
{
    __shared__ float  qs[64 * QST];
    __shared__ __half kh[32 * KHST], kl[32 * KHST];
    __shared__ __half vh[32 * KHST], vl[32 * KHST];

    const int tid = threadIdx.x, lane = tid & 31, wid = tid >> 5;
    const int gid = lane >> 2, tig = lane & 3;
    const int qb = blockIdx.x, h = blockIdx.y, b = blockIdx.z;
    const int kvh = h >> 2;
    const int wm = wid * 16;

    const float* qbase = q + ((size_t)(b * SS + qb * 64)) * DIMM + h * 64;
    for (int i = tid; i < 64 * 16; i += 128) {
        int j = i >> 4, d4 = i & 15;
        *(float4*)&qs[j * QST + d4 * 4] = *(const float4*)(qbase + (size_t)j * DIMM + d4 * 4);
    }
    __syncthreads();

    uint32_t qh_[4][4], ql_[4][4];
#pragma unroll
    for (int kc = 0; kc < 4; kc++) {
        float2 f0 = *(float2*)&qs[(wm + gid    ) * QST + kc * 16 + 2 * tig];
        float2 f1 = *(float2*)&qs[(wm + gid + 8) * QST + kc * 16 + 2 * tig];
        float2 f2 = *(float2*)&qs[(wm + gid    ) * QST + kc * 16 + 8 + 2 * tig];
        float2 f3 = *(float2*)&qs[(wm + gid + 8) * QST + kc * 16 + 8 + 2 * tig];
        f0.x *= 0.125f; f0.y *= 0.125f; f1.x *= 0.125f; f1.y *= 0.125f;
        f2.x *= 0.125f; f2.y *= 0.125f; f3.x *= 0.125f; f3.y *= 0.125f;
        qh_[kc][0] = pack2h(f0.x, f0.y); ql_[kc][0] = pack2h_lo(f0.x, f0.y, qh_[kc][0]);
        qh_[kc][1] = pack2h(f1.x, f1.y); ql_[kc][1] = pack2h_lo(f1.x, f1.y, qh_[kc][1]);
        qh_[kc][2] = pack2h(f2.x, f2.y); ql_[kc][2] = pack2h_lo(f2.x, f2.y, qh_[kc][2]);
        qh_[kc][3] = pack2h(f3.x, f3.y); ql_[kc][3] = pack2h_lo(f3.x, f3.y, qh_[kc][3]);
    }

    const uint32_t vrow = (lane & 7) + 8 * ((lane >> 3) & 1);
    const uint32_t vcolB = (lane >> 4) * 16;
    const uint32_t vh_base = (uint32_t)__cvta_generic_to_shared(vh) + vrow * (KHST * 2) + vcolB;
    const uint32_t vl_base = (uint32_t)__cvta_generic_to_shared(vl) + vrow * (KHST * 2) + vcolB;

    float m0 = -INFINITY, m1 = -INFINITY, l0 = 0.f, l1 = 0.f;
    float acc[8][4];
#pragma unroll
    for (int nd = 0; nd < 8; nd++)
#pragma unroll
        for (int c = 0; c < 4; c++) acc[nd][c] = 0.f;

    const int ntiles = 2 * qb + 2;
    for (int kt = 0; kt < ntiles; kt++) {
        __syncthreads();
        const size_t tb = ((size_t)(b * SS + kt * 32)) * KVD + kvh * 64;
        // 32 rows x 64 halves = 256 uint4 per array; 2 iters x 4 arrays per thread
        for (int i = tid; i < 256; i += 128) {
            int j = i >> 3, c = (i & 7) * 8;          // row, half-offset
            size_t go = tb + (size_t)j * KVD + c;
            int so = j * KHST + c;
            *(uint4*)&kh[so] = *(const uint4*)(gkh + go);
            *(uint4*)&kl[so] = *(const uint4*)(gkl + go);
            *(uint4*)&vh[so] = *(const uint4*)(gvh + go);
            *(uint4*)&vl[so] = *(const uint4*)(gvl + go);
        }
        __syncthreads();

        float sc[4][4];
#pragma unroll
        for (int nt = 0; nt < 4; nt++)
#pragma unroll
            for (int c = 0; c < 4; c++) sc[nt][c] = 0.f;

#pragma unroll
        for (int kc = 0; kc < 4; kc++) {
#pragma unroll
            for (int nt = 0; nt < 4; nt++) {
                const __half* krh = &kh[(nt * 8 + gid) * KHST + kc * 16 + 2 * tig];
                const __half* krl = &kl[(nt * 8 + gid) * KHST + kc * 16 + 2 * tig];
                uint32_t bh0 = *(const uint32_t*)krh;
                uint32_t bh1 = *(const uint32_t*)(krh + 8);
                uint32_t bl0 = *(const uint32_t*)krl;
                uint32_t bl1 = *(const uint32_t*)(krl + 8);
                mma16h(sc[nt], qh_[kc], bh0, bh1);
                mma16h(sc[nt], ql_[kc], bh0, bh1);
                mma16h(sc[nt], qh_[kc], bl0, bl1);
            }
        }

        if (kt >= 2 * qb) {
            const int off = (kt - 2 * qb) * 32;
#pragma unroll
            for (int nt = 0; nt < 4; nt++) {
                int c0 = off + nt * 8 + 2 * tig;
                if (c0     > wm + gid)     sc[nt][0] = -INFINITY;
                if (c0 + 1 > wm + gid)     sc[nt][1] = -INFINITY;
                if (c0     > wm + gid + 8) sc[nt][2] = -INFINITY;
                if (c0 + 1 > wm + gid + 8) sc[nt][3] = -INFINITY;
            }
        }

        float mt0 = m0, mt1 = m1;
#pragma unroll
        for (int nt = 0; nt < 4; nt++) {
            mt0 = fmaxf(mt0, fmaxf(sc[nt][0], sc[nt][1]));
            mt1 = fmaxf(mt1, fmaxf(sc[nt][2], sc[nt][3]));
        }
        mt0 = fmaxf(mt0, __shfl_xor_sync(0xffffffffu, mt0, 1));
        mt0 = fmaxf(mt0, __shfl_xor_sync(0xffffffffu, mt0, 2));
        mt1 = fmaxf(mt1, __shfl_xor_sync(0xffffffffu, mt1, 1));
        mt1 = fmaxf(mt1, __shfl_xor_sync(0xffffffffu, mt1, 2));

        float corr0 = __expf(m0 - mt0);
        float corr1 = __expf(m1 - mt1);
        m0 = mt0; m1 = mt1;
        l0 *= corr0; l1 *= corr1;
#pragma unroll
        for (int nd = 0; nd < 8; nd++) {
            acc[nd][0] *= corr0; acc[nd][1] *= corr0;
            acc[nd][2] *= corr1; acc[nd][3] *= corr1;
        }

#pragma unroll
        for (int nt = 0; nt < 4; nt++) {
            sc[nt][0] = __expf(sc[nt][0] - mt0);
            sc[nt][1] = __expf(sc[nt][1] - mt0);
            sc[nt][2] = __expf(sc[nt][2] - mt1);
            sc[nt][3] = __expf(sc[nt][3] - mt1);
            l0 += sc[nt][0] + sc[nt][1];
            l1 += sc[nt][2] + sc[nt][3];
        }

        uint32_t pfh[2][4], pfl[2][4];
#pragma unroll
        for (int kc = 0; kc < 2; kc++) {
            pfh[kc][0] = pack2h(sc[2 * kc][0],     sc[2 * kc][1]);
            pfl[kc][0] = pack2h_lo(sc[2 * kc][0],  sc[2 * kc][1],     pfh[kc][0]);
            pfh[kc][1] = pack2h(sc[2 * kc][2],     sc[2 * kc][3]);
            pfl[kc][1] = pack2h_lo(sc[2 * kc][2],  sc[2 * kc][3],     pfh[kc][1]);
            pfh[kc][2] = pack2h(sc[2 * kc + 1][0], sc[2 * kc + 1][1]);
            pfl[kc][2] = pack2h_lo(sc[2 * kc + 1][0], sc[2 * kc + 1][1], pfh[kc][2]);
            pfh[kc][3] = pack2h(sc[2 * kc + 1][2], sc[2 * kc + 1][3]);
            pfl[kc][3] = pack2h_lo(sc[2 * kc + 1][2], sc[2 * kc + 1][3], pfh[kc][3]);
        }

#pragma unroll
        for (int kc = 0; kc < 2; kc++) {
#pragma unroll
            for (int ndp = 0; ndp < 4; ndp++) {
                uint32_t r0, r1, r2, r3, s0, s1, s2, s3;
                uint32_t off = (uint32_t)(kc * 16 * (KHST * 2) + ndp * 32);
                ldsm4t(r0, r1, r2, r3, vh_base + off);
                ldsm4t(s0, s1, s2, s3, vl_base + off);
                mma16h(acc[ndp * 2],     pfh[kc], r0, r1);
                mma16h(acc[ndp * 2],     pfl[kc], r0, r1);
                mma16h(acc[ndp * 2],     pfh[kc], s0, s1);
                mma16h(acc[ndp * 2 + 1], pfh[kc], r2, r3);
                mma16h(acc[ndp * 2 + 1], pfl[kc], r2, r3);
                mma16h(acc[ndp * 2 + 1], pfh[kc], s2, s3);
            }
        }
    }

    l0 += __shfl_xor_sync(0xffffffffu, l0, 1);
    l0 += __shfl_xor_sync(0xffffffffu, l0, 2);
    l1 += __shfl_xor_sync(0xffffffffu, l1, 1);
    l1 += __shfl_xor_sync(0xffffffffu, l1, 2);
    const float inv0 = 1.f / l0;
    const float inv1 = 1.f / l1;

    float* yr0 = y + ((size_t)(b * SS + qb * 64 + wm + gid    )) * DIMM + h * 64 + 2 * tig;
    float* yr1 = y + ((size_t)(b * SS + qb * 64 + wm + gid + 8)) * DIMM + h * 64 + 2 * tig;
#pragma unroll
    for (int nd = 0; nd < 8; nd++) {
        *(float2*)(yr0 + nd * 8) = make_float2(cvt_tf32(acc[nd][0] * inv0),
                                               cvt_tf32(acc[nd][1] * inv0));
        *(float2*)(yr1 + nd * 8) = make_float2(cvt_tf32(acc[nd][2] * inv1),
                                               cvt_tf32(acc[nd][3] * inv1));
    }
}

// ---------------------------------------------------------------------------
extern "C" void kernel_launch(void* const* d_in, const int* in_sizes, int n_in,
                              void* d_out, int out_size)
{
    const float* x  = (const float*)d_in[0];
    const float* Wq = (const float*)d_in[1];
    const float* Wk = (const float*)d_in[2];
    const float* Wv = (const float*)d_in[3];
    const float* Wo = (const float*)d_in[4];
    const float* qg = (const float*)d_in[5];
    float* out = (float*)d_out;

    float *qp, *kp, *vp, *yp, *xr, *wq, *wk, *wv, *wo;
    __half *khp, *klp, *vhp, *vlp;
    cudaGetSymbolAddress((void**)&qp,  g_q);
    cudaGetSymbolAddress((void**)&kp,  g_k);
    cudaGetSymbolAddress((void**)&vp,  g_v);
    cudaGetSymbolAddress((void**)&yp,  g_y);
    cudaGetSymbolAddress((void**)&xr,  g_xr);
    cudaGetSymbolAddress((void**)&wq,  g_wq);
    cudaGetSymbolAddress((void**)&wk,  g_wk);
    cudaGetSymbolAddress((void**)&wv,  g_wv);
    cudaGetSymbolAddress((void**)&wo,  g_wo);
    cudaGetSymbolAddress((void**)&khp, g_kh);
    cudaGetSymbolAddress((void**)&klp, g_kl);
    cudaGetSymbolAddress((void**)&vhp, g_vh);
    cudaGetSymbolAddress((void**)&vlp, g_vl);

    // tf32 pre-round of GEMM operands
    round_tf32_kernel<<<(MROWS * DIMM / 4 + 255) / 256, 256>>>(x,  xr, MROWS * DIMM / 4);
    round_tf32_kernel<<<(DIMM * DIMM / 4 + 255) / 256, 256>>>(Wq, wq, DIMM * DIMM / 4);
    round_tf32_kernel<<<(KVD  * DIMM / 4 + 255) / 256, 256>>>(Wk, wk, KVD * DIMM / 4);
    round_tf32_kernel<<<(KVD  * DIMM / 4 + 255) / 256, 256>>>(Wv, wv, KVD * DIMM / 4);
    round_tf32_kernel<<<(DIMM * DIMM / 4 + 255) / 256, 256>>>(Wo, wo, DIMM * DIMM / 4);

    // QKV projections
    gemm_tf32_db_kernel<<<dim3(DIMM / 128, MROWS / 128), 256>>>(xr, wq, qp, MROWS, DIMM, DIMM);
    gemm_tf32_db_kernel<<<dim3(KVD  / 128, MROWS / 128), 256>>>(xr, wk, kp, MROWS, KVD,  DIMM);
    gemm_tf32_db_kernel<<<dim3(KVD  / 128, MROWS / 128), 256>>>(xr, wv, vp, MROWS, KVD,  DIMM);

    // norm/rope; K emits split fp16, V split kernel
    norm_rope_q_kernel<<<dim3(MROWS, HH / 4),  dim3(32, 4)>>>(qp, qg);
    norm_rope_k_kernel<<<dim3(MROWS, KVHH / 4), dim3(32, 4)>>>(kp, khp, klp);
    split_v_kernel<<<(MROWS * KVD / 2 + 255) / 256, 256>>>(vp, vhp, vlp, MROWS * KVD / 2);

    // attention (writes tf32-rounded y)
    attn_tc_kernel<<<dim3(SS / 64, HH, BB), 128>>>(qp, khp, klp, vhp, vlp, yp);

    // output projection
    gemm_tf32_db_kernel<<<dim3(DIMM / 128, MROWS / 128), 256>>>(yp, wo, out, MROWS, DIMM, DIMM);
}

// round 8
// speedup vs baseline: 4.5869x; 1.0689x over previous
#include <cuda_runtime.h>
#include <cuda_fp16.h>
#include <math.h>
#include <stdint.h>

#define BB   4
#define SS   2048
#define DIMM 1024
#define HH   16
#define KVHH 4
#define HDD  64
#define KVD  256
#define QKVD 1536
#define MROWS (BB*SS)   // 8192

// Scratch (device globals — no allocations allowed)
__device__ float  g_qkv [(size_t)MROWS * QKVD];  // 48 MB fused q|k|v
__device__ float  g_y   [(size_t)MROWS * DIMM];  // 32 MB
__device__ float  g_xr  [(size_t)MROWS * DIMM];  // 32 MB tf32-rounded x
__device__ float  g_wqkv[(size_t)QKVD * DIMM];   //  6 MB
__device__ float  g_wo  [(size_t)DIMM * DIMM];   //  4 MB
__device__ __half g_qh  [(size_t)MROWS * DIMM];  // 16 MB
__device__ __half g_ql  [(size_t)MROWS * DIMM];
__device__ __half g_kh  [(size_t)MROWS * KVD];   //  4 MB
__device__ __half g_kl  [(size_t)MROWS * KVD];
__device__ __half g_vh  [(size_t)MROWS * KVD];

__device__ __forceinline__ float cvt_tf32(float x) {
    uint32_t u;
    asm("cvt.rna.tf32.f32 %0, %1;" : "=r"(u) : "f"(x));
    return __uint_as_float(u);
}

__device__ __forceinline__ void mma8(float* c, const float* a, float b0, float b1) {
    asm volatile(
        "mma.sync.aligned.m16n8k8.row.col.f32.tf32.tf32.f32 "
        "{%0,%1,%2,%3}, {%4,%5,%6,%7}, {%8,%9}, {%0,%1,%2,%3};\n"
        : "+f"(c[0]), "+f"(c[1]), "+f"(c[2]), "+f"(c[3])
        : "r"(__float_as_uint(a[0])), "r"(__float_as_uint(a[1])),
          "r"(__float_as_uint(a[2])), "r"(__float_as_uint(a[3])),
          "r"(__float_as_uint(b0)), "r"(__float_as_uint(b1)));
}

__device__ __forceinline__ void mma16h(float* c, const uint32_t* a, uint32_t b0, uint32_t b1) {
    asm volatile(
        "mma.sync.aligned.m16n8k16.row.col.f32.f16.f16.f32 "
        "{%0,%1,%2,%3}, {%4,%5,%6,%7}, {%8,%9}, {%0,%1,%2,%3};\n"
        : "+f"(c[0]), "+f"(c[1]), "+f"(c[2]), "+f"(c[3])
        : "r"(a[0]), "r"(a[1]), "r"(a[2]), "r"(a[3]), "r"(b0), "r"(b1));
}

__device__ __forceinline__ void ldsm4t(uint32_t& r0, uint32_t& r1, uint32_t& r2, uint32_t& r3,
                                       uint32_t addr) {
    asm volatile("ldmatrix.sync.aligned.m8n8.x4.trans.shared.b16 {%0,%1,%2,%3}, [%4];"
                 : "=r"(r0), "=r"(r1), "=r"(r2), "=r"(r3) : "r"(addr));
}

__device__ __forceinline__ uint32_t pack2h(float x, float y) {
    __half2 t = __floats2half2_rn(x, y);
    return *reinterpret_cast<uint32_t*>(&t);
}
__device__ __forceinline__ uint32_t pack2h_lo(float x, float y, uint32_t hi) {
    __half2 h = *reinterpret_cast<__half2*>(&hi);
    __half2 t = __floats2half2_rn(x - __low2float(h), y - __high2float(h));
    return *reinterpret_cast<uint32_t*>(&t);
}

__device__ __forceinline__ void cp16(void* smem, const void* g) {
    uint32_t s = (uint32_t)__cvta_generic_to_shared(smem);
    asm volatile("cp.async.cg.shared.global [%0], [%1], 16;\n" :: "r"(s), "l"(g));
}

// ---------------------------------------------------------------------------
__global__ void round_tf32_kernel(const float* __restrict__ in, float* __restrict__ out, int n4)
{
    int i = blockIdx.x * blockDim.x + threadIdx.x;
    if (i < n4) {
        float4 v = ((const float4*)in)[i];
        v.x = cvt_tf32(v.x); v.y = cvt_tf32(v.y);
        v.z = cvt_tf32(v.z); v.w = cvt_tf32(v.w);
        ((float4*)out)[i] = v;
    }
}

// V (from fused qkv buffer) -> fp16 hi only
__global__ void conv_vh_kernel(const float* __restrict__ qkv, __half* __restrict__ vh, int n2)
{
    int i = blockIdx.x * blockDim.x + threadIdx.x;
    if (i < n2) {
        int row = i >> 7, col = i & 127;                 // 128 float2 per KVD row
        float2 f = ((const float2*)qkv)[(size_t)row * (QKVD / 2) + 640 + col];
        ((uint32_t*)vh)[i] = pack2h(f.x, f.y);
    }
}

// ---------------------------------------------------------------------------
// TF32 GEMM, cp.async double-buffered. Inputs tf32-pre-rounded.
// ---------------------------------------------------------------------------
__global__ void __launch_bounds__(256)
gemm_tf32_db_kernel(const float* __restrict__ A, const float* __restrict__ W,
                    float* __restrict__ C, int M, int N, int K)
{
    __shared__ float As[2][128][20];
    __shared__ float Bs[2][128][20];

    const int tid  = threadIdx.x;
    const int lane = tid & 31;
    const int wid  = tid >> 5;
    const int wm   = (wid & 3) * 32;
    const int wn   = (wid >> 2) * 64;
    const int gid  = lane >> 2;
    const int tig  = lane & 3;
    const int bm   = blockIdx.y * 128;
    const int bn   = blockIdx.x * 128;

    const int lm  = tid >> 2;
    const int lkc = (tid & 3) * 4;

    const float* Arow0 = A + (size_t)(bm + lm) * K + lkc;
    const float* Arow1 = Arow0 + (size_t)64 * K;
    const float* Wrow0 = W + (size_t)(bn + lm) * K + lkc;
    const float* Wrow1 = Wrow0 + (size_t)64 * K;

    float acc[2][8][4];
#pragma unroll
    for (int i = 0; i < 2; i++)
#pragma unroll
        for (int j = 0; j < 8; j++)
#pragma unroll
            for (int c = 0; c < 4; c++) acc[i][j][c] = 0.f;

    const int T = K / 16;

    cp16(&As[0][lm][lkc],      Arow0);
    cp16(&As[0][lm + 64][lkc], Arow1);
    cp16(&Bs[0][lm][lkc],      Wrow0);
    cp16(&Bs[0][lm + 64][lkc], Wrow1);
    asm volatile("cp.async.commit_group;\n");

    for (int t = 0; t < T; t++) {
        if (t + 1 < T) {
            const int s = (t + 1) & 1, k0 = (t + 1) * 16;
            cp16(&As[s][lm][lkc],      Arow0 + k0);
            cp16(&As[s][lm + 64][lkc], Arow1 + k0);
            cp16(&Bs[s][lm][lkc],      Wrow0 + k0);
            cp16(&Bs[s][lm + 64][lkc], Wrow1 + k0);
            asm volatile("cp.async.commit_group;\n");
            asm volatile("cp.async.wait_group 1;\n");
        } else {
            asm volatile("cp.async.wait_group 0;\n");
        }
        __syncthreads();

        const int cb = t & 1;
#pragma unroll
        for (int ks = 0; ks < 2; ks++) {
            const int kk = ks * 8;
            float a[2][4], b[8][2];
#pragma unroll
            for (int mt = 0; mt < 2; mt++) {
                a[mt][0] = As[cb][wm + mt * 16 + gid    ][kk + tig    ];
                a[mt][1] = As[cb][wm + mt * 16 + gid + 8][kk + tig    ];
                a[mt][2] = As[cb][wm + mt * 16 + gid    ][kk + tig + 4];
                a[mt][3] = As[cb][wm + mt * 16 + gid + 8][kk + tig + 4];
            }
#pragma unroll
            for (int nt = 0; nt < 8; nt++) {
                b[nt][0] = Bs[cb][wn + nt * 8 + gid][kk + tig    ];
                b[nt][1] = Bs[cb][wn + nt * 8 + gid][kk + tig + 4];
            }
#pragma unroll
            for (int mt = 0; mt < 2; mt++)
#pragma unroll
                for (int nt = 0; nt < 8; nt++)
                    mma8(acc[mt][nt], a[mt], b[nt][0], b[nt][1]);
        }
        __syncthreads();
    }

#pragma unroll
    for (int mt = 0; mt < 2; mt++) {
        const int row0 = bm + wm + mt * 16 + gid;
#pragma unroll
        for (int nt = 0; nt < 8; nt++) {
            const int col = bn + wn + nt * 8 + tig * 2;
            *(float2*)&C[(size_t)row0 * N + col]       = make_float2(acc[mt][nt][0], acc[mt][nt][1]);
            *(float2*)&C[(size_t)(row0 + 8) * N + col] = make_float2(acc[mt][nt][2], acc[mt][nt][3]);
        }
    }
}

// ---------------------------------------------------------------------------
// RMSNorm + RoPE + gain for Q; emits split fp16 with 0.125*gain baked in.
// ---------------------------------------------------------------------------
__global__ void norm_rope_q_kernel(const float* __restrict__ qkv, const float* __restrict__ gain,
                                   __half* __restrict__ qh, __half* __restrict__ ql)
{
    const int row = blockIdx.x;
    const int h = blockIdx.y * blockDim.y + threadIdx.y;
    const int s = row & (SS - 1);
    const int d = threadIdx.x;

    const float* p = qkv + (size_t)row * QKVD + h * 64;
    float t1 = p[d];
    float t2 = p[d + 32];

    float ss = t1 * t1 + t2 * t2;
#pragma unroll
    for (int o = 16; o; o >>= 1) ss += __shfl_xor_sync(0xffffffffu, ss, o);
    float r = rsqrtf(ss * (1.0f / 64.0f) + 1e-6f);
    t1 *= r; t2 *= r;

    float inv_freq = exp2f(-(float)d * (13.287712379549449f / 32.0f));
    float th = (float)s * inv_freq;
    float c, sn;
    sincosf(th, &sn, &c);

    float g = gain[h] * 0.125f;
    float o1 = ( t1 * c + t2 * sn) * g;
    float o2 = (-t1 * sn + t2 * c) * g;

    size_t base = (size_t)row * DIMM + h * 64;
    __half h1 = __float2half_rn(o1);
    __half h2 = __float2half_rn(o2);
    qh[base + d]      = h1;  ql[base + d]      = __float2half_rn(o1 - __half2float(h1));
    qh[base + d + 32] = h2;  ql[base + d + 32] = __float2half_rn(o2 - __half2float(h2));
}

// ---------------------------------------------------------------------------
// RMSNorm + RoPE for K; emits split fp16.
// ---------------------------------------------------------------------------
__global__ void norm_rope_k_kernel(const float* __restrict__ qkv,
                                   __half* __restrict__ kh, __half* __restrict__ kl)
{
    const int row = blockIdx.x;
    const int h = blockIdx.y * blockDim.y + threadIdx.y;
    const int s = row & (SS - 1);
    const int d = threadIdx.x;

    const float* p = qkv + (size_t)row * QKVD + 1024 + h * 64;
    float t1 = p[d];
    float t2 = p[d + 32];

    float ss = t1 * t1 + t2 * t2;
#pragma unroll
    for (int o = 16; o; o >>= 1) ss += __shfl_xor_sync(0xffffffffu, ss, o);
    float r = rsqrtf(ss * (1.0f / 64.0f) + 1e-6f);
    t1 *= r; t2 *= r;

    float inv_freq = exp2f(-(float)d * (13.287712379549449f / 32.0f));
    float th = (float)s * inv_freq;
    float c, sn;
    sincosf(th, &sn, &c);

    float o1 =  t1 * c + t2 * sn;
    float o2 = -t1 * sn + t2 * c;

    size_t base = (size_t)row * KVD + h * 64;
    __half h1 = __float2half_rn(o1);
    __half h2 = __float2half_rn(o2);
    kh[base + d]      = h1;  kl[base + d]      = __float2half_rn(o1 - __half2float(h1));
    kh[base + d + 32] = h2;  kl[base + d + 32] = __float2half_rn(o2 - __half2float(h2));
}

// ---------------------------------------------------------------------------
// Causal GQA flash attention — split-fp16, 64-key tiles, V hi-only PV.
// grid (S/64, H, B); 128 threads (4 warps); warp w owns query rows w*16..+15.
// ---------------------------------------------------------------------------
#define KHST 72

__global__ void __launch_bounds__(128)
attn_tc_kernel(const __half* __restrict__ gqh, const __half* __restrict__ gql,
               const __half* __restrict__ gkh, const __half* __restrict__ gkl,
               const __half* __restrict__ gvh, float* __restrict__ y)
{
    __shared__ __half kh[64 * KHST], kl[64 * KHST], vh[64 * KHST];  // 27648 B

    const int tid = threadIdx.x, lane = tid & 31, wid = tid >> 5;
    const int gid = lane >> 2, tig = lane & 3;
    const int qb = blockIdx.x, h = blockIdx.y, b = blockIdx.z;
    const int kvh = h >> 2;
    const int wm = wid * 16;

    // Q fragments straight from pre-split global fp16 (scale+gain baked in)
    uint32_t qh_[4][4], ql_[4][4];
    {
        const size_t r0 = (size_t)(b * SS + qb * 64 + wm + gid    ) * DIMM + h * 64 + 2 * tig;
        const size_t r1 = (size_t)(b * SS + qb * 64 + wm + gid + 8) * DIMM + h * 64 + 2 * tig;
#pragma unroll
        for (int kc = 0; kc < 4; kc++) {
            qh_[kc][0] = *(const uint32_t*)(gqh + r0 + kc * 16);
            qh_[kc][1] = *(const uint32_t*)(gqh + r1 + kc * 16);
            qh_[kc][2] = *(const uint32_t*)(gqh + r0 + kc * 16 + 8);
            qh_[kc][3] = *(const uint32_t*)(gqh + r1 + kc * 16 + 8);
            ql_[kc][0] = *(const uint32_t*)(gql + r0 + kc * 16);
            ql_[kc][1] = *(const uint32_t*)(gql + r1 + kc * 16);
            ql_[kc][2] = *(const uint32_t*)(gql + r0 + kc * 16 + 8);
            ql_[kc][3] = *(const uint32_t*)(gql + r1 + kc * 16 + 8);
        }
    }

    const uint32_t vrow = (lane & 7) + 8 * ((lane >> 3) & 1);
    const uint32_t vcolB = (lane >> 4) * 16;
    const uint32_t vh_base = (uint32_t)__cvta_generic_to_shared(vh) + vrow * (KHST * 2) + vcolB;

    float m0 = -INFINITY, m1 = -INFINITY, l0 = 0.f, l1 = 0.f;
    float acc[8][4];
#pragma unroll
    for (int nd = 0; nd < 8; nd++)
#pragma unroll
        for (int c = 0; c < 4; c++) acc[nd][c] = 0.f;

    const int ntiles = qb + 1;
    for (int kt = 0; kt < ntiles; kt++) {
        if (kt) __syncthreads();
        const size_t tb = ((size_t)(b * SS + kt * 64)) * KVD + kvh * 64;
        // 64 rows x 64 halves = 512 uint4 per array
        for (int i = tid; i < 512; i += 128) {
            int j = i >> 3, c = (i & 7) * 8;
            size_t go = tb + (size_t)j * KVD + c;
            int so = j * KHST + c;
            *(uint4*)&kh[so] = *(const uint4*)(gkh + go);
            *(uint4*)&kl[so] = *(const uint4*)(gkl + go);
            *(uint4*)&vh[so] = *(const uint4*)(gvh + go);
        }
        __syncthreads();

        // ---- scores: S[16q x 64k], split-fp16 x3 ----
        float sc[8][4];
#pragma unroll
        for (int nt = 0; nt < 8; nt++)
#pragma unroll
            for (int c = 0; c < 4; c++) sc[nt][c] = 0.f;

#pragma unroll
        for (int kc = 0; kc < 4; kc++) {
#pragma unroll
            for (int nt = 0; nt < 8; nt++) {
                const __half* krh = &kh[(nt * 8 + gid) * KHST + kc * 16 + 2 * tig];
                const __half* krl = &kl[(nt * 8 + gid) * KHST + kc * 16 + 2 * tig];
                uint32_t bh0 = *(const uint32_t*)krh;
                uint32_t bh1 = *(const uint32_t*)(krh + 8);
                uint32_t bl0 = *(const uint32_t*)krl;
                uint32_t bl1 = *(const uint32_t*)(krl + 8);
                mma16h(sc[nt], qh_[kc], bh0, bh1);
                mma16h(sc[nt], ql_[kc], bh0, bh1);
                mma16h(sc[nt], qh_[kc], bl0, bl1);
            }
        }

        // causal mask (diagonal tile only)
        if (kt == qb) {
#pragma unroll
            for (int nt = 0; nt < 8; nt++) {
                int c0 = nt * 8 + 2 * tig;
                if (c0     > wm + gid)     sc[nt][0] = -INFINITY;
                if (c0 + 1 > wm + gid)     sc[nt][1] = -INFINITY;
                if (c0     > wm + gid + 8) sc[nt][2] = -INFINITY;
                if (c0 + 1 > wm + gid + 8) sc[nt][3] = -INFINITY;
            }
        }

        float mt0 = m0, mt1 = m1;
#pragma unroll
        for (int nt = 0; nt < 8; nt++) {
            mt0 = fmaxf(mt0, fmaxf(sc[nt][0], sc[nt][1]));
            mt1 = fmaxf(mt1, fmaxf(sc[nt][2], sc[nt][3]));
        }
        mt0 = fmaxf(mt0, __shfl_xor_sync(0xffffffffu, mt0, 1));
        mt0 = fmaxf(mt0, __shfl_xor_sync(0xffffffffu, mt0, 2));
        mt1 = fmaxf(mt1, __shfl_xor_sync(0xffffffffu, mt1, 1));
        mt1 = fmaxf(mt1, __shfl_xor_sync(0xffffffffu, mt1, 2));

        float corr0 = __expf(m0 - mt0);
        float corr1 = __expf(m1 - mt1);
        m0 = mt0; m1 = mt1;
        l0 *= corr0; l1 *= corr1;
#pragma unroll
        for (int nd = 0; nd < 8; nd++) {
            acc[nd][0] *= corr0; acc[nd][1] *= corr0;
            acc[nd][2] *= corr1; acc[nd][3] *= corr1;
        }

#pragma unroll
        for (int nt = 0; nt < 8; nt++) {
            sc[nt][0] = __expf(sc[nt][0] - mt0);
            sc[nt][1] = __expf(sc[nt][1] - mt0);
            sc[nt][2] = __expf(sc[nt][2] - mt1);
            sc[nt][3] = __expf(sc[nt][3] - mt1);
            l0 += sc[nt][0] + sc[nt][1];
            l1 += sc[nt][2] + sc[nt][3];
        }

        // ---- PV: Y += P·V_hi, P split x2; V b-frags via ldmatrix.trans ----
#pragma unroll
        for (int kc = 0; kc < 4; kc++) {
            uint32_t pfh[4], pfl[4];
            pfh[0] = pack2h(sc[2 * kc][0],     sc[2 * kc][1]);
            pfl[0] = pack2h_lo(sc[2 * kc][0],  sc[2 * kc][1],     pfh[0]);
            pfh[1] = pack2h(sc[2 * kc][2],     sc[2 * kc][3]);
            pfl[1] = pack2h_lo(sc[2 * kc][2],  sc[2 * kc][3],     pfh[1]);
            pfh[2] = pack2h(sc[2 * kc + 1][0], sc[2 * kc + 1][1]);
            pfl[2] = pack2h_lo(sc[2 * kc + 1][0], sc[2 * kc + 1][1], pfh[2]);
            pfh[3] = pack2h(sc[2 * kc + 1][2], sc[2 * kc + 1][3]);
            pfl[3] = pack2h_lo(sc[2 * kc + 1][2], sc[2 * kc + 1][3], pfh[3]);
#pragma unroll
            for (int ndp = 0; ndp < 4; ndp++) {
                uint32_t r0, r1, r2, r3;
                ldsm4t(r0, r1, r2, r3, vh_base + (uint32_t)(kc * 16 * (KHST * 2) + ndp * 32));
                mma16h(acc[ndp * 2],     pfh, r0, r1);
                mma16h(acc[ndp * 2],     pfl, r0, r1);
                mma16h(acc[ndp * 2 + 1], pfh, r2, r3);
                mma16h(acc[ndp * 2 + 1], pfl, r2, r3);
            }
        }
    }

    l0 += __shfl_xor_sync(0xffffffffu, l0, 1);
    l0 += __shfl_xor_sync(0xffffffffu, l0, 2);
    l1 += __shfl_xor_sync(0xffffffffu, l1, 1);
    l1 += __shfl_xor_sync(0xffffffffu, l1, 2);
    const float inv0 = 1.f / l0;
    const float inv1 = 1.f / l1;

    float* yr0 = y + ((size_t)(b * SS + qb * 64 + wm + gid    )) * DIMM + h * 64 + 2 * tig;
    float* yr1 = y + ((size_t)(b * SS + qb * 64 + wm + gid + 8)) * DIMM + h * 64 + 2 * tig;
#pragma unroll
    for (int nd = 0; nd < 8; nd++) {
        *(float2*)(yr0 + nd * 8) = make_float2(cvt_tf32(acc[nd][0] * inv0),
                                               cvt_tf32(acc[nd][1] * inv0));
        *(float2*)(yr1 + nd * 8) = make_float2(cvt_tf32(acc[nd][2] * inv1),
                                               cvt_tf32(acc[nd][3] * inv1));
    }
}

// ---------------------------------------------------------------------------
extern "C" void kernel_launch(void* const* d_in, const int* in_sizes, int n_in,
                              void* d_out, int out_size)
{
    const float* x  = (const float*)d_in[0];
    const float* Wq = (const float*)d_in[1];
    const float* Wk = (const float*)d_in[2];
    const float* Wv = (const float*)d_in[3];
    const float* Wo = (const float*)d_in[4];
    const float* qg = (const float*)d_in[5];
    float* out = (float*)d_out;

    float *qkv, *yp, *xr, *wqkv, *wo;
    __half *qhp, *qlp, *khp, *klp, *vhp;
    cudaGetSymbolAddress((void**)&qkv,  g_qkv);
    cudaGetSymbolAddress((void**)&yp,   g_y);
    cudaGetSymbolAddress((void**)&xr,   g_xr);
    cudaGetSymbolAddress((void**)&wqkv, g_wqkv);
    cudaGetSymbolAddress((void**)&wo,   g_wo);
    cudaGetSymbolAddress((void**)&qhp,  g_qh);
    cudaGetSymbolAddress((void**)&qlp,  g_ql);
    cudaGetSymbolAddress((void**)&khp,  g_kh);
    cudaGetSymbolAddress((void**)&klp,  g_kl);
    cudaGetSymbolAddress((void**)&vhp,  g_vh);

    // tf32 pre-round (weights concatenated: Wq rows 0-1023, Wk 1024-1279, Wv 1280-1535)
    round_tf32_kernel<<<(MROWS * DIMM / 4 + 255) / 256, 256>>>(x,  xr, MROWS * DIMM / 4);
    round_tf32_kernel<<<(DIMM * DIMM / 4 + 255) / 256, 256>>>(Wq, wqkv, DIMM * DIMM / 4);
    round_tf32_kernel<<<(KVD  * DIMM / 4 + 255) / 256, 256>>>(Wk, wqkv + (size_t)DIMM * DIMM, KVD * DIMM / 4);
    round_tf32_kernel<<<(KVD  * DIMM / 4 + 255) / 256, 256>>>(Wv, wqkv + (size_t)(DIMM + KVD) * DIMM, KVD * DIMM / 4);
    round_tf32_kernel<<<(DIMM * DIMM / 4 + 255) / 256, 256>>>(Wo, wo, DIMM * DIMM / 4);

    // fused QKV projection (N = 1536)
    gemm_tf32_db_kernel<<<dim3(QKVD / 128, MROWS / 128), 256>>>(xr, wqkv, qkv, MROWS, QKVD, DIMM);

    // norm/rope -> split fp16; V -> fp16 hi
    norm_rope_q_kernel<<<dim3(MROWS, HH / 4),   dim3(32, 4)>>>(qkv, qg, qhp, qlp);
    norm_rope_k_kernel<<<dim3(MROWS, KVHH / 4), dim3(32, 4)>>>(qkv, khp, klp);
    conv_vh_kernel<<<(MROWS * KVD / 2 + 255) / 256, 256>>>(qkv, vhp, MROWS * KVD / 2);

    // attention (writes tf32-rounded y)
    attn_tc_kernel<<<dim3(SS / 64, HH, BB), 128>>>(qhp, qlp, khp, klp, vhp, yp);

    // output projection
    gemm_tf32_db_kernel<<<dim3(DIMM / 128, MROWS / 128), 256>>>(yp, wo, out, MROWS, DIMM, DIMM);
}

// round 9
// speedup vs baseline: 4.8438x; 1.0560x over previous
#include <cuda_runtime.h>
#include <cuda_fp16.h>
#include <math.h>
#include <stdint.h>

#define BB   4
#define SS   2048
#define DIMM 1024
#define HH   16
#define KVHH 4
#define HDD  64
#define KVD  256
#define QKVD 1536
#define MROWS (BB*SS)   // 8192

// Scratch (device globals — no allocations allowed)
__device__ float  g_qkv  [(size_t)MROWS * QKVD];  // 48 MB fused q|k|v (fp32)
__device__ __half g_xh   [(size_t)MROWS * DIMM];  // 16 MB
__device__ __half g_xl   [(size_t)MROWS * DIMM];
__device__ __half g_wqkvh[(size_t)QKVD * DIMM];   //  3 MB
__device__ __half g_woh  [(size_t)DIMM * DIMM];   //  2 MB
__device__ __half g_yh   [(size_t)MROWS * DIMM];  // 16 MB
__device__ __half g_yl   [(size_t)MROWS * DIMM];
__device__ __half g_qh   [(size_t)MROWS * DIMM];  // 16 MB
__device__ __half g_ql   [(size_t)MROWS * DIMM];
__device__ __half g_kh   [(size_t)MROWS * KVD];   //  4 MB
__device__ __half g_kl   [(size_t)MROWS * KVD];
__device__ __half g_vh   [(size_t)MROWS * KVD];

__device__ __forceinline__ void mma16h(float* c, const uint32_t* a, uint32_t b0, uint32_t b1) {
    asm volatile(
        "mma.sync.aligned.m16n8k16.row.col.f32.f16.f16.f32 "
        "{%0,%1,%2,%3}, {%4,%5,%6,%7}, {%8,%9}, {%0,%1,%2,%3};\n"
        : "+f"(c[0]), "+f"(c[1]), "+f"(c[2]), "+f"(c[3])
        : "r"(a[0]), "r"(a[1]), "r"(a[2]), "r"(a[3]), "r"(b0), "r"(b1));
}

__device__ __forceinline__ void ldsm4(uint32_t* r, uint32_t addr) {
    asm volatile("ldmatrix.sync.aligned.m8n8.x4.shared.b16 {%0,%1,%2,%3}, [%4];"
                 : "=r"(r[0]), "=r"(r[1]), "=r"(r[2]), "=r"(r[3]) : "r"(addr));
}

__device__ __forceinline__ void ldsm4t(uint32_t& r0, uint32_t& r1, uint32_t& r2, uint32_t& r3,
                                       uint32_t addr) {
    asm volatile("ldmatrix.sync.aligned.m8n8.x4.trans.shared.b16 {%0,%1,%2,%3}, [%4];"
                 : "=r"(r0), "=r"(r1), "=r"(r2), "=r"(r3) : "r"(addr));
}

__device__ __forceinline__ uint32_t pack2h(float x, float y) {
    __half2 t = __floats2half2_rn(x, y);
    return *reinterpret_cast<uint32_t*>(&t);
}
__device__ __forceinline__ uint32_t pack2h_lo(float x, float y, uint32_t hi) {
    __half2 h = *reinterpret_cast<__half2*>(&hi);
    __half2 t = __floats2half2_rn(x - __low2float(h), y - __high2float(h));
    return *reinterpret_cast<uint32_t*>(&t);
}

__device__ __forceinline__ void cp16(void* smem, const void* g) {
    uint32_t s = (uint32_t)__cvta_generic_to_shared(smem);
    asm volatile("cp.async.cg.shared.global [%0], [%1], 16;\n" :: "r"(s), "l"(g));
}

// ---------------------------------------------------------------------------
// x -> fp16 hi/lo split
__global__ void split_x_kernel(const float* __restrict__ in,
                               __half* __restrict__ xh, __half* __restrict__ xl, int n2)
{
    int i = blockIdx.x * blockDim.x + threadIdx.x;
    if (i < n2) {
        float2 f = ((const float2*)in)[i];
        uint32_t hi = pack2h(f.x, f.y);
        ((uint32_t*)xh)[i] = hi;
        ((uint32_t*)xl)[i] = pack2h_lo(f.x, f.y, hi);
    }
}

// weights -> fp16 (hi only)
__global__ void conv_w_kernel(const float* __restrict__ in, __half* __restrict__ out, int n2)
{
    int i = blockIdx.x * blockDim.x + threadIdx.x;
    if (i < n2) {
        float2 f = ((const float2*)in)[i];
        ((uint32_t*)out)[i] = pack2h(f.x, f.y);
    }
}

// V (from fused qkv buffer) -> fp16 hi only
__global__ void conv_vh_kernel(const float* __restrict__ qkv, __half* __restrict__ vh, int n2)
{
    int i = blockIdx.x * blockDim.x + threadIdx.x;
    if (i < n2) {
        int row = i >> 7, col = i & 127;
        float2 f = ((const float2*)qkv)[(size_t)row * (QKVD / 2) + 640 + col];
        ((uint32_t*)vh)[i] = pack2h(f.x, f.y);
    }
}

// ---------------------------------------------------------------------------
// Split-FP16 GEMM: C[M,N] = (Ah+Al)[M,K] @ Bh[N,K]^T,  fp32 accum/output.
// CTA 128x128, BK=16, 256 thr, 8 warps (4m x 2n), warp tile 32x64.
// All fragments via ldmatrix.x4; smem rows padded to 24 halves (48 B).
// ---------------------------------------------------------------------------
#define GST 24   // halves per smem row

__global__ void __launch_bounds__(256)
gemm_fp16s_kernel(const __half* __restrict__ Ahg, const __half* __restrict__ Alg,
                  const __half* __restrict__ Bhg, float* __restrict__ C,
                  int M, int N, int K)
{
    __shared__ __half Ah[2][128 * GST], Al[2][128 * GST], Bh[2][128 * GST];  // 36864 B

    const int tid  = threadIdx.x;
    const int lane = tid & 31;
    const int wid  = tid >> 5;
    const int wm   = (wid & 3) * 32;
    const int wn   = (wid >> 2) * 64;
    const int gid  = lane >> 2;
    const int tig  = lane & 3;
    const int bm   = blockIdx.y * 128;
    const int bn   = blockIdx.x * 128;

    // loader: 256 chunks of 16B per array; thread -> (row, 8-half chunk)
    const int lrow = tid >> 1;
    const int lch  = (tid & 1) * 8;
    const __half* Arow = Ahg + (size_t)(bm + lrow) * K + lch;
    const __half* Lrow = Alg + (size_t)(bm + lrow) * K + lch;
    const __half* Brow = Bhg + (size_t)(bn + lrow) * K + lch;
    const int soff = lrow * GST + lch;

    // ldmatrix lane addressing
    const int tl = lane >> 3, lr = lane & 7;
    const int a_row = lr + ((tl & 1) ? 8 : 0);      // + m-tile base
    const int a_kb  = (tl >= 2) ? 16 : 0;
    const int b_row = lr + ((tl >= 2) ? 8 : 0);     // + n-pair base
    const int b_kb  = (tl & 1) ? 16 : 0;

    uint32_t aAddrH[2][2], aAddrL[2][2], bAddr[2][4];
#pragma unroll
    for (int s = 0; s < 2; s++) {
#pragma unroll
        for (int mt = 0; mt < 2; mt++) {
            int r = wm + mt * 16 + a_row;
            aAddrH[s][mt] = (uint32_t)__cvta_generic_to_shared(&Ah[s][r * GST]) + a_kb;
            aAddrL[s][mt] = (uint32_t)__cvta_generic_to_shared(&Al[s][r * GST]) + a_kb;
        }
#pragma unroll
        for (int np = 0; np < 4; np++) {
            int r = wn + np * 16 + b_row;
            bAddr[s][np] = (uint32_t)__cvta_generic_to_shared(&Bh[s][r * GST]) + b_kb;
        }
    }

    float acc[2][8][4];
#pragma unroll
    for (int i = 0; i < 2; i++)
#pragma unroll
        for (int j = 0; j < 8; j++)
#pragma unroll
            for (int c = 0; c < 4; c++) acc[i][j][c] = 0.f;

    const int T = K / 16;

    cp16(&Ah[0][soff], Arow);
    cp16(&Al[0][soff], Lrow);
    cp16(&Bh[0][soff], Brow);
    asm volatile("cp.async.commit_group;\n");

    for (int t = 0; t < T; t++) {
        if (t + 1 < T) {
            const int s = (t + 1) & 1, k0 = (t + 1) * 16;
            cp16(&Ah[s][soff], Arow + k0);
            cp16(&Al[s][soff], Lrow + k0);
            cp16(&Bh[s][soff], Brow + k0);
            asm volatile("cp.async.commit_group;\n");
            asm volatile("cp.async.wait_group 1;\n");
        } else {
            asm volatile("cp.async.wait_group 0;\n");
        }
        __syncthreads();

        const int cb = t & 1;
        uint32_t aF[2][4], aL[2][4], bF[4][4];
#pragma unroll
        for (int mt = 0; mt < 2; mt++) {
            ldsm4(aF[mt], aAddrH[cb][mt]);
            ldsm4(aL[mt], aAddrL[cb][mt]);
        }
#pragma unroll
        for (int np = 0; np < 4; np++) ldsm4(bF[np], bAddr[cb][np]);

#pragma unroll
        for (int mt = 0; mt < 2; mt++)
#pragma unroll
            for (int np = 0; np < 4; np++) {
                mma16h(acc[mt][np * 2],     aF[mt], bF[np][0], bF[np][1]);
                mma16h(acc[mt][np * 2],     aL[mt], bF[np][0], bF[np][1]);
                mma16h(acc[mt][np * 2 + 1], aF[mt], bF[np][2], bF[np][3]);
                mma16h(acc[mt][np * 2 + 1], aL[mt], bF[np][2], bF[np][3]);
            }
        __syncthreads();
    }

#pragma unroll
    for (int mt = 0; mt < 2; mt++) {
        const int row0 = bm + wm + mt * 16 + gid;
#pragma unroll
        for (int nt = 0; nt < 8; nt++) {
            const int col = bn + wn + nt * 8 + tig * 2;
            *(float2*)&C[(size_t)row0 * N + col]       = make_float2(acc[mt][nt][0], acc[mt][nt][1]);
            *(float2*)&C[(size_t)(row0 + 8) * N + col] = make_float2(acc[mt][nt][2], acc[mt][nt][3]);
        }
    }
}

// ---------------------------------------------------------------------------
// RMSNorm + RoPE + gain for Q; emits split fp16 with 0.125*gain baked in.
// ---------------------------------------------------------------------------
__global__ void norm_rope_q_kernel(const float* __restrict__ qkv, const float* __restrict__ gain,
                                   __half* __restrict__ qh, __half* __restrict__ ql)
{
    const int row = blockIdx.x;
    const int h = blockIdx.y * blockDim.y + threadIdx.y;
    const int s = row & (SS - 1);
    const int d = threadIdx.x;

    const float* p = qkv + (size_t)row * QKVD + h * 64;
    float t1 = p[d];
    float t2 = p[d + 32];

    float ss = t1 * t1 + t2 * t2;
#pragma unroll
    for (int o = 16; o; o >>= 1) ss += __shfl_xor_sync(0xffffffffu, ss, o);
    float r = rsqrtf(ss * (1.0f / 64.0f) + 1e-6f);
    t1 *= r; t2 *= r;

    float inv_freq = exp2f(-(float)d * (13.287712379549449f / 32.0f));
    float th = (float)s * inv_freq;
    float c, sn;
    sincosf(th, &sn, &c);

    float g = gain[h] * 0.125f;
    float o1 = ( t1 * c + t2 * sn) * g;
    float o2 = (-t1 * sn + t2 * c) * g;

    size_t base = (size_t)row * DIMM + h * 64;
    __half h1 = __float2half_rn(o1);
    __half h2 = __float2half_rn(o2);
    qh[base + d]      = h1;  ql[base + d]      = __float2half_rn(o1 - __half2float(h1));
    qh[base + d + 32] = h2;  ql[base + d + 32] = __float2half_rn(o2 - __half2float(h2));
}

// ---------------------------------------------------------------------------
// RMSNorm + RoPE for K; emits split fp16.
// ---------------------------------------------------------------------------
__global__ void norm_rope_k_kernel(const float* __restrict__ qkv,
                                   __half* __restrict__ kh, __half* __restrict__ kl)
{
    const int row = blockIdx.x;
    const int h = blockIdx.y * blockDim.y + threadIdx.y;
    const int s = row & (SS - 1);
    const int d = threadIdx.x;

    const float* p = qkv + (size_t)row * QKVD + 1024 + h * 64;
    float t1 = p[d];
    float t2 = p[d + 32];

    float ss = t1 * t1 + t2 * t2;
#pragma unroll
    for (int o = 16; o; o >>= 1) ss += __shfl_xor_sync(0xffffffffu, ss, o);
    float r = rsqrtf(ss * (1.0f / 64.0f) + 1e-6f);
    t1 *= r; t2 *= r;

    float inv_freq = exp2f(-(float)d * (13.287712379549449f / 32.0f));
    float th = (float)s * inv_freq;
    float c, sn;
    sincosf(th, &sn, &c);

    float o1 =  t1 * c + t2 * sn;
    float o2 = -t1 * sn + t2 * c;

    size_t base = (size_t)row * KVD + h * 64;
    __half h1 = __float2half_rn(o1);
    __half h2 = __float2half_rn(o2);
    kh[base + d]      = h1;  kl[base + d]      = __float2half_rn(o1 - __half2float(h1));
    kh[base + d + 32] = h2;  kl[base + d + 32] = __float2half_rn(o2 - __half2float(h2));
}

// ---------------------------------------------------------------------------
// Causal GQA flash attention — split-fp16, 64-key tiles, V hi-only PV.
// Writes split-fp16 output (feeds out-projection GEMM directly).
// ---------------------------------------------------------------------------
#define KHST 72

__global__ void __launch_bounds__(128)
attn_tc_kernel(const __half* __restrict__ gqh, const __half* __restrict__ gql,
               const __half* __restrict__ gkh, const __half* __restrict__ gkl,
               const __half* __restrict__ gvh,
               __half* __restrict__ gyh, __half* __restrict__ gyl)
{
    __shared__ __half kh[64 * KHST], kl[64 * KHST], vh[64 * KHST];  // 27648 B

    const int tid = threadIdx.x, lane = tid & 31, wid = tid >> 5;
    const int gid = lane >> 2, tig = lane & 3;
    const int qb = blockIdx.x, h = blockIdx.y, b = blockIdx.z;
    const int kvh = h >> 2;
    const int wm = wid * 16;

    uint32_t qh_[4][4], ql_[4][4];
    {
        const size_t r0 = (size_t)(b * SS + qb * 64 + wm + gid    ) * DIMM + h * 64 + 2 * tig;
        const size_t r1 = (size_t)(b * SS + qb * 64 + wm + gid + 8) * DIMM + h * 64 + 2 * tig;
#pragma unroll
        for (int kc = 0; kc < 4; kc++) {
            qh_[kc][0] = *(const uint32_t*)(gqh + r0 + kc * 16);
            qh_[kc][1] = *(const uint32_t*)(gqh + r1 + kc * 16);
            qh_[kc][2] = *(const uint32_t*)(gqh + r0 + kc * 16 + 8);
            qh_[kc][3] = *(const uint32_t*)(gqh + r1 + kc * 16 + 8);
            ql_[kc][0] = *(const uint32_t*)(gql + r0 + kc * 16);
            ql_[kc][1] = *(const uint32_t*)(gql + r1 + kc * 16);
            ql_[kc][2] = *(const uint32_t*)(gql + r0 + kc * 16 + 8);
            ql_[kc][3] = *(const uint32_t*)(gql + r1 + kc * 16 + 8);
        }
    }

    const uint32_t vrow = (lane & 7) + 8 * ((lane >> 3) & 1);
    const uint32_t vcolB = (lane >> 4) * 16;
    const uint32_t vh_base = (uint32_t)__cvta_generic_to_shared(vh) + vrow * (KHST * 2) + vcolB;

    float m0 = -INFINITY, m1 = -INFINITY, l0 = 0.f, l1 = 0.f;
    float acc[8][4];
#pragma unroll
    for (int nd = 0; nd < 8; nd++)
#pragma unroll
        for (int c = 0; c < 4; c++) acc[nd][c] = 0.f;

    const int ntiles = qb + 1;
    for (int kt = 0; kt < ntiles; kt++) {
        if (kt) __syncthreads();
        const size_t tb = ((size_t)(b * SS + kt * 64)) * KVD + kvh * 64;
        for (int i = tid; i < 512; i += 128) {
            int j = i >> 3, c = (i & 7) * 8;
            size_t go = tb + (size_t)j * KVD + c;
            int so = j * KHST + c;
            *(uint4*)&kh[so] = *(const uint4*)(gkh + go);
            *(uint4*)&kl[so] = *(const uint4*)(gkl + go);
            *(uint4*)&vh[so] = *(const uint4*)(gvh + go);
        }
        __syncthreads();

        float sc[8][4];
#pragma unroll
        for (int nt = 0; nt < 8; nt++)
#pragma unroll
            for (int c = 0; c < 4; c++) sc[nt][c] = 0.f;

#pragma unroll
        for (int kc = 0; kc < 4; kc++) {
#pragma unroll
            for (int nt = 0; nt < 8; nt++) {
                const __half* krh = &kh[(nt * 8 + gid) * KHST + kc * 16 + 2 * tig];
                const __half* krl = &kl[(nt * 8 + gid) * KHST + kc * 16 + 2 * tig];
                uint32_t bh0 = *(const uint32_t*)krh;
                uint32_t bh1 = *(const uint32_t*)(krh + 8);
                uint32_t bl0 = *(const uint32_t*)krl;
                uint32_t bl1 = *(const uint32_t*)(krl + 8);
                mma16h(sc[nt], qh_[kc], bh0, bh1);
                mma16h(sc[nt], ql_[kc], bh0, bh1);
                mma16h(sc[nt], qh_[kc], bl0, bl1);
            }
        }

        if (kt == qb) {
#pragma unroll
            for (int nt = 0; nt < 8; nt++) {
                int c0 = nt * 8 + 2 * tig;
                if (c0     > wm + gid)     sc[nt][0] = -INFINITY;
                if (c0 + 1 > wm + gid)     sc[nt][1] = -INFINITY;
                if (c0     > wm + gid + 8) sc[nt][2] = -INFINITY;
                if (c0 + 1 > wm + gid + 8) sc[nt][3] = -INFINITY;
            }
        }

        float mt0 = m0, mt1 = m1;
#pragma unroll
        for (int nt = 0; nt < 8; nt++) {
            mt0 = fmaxf(mt0, fmaxf(sc[nt][0], sc[nt][1]));
            mt1 = fmaxf(mt1, fmaxf(sc[nt][2], sc[nt][3]));
        }
        mt0 = fmaxf(mt0, __shfl_xor_sync(0xffffffffu, mt0, 1));
        mt0 = fmaxf(mt0, __shfl_xor_sync(0xffffffffu, mt0, 2));
        mt1 = fmaxf(mt1, __shfl_xor_sync(0xffffffffu, mt1, 1));
        mt1 = fmaxf(mt1, __shfl_xor_sync(0xffffffffu, mt1, 2));

        float corr0 = __expf(m0 - mt0);
        float corr1 = __expf(m1 - mt1);
        m0 = mt0; m1 = mt1;
        l0 *= corr0; l1 *= corr1;
#pragma unroll
        for (int nd = 0; nd < 8; nd++) {
            acc[nd][0] *= corr0; acc[nd][1] *= corr0;
            acc[nd][2] *= corr1; acc[nd][3] *= corr1;
        }

#pragma unroll
        for (int nt = 0; nt < 8; nt++) {
            sc[nt][0] = __expf(sc[nt][0] - mt0);
            sc[nt][1] = __expf(sc[nt][1] - mt0);
            sc[nt][2] = __expf(sc[nt][2] - mt1);
            sc[nt][3] = __expf(sc[nt][3] - mt1);
            l0 += sc[nt][0] + sc[nt][1];
            l1 += sc[nt][2] + sc[nt][3];
        }

#pragma unroll
        for (int kc = 0; kc < 4; kc++) {
            uint32_t pfh[4], pfl[4];
            pfh[0] = pack2h(sc[2 * kc][0],     sc[2 * kc][1]);
            pfl[0] = pack2h_lo(sc[2 * kc][0],  sc[2 * kc][1],     pfh[0]);
            pfh[1] = pack2h(sc[2 * kc][2],     sc[2 * kc][3]);
            pfl[1] = pack2h_lo(sc[2 * kc][2],  sc[2 * kc][3],     pfh[1]);
            pfh[2] = pack2h(sc[2 * kc + 1][0], sc[2 * kc + 1][1]);
            pfl[2] = pack2h_lo(sc[2 * kc + 1][0], sc[2 * kc + 1][1], pfh[2]);
            pfh[3] = pack2h(sc[2 * kc + 1][2], sc[2 * kc + 1][3]);
            pfl[3] = pack2h_lo(sc[2 * kc + 1][2], sc[2 * kc + 1][3], pfh[3]);
#pragma unroll
            for (int ndp = 0; ndp < 4; ndp++) {
                uint32_t r0, r1, r2, r3;
                ldsm4t(r0, r1, r2, r3, vh_base + (uint32_t)(kc * 16 * (KHST * 2) + ndp * 32));
                mma16h(acc[ndp * 2],     pfh, r0, r1);
                mma16h(acc[ndp * 2],     pfl, r0, r1);
                mma16h(acc[ndp * 2 + 1], pfh, r2, r3);
                mma16h(acc[ndp * 2 + 1], pfl, r2, r3);
            }
        }
    }

    l0 += __shfl_xor_sync(0xffffffffu, l0, 1);
    l0 += __shfl_xor_sync(0xffffffffu, l0, 2);
    l1 += __shfl_xor_sync(0xffffffffu, l1, 1);
    l1 += __shfl_xor_sync(0xffffffffu, l1, 2);
    const float inv0 = 1.f / l0;
    const float inv1 = 1.f / l1;

    // split-fp16 output
    const size_t o0 = (size_t)(b * SS + qb * 64 + wm + gid    ) * DIMM + h * 64 + 2 * tig;
    const size_t o1 = (size_t)(b * SS + qb * 64 + wm + gid + 8) * DIMM + h * 64 + 2 * tig;
#pragma unroll
    for (int nd = 0; nd < 8; nd++) {
        float a0 = acc[nd][0] * inv0, a1 = acc[nd][1] * inv0;
        float a2 = acc[nd][2] * inv1, a3 = acc[nd][3] * inv1;
        uint32_t h0 = pack2h(a0, a1);
        uint32_t h1 = pack2h(a2, a3);
        *(uint32_t*)(gyh + o0 + nd * 8) = h0;
        *(uint32_t*)(gyl + o0 + nd * 8) = pack2h_lo(a0, a1, h0);
        *(uint32_t*)(gyh + o1 + nd * 8) = h1;
        *(uint32_t*)(gyl + o1 + nd * 8) = pack2h_lo(a2, a3, h1);
    }
}

// ---------------------------------------------------------------------------
extern "C" void kernel_launch(void* const* d_in, const int* in_sizes, int n_in,
                              void* d_out, int out_size)
{
    const float* x  = (const float*)d_in[0];
    const float* Wq = (const float*)d_in[1];
    const float* Wk = (const float*)d_in[2];
    const float* Wv = (const float*)d_in[3];
    const float* Wo = (const float*)d_in[4];
    const float* qg = (const float*)d_in[5];
    float* out = (float*)d_out;

    float* qkv;
    __half *xh, *xl, *wqkvh, *woh, *yh, *yl, *qhp, *qlp, *khp, *klp, *vhp;
    cudaGetSymbolAddress((void**)&qkv,   g_qkv);
    cudaGetSymbolAddress((void**)&xh,    g_xh);
    cudaGetSymbolAddress((void**)&xl,    g_xl);
    cudaGetSymbolAddress((void**)&wqkvh, g_wqkvh);
    cudaGetSymbolAddress((void**)&woh,   g_woh);
    cudaGetSymbolAddress((void**)&yh,    g_yh);
    cudaGetSymbolAddress((void**)&yl,    g_yl);
    cudaGetSymbolAddress((void**)&qhp,   g_qh);
    cudaGetSymbolAddress((void**)&qlp,   g_ql);
    cudaGetSymbolAddress((void**)&khp,   g_kh);
    cudaGetSymbolAddress((void**)&klp,   g_kl);
    cudaGetSymbolAddress((void**)&vhp,   g_vh);

    // operand preparation
    split_x_kernel<<<(MROWS * DIMM / 2 + 255) / 256, 256>>>(x, xh, xl, MROWS * DIMM / 2);
    conv_w_kernel<<<(DIMM * DIMM / 2 + 255) / 256, 256>>>(Wq, wqkvh, DIMM * DIMM / 2);
    conv_w_kernel<<<(KVD  * DIMM / 2 + 255) / 256, 256>>>(Wk, wqkvh + (size_t)DIMM * DIMM, KVD * DIMM / 2);
    conv_w_kernel<<<(KVD  * DIMM / 2 + 255) / 256, 256>>>(Wv, wqkvh + (size_t)(DIMM + KVD) * DIMM, KVD * DIMM / 2);
    conv_w_kernel<<<(DIMM * DIMM / 2 + 255) / 256, 256>>>(Wo, woh, DIMM * DIMM / 2);

    // fused QKV projection (N = 1536)
    gemm_fp16s_kernel<<<dim3(QKVD / 128, MROWS / 128), 256>>>(xh, xl, wqkvh, qkv, MROWS, QKVD, DIMM);

    // norm/rope -> split fp16; V -> fp16 hi
    norm_rope_q_kernel<<<dim3(MROWS, HH / 4),   dim3(32, 4)>>>(qkv, qg, qhp, qlp);
    norm_rope_k_kernel<<<dim3(MROWS, KVHH / 4), dim3(32, 4)>>>(qkv, khp, klp);
    conv_vh_kernel<<<(MROWS * KVD / 2 + 255) / 256, 256>>>(qkv, vhp, MROWS * KVD / 2);

    // attention (writes split-fp16 y)
    attn_tc_kernel<<<dim3(SS / 64, HH, BB), 128>>>(qhp, qlp, khp, klp, vhp, yh, yl);

    // output projection
    gemm_fp16s_kernel<<<dim3(DIMM / 128, MROWS / 128), 256>>>(yh, yl, woh, out, MROWS, DIMM, DIMM);
}

// round 10
// speedup vs baseline: 4.8641x; 1.0042x over previous
#include <cuda_runtime.h>
#include <cuda_fp16.h>
#include <math.h>
#include <stdint.h>

#define BB   4
#define SS   2048
#define DIMM 1024
#define HH   16
#define KVHH 4
#define HDD  64
#define KVD  256
#define QKVD 1536
#define MROWS (BB*SS)   // 8192

// Scratch (device globals — no allocations allowed)
__device__ float  g_qkv  [(size_t)MROWS * QKVD];  // 48 MB fused q|k|v (fp32)
__device__ __half g_xh   [(size_t)MROWS * DIMM];  // 16 MB
__device__ __half g_xl   [(size_t)MROWS * DIMM];
__device__ __half g_wqkvh[(size_t)QKVD * DIMM];   //  3 MB
__device__ __half g_woh  [(size_t)DIMM * DIMM];   //  2 MB
__device__ __half g_yh   [(size_t)MROWS * DIMM];  // 16 MB
__device__ __half g_yl   [(size_t)MROWS * DIMM];
__device__ __half g_qh   [(size_t)MROWS * DIMM];  // 16 MB
__device__ __half g_ql   [(size_t)MROWS * DIMM];
__device__ __half g_kh   [(size_t)MROWS * KVD];   //  4 MB
__device__ __half g_kl   [(size_t)MROWS * KVD];
__device__ __half g_vh   [(size_t)MROWS * KVD];

__device__ __forceinline__ void mma16h(float* c, const uint32_t* a, uint32_t b0, uint32_t b1) {
    asm volatile(
        "mma.sync.aligned.m16n8k16.row.col.f32.f16.f16.f32 "
        "{%0,%1,%2,%3}, {%4,%5,%6,%7}, {%8,%9}, {%0,%1,%2,%3};\n"
        : "+f"(c[0]), "+f"(c[1]), "+f"(c[2]), "+f"(c[3])
        : "r"(a[0]), "r"(a[1]), "r"(a[2]), "r"(a[3]), "r"(b0), "r"(b1));
}

__device__ __forceinline__ void ldsm4(uint32_t* r, uint32_t addr) {
    asm volatile("ldmatrix.sync.aligned.m8n8.x4.shared.b16 {%0,%1,%2,%3}, [%4];"
                 : "=r"(r[0]), "=r"(r[1]), "=r"(r[2]), "=r"(r[3]) : "r"(addr));
}

__device__ __forceinline__ void ldsm4t(uint32_t& r0, uint32_t& r1, uint32_t& r2, uint32_t& r3,
                                       uint32_t addr) {
    asm volatile("ldmatrix.sync.aligned.m8n8.x4.trans.shared.b16 {%0,%1,%2,%3}, [%4];"
                 : "=r"(r0), "=r"(r1), "=r"(r2), "=r"(r3) : "r"(addr));
}

__device__ __forceinline__ uint32_t pack2h(float x, float y) {
    __half2 t = __floats2half2_rn(x, y);
    return *reinterpret_cast<uint32_t*>(&t);
}
__device__ __forceinline__ uint32_t pack2h_lo(float x, float y, uint32_t hi) {
    __half2 h = *reinterpret_cast<__half2*>(&hi);
    __half2 t = __floats2half2_rn(x - __low2float(h), y - __high2float(h));
    return *reinterpret_cast<uint32_t*>(&t);
}

__device__ __forceinline__ void cp16(void* smem, const void* g) {
    uint32_t s = (uint32_t)__cvta_generic_to_shared(smem);
    asm volatile("cp.async.cg.shared.global [%0], [%1], 16;\n" :: "r"(s), "l"(g));
}

// ---------------------------------------------------------------------------
__global__ void split_x_kernel(const float* __restrict__ in,
                               __half* __restrict__ xh, __half* __restrict__ xl, int n2)
{
    int i = blockIdx.x * blockDim.x + threadIdx.x;
    if (i < n2) {
        float2 f = ((const float2*)in)[i];
        uint32_t hi = pack2h(f.x, f.y);
        ((uint32_t*)xh)[i] = hi;
        ((uint32_t*)xl)[i] = pack2h_lo(f.x, f.y, hi);
    }
}

__global__ void conv_w_kernel(const float* __restrict__ in, __half* __restrict__ out, int n2)
{
    int i = blockIdx.x * blockDim.x + threadIdx.x;
    if (i < n2) {
        float2 f = ((const float2*)in)[i];
        ((uint32_t*)out)[i] = pack2h(f.x, f.y);
    }
}

__global__ void conv_vh_kernel(const float* __restrict__ qkv, __half* __restrict__ vh, int n2)
{
    int i = blockIdx.x * blockDim.x + threadIdx.x;
    if (i < n2) {
        int row = i >> 7, col = i & 127;
        float2 f = ((const float2*)qkv)[(size_t)row * (QKVD / 2) + 640 + col];
        ((uint32_t*)vh)[i] = pack2h(f.x, f.y);
    }
}

// ---------------------------------------------------------------------------
// Split-FP16 GEMM: C[M,N] = (Ah+Al)[M,K] @ Bh[N,K]^T  (unchanged from R8)
// ---------------------------------------------------------------------------
#define GST 24

__global__ void __launch_bounds__(256)
gemm_fp16s_kernel(const __half* __restrict__ Ahg, const __half* __restrict__ Alg,
                  const __half* __restrict__ Bhg, float* __restrict__ C,
                  int M, int N, int K)
{
    __shared__ __half Ah[2][128 * GST], Al[2][128 * GST], Bh[2][128 * GST];

    const int tid  = threadIdx.x;
    const int lane = tid & 31;
    const int wid  = tid >> 5;
    const int wm   = (wid & 3) * 32;
    const int wn   = (wid >> 2) * 64;
    const int gid  = lane >> 2;
    const int tig  = lane & 3;
    const int bm   = blockIdx.y * 128;
    const int bn   = blockIdx.x * 128;

    const int lrow = tid >> 1;
    const int lch  = (tid & 1) * 8;
    const __half* Arow = Ahg + (size_t)(bm + lrow) * K + lch;
    const __half* Lrow = Alg + (size_t)(bm + lrow) * K + lch;
    const __half* Brow = Bhg + (size_t)(bn + lrow) * K + lch;
    const int soff = lrow * GST + lch;

    const int tl = lane >> 3, lr = lane & 7;
    const int a_row = lr + ((tl & 1) ? 8 : 0);
    const int a_kb  = (tl >= 2) ? 16 : 0;
    const int b_row = lr + ((tl >= 2) ? 8 : 0);
    const int b_kb  = (tl & 1) ? 16 : 0;

    uint32_t aAddrH[2][2], aAddrL[2][2], bAddr[2][4];
#pragma unroll
    for (int s = 0; s < 2; s++) {
#pragma unroll
        for (int mt = 0; mt < 2; mt++) {
            int r = wm + mt * 16 + a_row;
            aAddrH[s][mt] = (uint32_t)__cvta_generic_to_shared(&Ah[s][r * GST]) + a_kb;
            aAddrL[s][mt] = (uint32_t)__cvta_generic_to_shared(&Al[s][r * GST]) + a_kb;
        }
#pragma unroll
        for (int np = 0; np < 4; np++) {
            int r = wn + np * 16 + b_row;
            bAddr[s][np] = (uint32_t)__cvta_generic_to_shared(&Bh[s][r * GST]) + b_kb;
        }
    }

    float acc[2][8][4];
#pragma unroll
    for (int i = 0; i < 2; i++)
#pragma unroll
        for (int j = 0; j < 8; j++)
#pragma unroll
            for (int c = 0; c < 4; c++) acc[i][j][c] = 0.f;

    const int T = K / 16;

    cp16(&Ah[0][soff], Arow);
    cp16(&Al[0][soff], Lrow);
    cp16(&Bh[0][soff], Brow);
    asm volatile("cp.async.commit_group;\n");

    for (int t = 0; t < T; t++) {
        if (t + 1 < T) {
            const int s = (t + 1) & 1, k0 = (t + 1) * 16;
            cp16(&Ah[s][soff], Arow + k0);
            cp16(&Al[s][soff], Lrow + k0);
            cp16(&Bh[s][soff], Brow + k0);
            asm volatile("cp.async.commit_group;\n");
            asm volatile("cp.async.wait_group 1;\n");
        } else {
            asm volatile("cp.async.wait_group 0;\n");
        }
        __syncthreads();

        const int cb = t & 1;
        uint32_t aF[2][4], aL[2][4], bF[4][4];
#pragma unroll
        for (int mt = 0; mt < 2; mt++) {
            ldsm4(aF[mt], aAddrH[cb][mt]);
            ldsm4(aL[mt], aAddrL[cb][mt]);
        }
#pragma unroll
        for (int np = 0; np < 4; np++) ldsm4(bF[np], bAddr[cb][np]);

#pragma unroll
        for (int mt = 0; mt < 2; mt++)
#pragma unroll
            for (int np = 0; np < 4; np++) {
                mma16h(acc[mt][np * 2],     aF[mt], bF[np][0], bF[np][1]);
                mma16h(acc[mt][np * 2],     aL[mt], bF[np][0], bF[np][1]);
                mma16h(acc[mt][np * 2 + 1], aF[mt], bF[np][2], bF[np][3]);
                mma16h(acc[mt][np * 2 + 1], aL[mt], bF[np][2], bF[np][3]);
            }
        __syncthreads();
    }

#pragma unroll
    for (int mt = 0; mt < 2; mt++) {
        const int row0 = bm + wm + mt * 16 + gid;
#pragma unroll
        for (int nt = 0; nt < 8; nt++) {
            const int col = bn + wn + nt * 8 + tig * 2;
            *(float2*)&C[(size_t)row0 * N + col]       = make_float2(acc[mt][nt][0], acc[mt][nt][1]);
            *(float2*)&C[(size_t)(row0 + 8) * N + col] = make_float2(acc[mt][nt][2], acc[mt][nt][3]);
        }
    }
}

// ---------------------------------------------------------------------------
// RMSNorm + RoPE + gain for Q; emits split fp16 with 0.125*gain baked in.
// ---------------------------------------------------------------------------
__global__ void norm_rope_q_kernel(const float* __restrict__ qkv, const float* __restrict__ gain,
                                   __half* __restrict__ qh, __half* __restrict__ ql)
{
    const int row = blockIdx.x;
    const int h = blockIdx.y * blockDim.y + threadIdx.y;
    const int s = row & (SS - 1);
    const int d = threadIdx.x;

    const float* p = qkv + (size_t)row * QKVD + h * 64;
    float t1 = p[d];
    float t2 = p[d + 32];

    float ss = t1 * t1 + t2 * t2;
#pragma unroll
    for (int o = 16; o; o >>= 1) ss += __shfl_xor_sync(0xffffffffu, ss, o);
    float r = rsqrtf(ss * (1.0f / 64.0f) + 1e-6f);
    t1 *= r; t2 *= r;

    float inv_freq = exp2f(-(float)d * (13.287712379549449f / 32.0f));
    float th = (float)s * inv_freq;
    float c, sn;
    sincosf(th, &sn, &c);

    float g = gain[h] * 0.125f;
    float o1 = ( t1 * c + t2 * sn) * g;
    float o2 = (-t1 * sn + t2 * c) * g;

    size_t base = (size_t)row * DIMM + h * 64;
    __half h1 = __float2half_rn(o1);
    __half h2 = __float2half_rn(o2);
    qh[base + d]      = h1;  ql[base + d]      = __float2half_rn(o1 - __half2float(h1));
    qh[base + d + 32] = h2;  ql[base + d + 32] = __float2half_rn(o2 - __half2float(h2));
}

// ---------------------------------------------------------------------------
// RMSNorm + RoPE for K; emits split fp16.
// ---------------------------------------------------------------------------
__global__ void norm_rope_k_kernel(const float* __restrict__ qkv,
                                   __half* __restrict__ kh, __half* __restrict__ kl)
{
    const int row = blockIdx.x;
    const int h = blockIdx.y * blockDim.y + threadIdx.y;
    const int s = row & (SS - 1);
    const int d = threadIdx.x;

    const float* p = qkv + (size_t)row * QKVD + 1024 + h * 64;
    float t1 = p[d];
    float t2 = p[d + 32];

    float ss = t1 * t1 + t2 * t2;
#pragma unroll
    for (int o = 16; o; o >>= 1) ss += __shfl_xor_sync(0xffffffffu, ss, o);
    float r = rsqrtf(ss * (1.0f / 64.0f) + 1e-6f);
    t1 *= r; t2 *= r;

    float inv_freq = exp2f(-(float)d * (13.287712379549449f / 32.0f));
    float th = (float)s * inv_freq;
    float c, sn;
    sincosf(th, &sn, &c);

    float o1 =  t1 * c + t2 * sn;
    float o2 = -t1 * sn + t2 * c;

    size_t base = (size_t)row * KVD + h * 64;
    __half h1 = __float2half_rn(o1);
    __half h2 = __float2half_rn(o2);
    kh[base + d]      = h1;  kl[base + d]      = __float2half_rn(o1 - __half2float(h1));
    kh[base + d + 32] = h2;  kl[base + d + 32] = __float2half_rn(o2 - __half2float(h2));
}

// ---------------------------------------------------------------------------
// Causal GQA flash attention — split-fp16, 128-query CTAs (8 warps),
// 3-stage cp.async pipeline over 32-key tiles, per-warp causal tile skip.
// ---------------------------------------------------------------------------
#define KHST 72
#define TROWS 32                   // keys per stage
#define TSZ (TROWS * KHST)         // halves per stage per array

__global__ void __launch_bounds__(256)
attn_tc_kernel(const __half* __restrict__ gqh, const __half* __restrict__ gql,
               const __half* __restrict__ gkh, const __half* __restrict__ gkl,
               const __half* __restrict__ gvh,
               __half* __restrict__ gyh, __half* __restrict__ gyl)
{
    __shared__ __half kh[3][TSZ], kl[3][TSZ], vh[3][TSZ];   // 41472 B

    const int tid = threadIdx.x, lane = tid & 31, wid = tid >> 5;
    const int gid = lane >> 2, tig = lane & 3;
    const int qb = (gridDim.x - 1) - blockIdx.x;   // heavy CTAs first
    const int h = blockIdx.y, b = blockIdx.z;
    const int kvh = h >> 2;
    const int wm = wid * 16;
    const int qrow = qb * 128 + wm;                // warp's first query (in-sequence)

    // Q fragments straight from pre-split global fp16 (scale+gain baked in)
    uint32_t qh_[4][4], ql_[4][4];
    {
        const size_t r0 = (size_t)(b * SS + qrow + gid    ) * DIMM + h * 64 + 2 * tig;
        const size_t r1 = (size_t)(b * SS + qrow + gid + 8) * DIMM + h * 64 + 2 * tig;
#pragma unroll
        for (int kc = 0; kc < 4; kc++) {
            qh_[kc][0] = *(const uint32_t*)(gqh + r0 + kc * 16);
            qh_[kc][1] = *(const uint32_t*)(gqh + r1 + kc * 16);
            qh_[kc][2] = *(const uint32_t*)(gqh + r0 + kc * 16 + 8);
            qh_[kc][3] = *(const uint32_t*)(gqh + r1 + kc * 16 + 8);
            ql_[kc][0] = *(const uint32_t*)(gql + r0 + kc * 16);
            ql_[kc][1] = *(const uint32_t*)(gql + r1 + kc * 16);
            ql_[kc][2] = *(const uint32_t*)(gql + r0 + kc * 16 + 8);
            ql_[kc][3] = *(const uint32_t*)(gql + r1 + kc * 16 + 8);
        }
    }

    // loader mapping: one 16B chunk per array per thread per stage
    const int lrow = tid >> 3;               // 0..31
    const int lch  = (tid & 7) * 8;          // half offset in row
    const int soff = lrow * KHST + lch;

    // ldmatrix.trans V lane bases per stage
    const uint32_t vrow = (lane & 7) + 8 * ((lane >> 3) & 1);
    const uint32_t vcolB = (lane >> 4) * 16;
    uint32_t vbase[3];
#pragma unroll
    for (int s = 0; s < 3; s++)
        vbase[s] = (uint32_t)__cvta_generic_to_shared(&vh[s][0]) + vrow * (KHST * 2) + vcolB;

    float m0 = -INFINITY, m1 = -INFINITY, l0 = 0.f, l1 = 0.f;
    float acc[8][4];
#pragma unroll
    for (int nd = 0; nd < 8; nd++)
#pragma unroll
        for (int c = 0; c < 4; c++) acc[nd][c] = 0.f;

    const int ntiles = 4 * qb + 4;
    const size_t kvbase = (size_t)(b * SS) * KVD + kvh * 64 + (size_t)lrow * KVD + lch;

    // prologue: stage 0
    {
        size_t go = kvbase;   // kt = 0
        cp16(&kh[0][soff], gkh + go);
        cp16(&kl[0][soff], gkl + go);
        cp16(&vh[0][soff], gvh + go);
        asm volatile("cp.async.commit_group;\n");
    }

    for (int kt = 0; kt < ntiles; kt++) {
        if (kt + 1 < ntiles) {
            const int s = (kt + 1) % 3;
            size_t go = kvbase + (size_t)(kt + 1) * TROWS * KVD;
            cp16(&kh[s][soff], gkh + go);
            cp16(&kl[s][soff], gkl + go);
            cp16(&vh[s][soff], gvh + go);
            asm volatile("cp.async.commit_group;\n");
            asm volatile("cp.async.wait_group 1;\n");
        } else {
            asm volatile("cp.async.wait_group 0;\n");
        }
        __syncthreads();

        // per-warp causal skip: no keys in this tile can be <= any of our queries
        if (kt * 32 <= qrow - qb * 128 + qb * 128 + wm + 15 - wm + qrow - qrow) {} // (no-op guard removed below)
        const int keybase = kt * 32;
        if (keybase > qrow + 15) continue;   // fully masked for this warp

        const int cb = kt % 3;

        // ---- scores: S[16q x 32k], split-fp16 x3 ----
        float sc[4][4];
#pragma unroll
        for (int nt = 0; nt < 4; nt++)
#pragma unroll
            for (int c = 0; c < 4; c++) sc[nt][c] = 0.f;

#pragma unroll
        for (int kc = 0; kc < 4; kc++) {
#pragma unroll
            for (int nt = 0; nt < 4; nt++) {
                const __half* krh = &kh[cb][(nt * 8 + gid) * KHST + kc * 16 + 2 * tig];
                const __half* krl = &kl[cb][(nt * 8 + gid) * KHST + kc * 16 + 2 * tig];
                uint32_t bh0 = *(const uint32_t*)krh;
                uint32_t bh1 = *(const uint32_t*)(krh + 8);
                uint32_t bl0 = *(const uint32_t*)krl;
                uint32_t bl1 = *(const uint32_t*)(krl + 8);
                mma16h(sc[nt], qh_[kc], bh0, bh1);
                mma16h(sc[nt], ql_[kc], bh0, bh1);
                mma16h(sc[nt], qh_[kc], bl0, bl1);
            }
        }

        // causal mask (tiles overlapping this warp's diagonal)
        if (keybase + 31 > qrow) {
            const int off = keybase - qrow;   // key index relative to warp query base
#pragma unroll
            for (int nt = 0; nt < 4; nt++) {
                int c0 = off + nt * 8 + 2 * tig;
                if (c0     > gid)     sc[nt][0] = -INFINITY;
                if (c0 + 1 > gid)     sc[nt][1] = -INFINITY;
                if (c0     > gid + 8) sc[nt][2] = -INFINITY;
                if (c0 + 1 > gid + 8) sc[nt][3] = -INFINITY;
            }
        }

        float mt0 = m0, mt1 = m1;
#pragma unroll
        for (int nt = 0; nt < 4; nt++) {
            mt0 = fmaxf(mt0, fmaxf(sc[nt][0], sc[nt][1]));
            mt1 = fmaxf(mt1, fmaxf(sc[nt][2], sc[nt][3]));
        }
        mt0 = fmaxf(mt0, __shfl_xor_sync(0xffffffffu, mt0, 1));
        mt0 = fmaxf(mt0, __shfl_xor_sync(0xffffffffu, mt0, 2));
        mt1 = fmaxf(mt1, __shfl_xor_sync(0xffffffffu, mt1, 1));
        mt1 = fmaxf(mt1, __shfl_xor_sync(0xffffffffu, mt1, 2));

        float corr0 = __expf(m0 - mt0);
        float corr1 = __expf(m1 - mt1);
        m0 = mt0; m1 = mt1;
        l0 *= corr0; l1 *= corr1;
#pragma unroll
        for (int nd = 0; nd < 8; nd++) {
            acc[nd][0] *= corr0; acc[nd][1] *= corr0;
            acc[nd][2] *= corr1; acc[nd][3] *= corr1;
        }

#pragma unroll
        for (int nt = 0; nt < 4; nt++) {
            sc[nt][0] = __expf(sc[nt][0] - mt0);
            sc[nt][1] = __expf(sc[nt][1] - mt0);
            sc[nt][2] = __expf(sc[nt][2] - mt1);
            sc[nt][3] = __expf(sc[nt][3] - mt1);
            l0 += sc[nt][0] + sc[nt][1];
            l1 += sc[nt][2] + sc[nt][3];
        }

        // ---- PV: Y += P·V_hi, P split x2; V b-frags via ldmatrix.trans ----
#pragma unroll
        for (int kc = 0; kc < 2; kc++) {
            uint32_t pfh[4], pfl[4];
            pfh[0] = pack2h(sc[2 * kc][0],     sc[2 * kc][1]);
            pfl[0] = pack2h_lo(sc[2 * kc][0],  sc[2 * kc][1],     pfh[0]);
            pfh[1] = pack2h(sc[2 * kc][2],     sc[2 * kc][3]);
            pfl[1] = pack2h_lo(sc[2 * kc][2],  sc[2 * kc][3],     pfh[1]);
            pfh[2] = pack2h(sc[2 * kc + 1][0], sc[2 * kc + 1][1]);
            pfl[2] = pack2h_lo(sc[2 * kc + 1][0], sc[2 * kc + 1][1], pfh[2]);
            pfh[3] = pack2h(sc[2 * kc + 1][2], sc[2 * kc + 1][3]);
            pfl[3] = pack2h_lo(sc[2 * kc + 1][2], sc[2 * kc + 1][3], pfh[3]);
#pragma unroll
            for (int ndp = 0; ndp < 4; ndp++) {
                uint32_t r0, r1, r2, r3;
                ldsm4t(r0, r1, r2, r3, vbase[cb] + (uint32_t)(kc * 16 * (KHST * 2) + ndp * 32));
                mma16h(acc[ndp * 2],     pfh, r0, r1);
                mma16h(acc[ndp * 2],     pfl, r0, r1);
                mma16h(acc[ndp * 2 + 1], pfh, r2, r3);
                mma16h(acc[ndp * 2 + 1], pfl, r2, r3);
            }
        }
    }

    l0 += __shfl_xor_sync(0xffffffffu, l0, 1);
    l0 += __shfl_xor_sync(0xffffffffu, l0, 2);
    l1 += __shfl_xor_sync(0xffffffffu, l1, 1);
    l1 += __shfl_xor_sync(0xffffffffu, l1, 2);
    const float inv0 = 1.f / l0;
    const float inv1 = 1.f / l1;

    const size_t o0 = (size_t)(b * SS + qrow + gid    ) * DIMM + h * 64 + 2 * tig;
    const size_t o1 = (size_t)(b * SS + qrow + gid + 8) * DIMM + h * 64 + 2 * tig;
#pragma unroll
    for (int nd = 0; nd < 8; nd++) {
        float a0 = acc[nd][0] * inv0, a1 = acc[nd][1] * inv0;
        float a2 = acc[nd][2] * inv1, a3 = acc[nd][3] * inv1;
        uint32_t h0 = pack2h(a0, a1);
        uint32_t h1 = pack2h(a2, a3);
        *(uint32_t*)(gyh + o0 + nd * 8) = h0;
        *(uint32_t*)(gyl + o0 + nd * 8) = pack2h_lo(a0, a1, h0);
        *(uint32_t*)(gyh + o1 + nd * 8) = h1;
        *(uint32_t*)(gyl + o1 + nd * 8) = pack2h_lo(a2, a3, h1);
    }
}

// ---------------------------------------------------------------------------
extern "C" void kernel_launch(void* const* d_in, const int* in_sizes, int n_in,
                              void* d_out, int out_size)
{
    const float* x  = (const float*)d_in[0];
    const float* Wq = (const float*)d_in[1];
    const float* Wk = (const float*)d_in[2];
    const float* Wv = (const float*)d_in[3];
    const float* Wo = (const float*)d_in[4];
    const float* qg = (const float*)d_in[5];
    float* out = (float*)d_out;

    float* qkv;
    __half *xh, *xl, *wqkvh, *woh, *yh, *yl, *qhp, *qlp, *khp, *klp, *vhp;
    cudaGetSymbolAddress((void**)&qkv,   g_qkv);
    cudaGetSymbolAddress((void**)&xh,    g_xh);
    cudaGetSymbolAddress((void**)&xl,    g_xl);
    cudaGetSymbolAddress((void**)&wqkvh, g_wqkvh);
    cudaGetSymbolAddress((void**)&woh,   g_woh);
    cudaGetSymbolAddress((void**)&yh,    g_yh);
    cudaGetSymbolAddress((void**)&yl,    g_yl);
    cudaGetSymbolAddress((void**)&qhp,   g_qh);
    cudaGetSymbolAddress((void**)&qlp,   g_ql);
    cudaGetSymbolAddress((void**)&khp,   g_kh);
    cudaGetSymbolAddress((void**)&klp,   g_kl);
    cudaGetSymbolAddress((void**)&vhp,   g_vh);

    // operand preparation
    split_x_kernel<<<(MROWS * DIMM / 2 + 255) / 256, 256>>>(x, xh, xl, MROWS * DIMM / 2);
    conv_w_kernel<<<(DIMM * DIMM / 2 + 255) / 256, 256>>>(Wq, wqkvh, DIMM * DIMM / 2);
    conv_w_kernel<<<(KVD  * DIMM / 2 + 255) / 256, 256>>>(Wk, wqkvh + (size_t)DIMM * DIMM, KVD * DIMM / 2);
    conv_w_kernel<<<(KVD  * DIMM / 2 + 255) / 256, 256>>>(Wv, wqkvh + (size_t)(DIMM + KVD) * DIMM, KVD * DIMM / 2);
    conv_w_kernel<<<(DIMM * DIMM / 2 + 255) / 256, 256>>>(Wo, woh, DIMM * DIMM / 2);

    // fused QKV projection (N = 1536)
    gemm_fp16s_kernel<<<dim3(QKVD / 128, MROWS / 128), 256>>>(xh, xl, wqkvh, qkv, MROWS, QKVD, DIMM);

    // norm/rope -> split fp16; V -> fp16 hi
    norm_rope_q_kernel<<<dim3(MROWS, HH / 4),   dim3(32, 4)>>>(qkv, qg, qhp, qlp);
    norm_rope_k_kernel<<<dim3(MROWS, KVHH / 4), dim3(32, 4)>>>(qkv, khp, klp);
    conv_vh_kernel<<<(MROWS * KVD / 2 + 255) / 256, 256>>>(qkv, vhp, MROWS * KVD / 2);

    // attention: 128-query CTAs, pipelined
    attn_tc_kernel<<<dim3(SS / 128, HH, BB), 256>>>(qhp, qlp, khp, klp, vhp, yh, yl);

    // output projection
    gemm_fp16s_kernel<<<dim3(DIMM / 128, MROWS / 128), 256>>>(yh, yl, woh, out, MROWS, DIMM, DIMM);
}

// round 13
// speedup vs baseline: 5.7870x; 1.1897x over previous
#include <cuda_runtime.h>
#include <cuda_fp16.h>
#include <math.h>
#include <stdint.h>

#define BB   4
#define SS   2048
#define DIMM 1024
#define HH   16
#define KVHH 4
#define HDD  64
#define KVD  256
#define QKVD 1536
#define MROWS (BB*SS)   // 8192

// Scratch (device globals — no allocations allowed)
__device__ float  g_qkv  [(size_t)MROWS * QKVD];  // 48 MB fused q|k|v (fp32)
__device__ __half g_xh   [(size_t)MROWS * DIMM];  // 16 MB
__device__ __half g_wqkvh[(size_t)QKVD * DIMM];   //  3 MB
__device__ __half g_woh  [(size_t)DIMM * DIMM];   //  2 MB
__device__ __half g_yh   [(size_t)MROWS * DIMM];  // 16 MB
__device__ __half g_qh   [(size_t)MROWS * DIMM];  // 16 MB
__device__ __half g_ql   [(size_t)MROWS * DIMM];
__device__ __half g_kh   [(size_t)MROWS * KVD];   //  4 MB
__device__ __half g_kl   [(size_t)MROWS * KVD];
__device__ __half g_vh   [(size_t)MROWS * KVD];

__device__ __forceinline__ void mma16h(float* c, const uint32_t* a, uint32_t b0, uint32_t b1) {
    asm volatile(
        "mma.sync.aligned.m16n8k16.row.col.f32.f16.f16.f32 "
        "{%0,%1,%2,%3}, {%4,%5,%6,%7}, {%8,%9}, {%0,%1,%2,%3};\n"
        : "+f"(c[0]), "+f"(c[1]), "+f"(c[2]), "+f"(c[3])
        : "r"(a[0]), "r"(a[1]), "r"(a[2]), "r"(a[3]), "r"(b0), "r"(b1));
}

__device__ __forceinline__ void ldsm4(uint32_t* r, uint32_t addr) {
    asm volatile("ldmatrix.sync.aligned.m8n8.x4.shared.b16 {%0,%1,%2,%3}, [%4];"
                 : "=r"(r[0]), "=r"(r[1]), "=r"(r[2]), "=r"(r[3]) : "r"(addr));
}

__device__ __forceinline__ void ldsm4t(uint32_t& r0, uint32_t& r1, uint32_t& r2, uint32_t& r3,
                                       uint32_t addr) {
    asm volatile("ldmatrix.sync.aligned.m8n8.x4.trans.shared.b16 {%0,%1,%2,%3}, [%4];"
                 : "=r"(r0), "=r"(r1), "=r"(r2), "=r"(r3) : "r"(addr));
}

__device__ __forceinline__ uint32_t pack2h(float x, float y) {
    __half2 t = __floats2half2_rn(x, y);
    return *reinterpret_cast<uint32_t*>(&t);
}
__device__ __forceinline__ uint32_t pack2h_lo(float x, float y, uint32_t hi) {
    __half2 h = *reinterpret_cast<__half2*>(&hi);
    __half2 t = __floats2half2_rn(x - __low2float(h), y - __high2float(h));
    return *reinterpret_cast<uint32_t*>(&t);
}

__device__ __forceinline__ void cp16(void* smem, const void* g) {
    uint32_t s = (uint32_t)__cvta_generic_to_shared(smem);
    asm volatile("cp.async.cg.shared.global [%0], [%1], 16;\n" :: "r"(s), "l"(g));
}

// ---------------------------------------------------------------------------
// fp32 -> fp16 (round-to-nearest), float2 granularity
__global__ void conv_h_kernel(const float* __restrict__ in, __half* __restrict__ out, int n2)
{
    int i = blockIdx.x * blockDim.x + threadIdx.x;
    if (i < n2) {
        float2 f = ((const float2*)in)[i];
        ((uint32_t*)out)[i] = pack2h(f.x, f.y);
    }
}

__global__ void conv_vh_kernel(const float* __restrict__ qkv, __half* __restrict__ vh, int n2)
{
    int i = blockIdx.x * blockDim.x + threadIdx.x;
    if (i < n2) {
        int row = i >> 7, col = i & 127;
        float2 f = ((const float2*)qkv)[(size_t)row * (QKVD / 2) + 640 + col];
        ((uint32_t*)vh)[i] = pack2h(f.x, f.y);
    }
}

// ---------------------------------------------------------------------------
// Plain FP16 GEMM: C[M,N] = Ah[M,K] @ Bh[N,K]^T,  fp32 accum/output.
// CTA 128x128, BK=16, 256 thr, 8 warps (4m x 2n), warp tile 32x64.
// Fragments via ldmatrix.x4; smem rows padded to 24 halves (48 B).
// ---------------------------------------------------------------------------
#define GST 24

__global__ void __launch_bounds__(256)
gemm_fp16_kernel(const __half* __restrict__ Ahg, const __half* __restrict__ Bhg,
                 float* __restrict__ C, int M, int N, int K)
{
    __shared__ __half Ah[2][128 * GST], Bh[2][128 * GST];   // 24576 B

    const int tid  = threadIdx.x;
    const int lane = tid & 31;
    const int wid  = tid >> 5;
    const int wm   = (wid & 3) * 32;
    const int wn   = (wid >> 2) * 64;
    const int gid  = lane >> 2;
    const int tig  = lane & 3;
    const int bm   = blockIdx.y * 128;
    const int bn   = blockIdx.x * 128;

    const int lrow = tid >> 1;
    const int lch  = (tid & 1) * 8;
    const __half* Arow = Ahg + (size_t)(bm + lrow) * K + lch;
    const __half* Brow = Bhg + (size_t)(bn + lrow) * K + lch;
    const int soff = lrow * GST + lch;

    const int tl = lane >> 3, lr = lane & 7;
    const int a_row = lr + ((tl & 1) ? 8 : 0);
    const int a_kb  = (tl >= 2) ? 16 : 0;
    const int b_row = lr + ((tl >= 2) ? 8 : 0);
    const int b_kb  = (tl & 1) ? 16 : 0;

    uint32_t aAddr[2][2], bAddr[2][4];
#pragma unroll
    for (int s = 0; s < 2; s++) {
#pragma unroll
        for (int mt = 0; mt < 2; mt++) {
            int r = wm + mt * 16 + a_row;
            aAddr[s][mt] = (uint32_t)__cvta_generic_to_shared(&Ah[s][r * GST]) + a_kb;
        }
#pragma unroll
        for (int np = 0; np < 4; np++) {
            int r = wn + np * 16 + b_row;
            bAddr[s][np] = (uint32_t)__cvta_generic_to_shared(&Bh[s][r * GST]) + b_kb;
        }
    }

    float acc[2][8][4];
#pragma unroll
    for (int i = 0; i < 2; i++)
#pragma unroll
        for (int j = 0; j < 8; j++)
#pragma unroll
            for (int c = 0; c < 4; c++) acc[i][j][c] = 0.f;

    const int T = K / 16;

    cp16(&Ah[0][soff], Arow);
    cp16(&Bh[0][soff], Brow);
    asm volatile("cp.async.commit_group;\n");

    for (int t = 0; t < T; t++) {
        if (t + 1 < T) {
            const int s = (t + 1) & 1, k0 = (t + 1) * 16;
            cp16(&Ah[s][soff], Arow + k0);
            cp16(&Bh[s][soff], Brow + k0);
            asm volatile("cp.async.commit_group;\n");
            asm volatile("cp.async.wait_group 1;\n");
        } else {
            asm volatile("cp.async.wait_group 0;\n");
        }
        __syncthreads();

        const int cb = t & 1;
        uint32_t aF[2][4], bF[4][4];
#pragma unroll
        for (int mt = 0; mt < 2; mt++) ldsm4(aF[mt], aAddr[cb][mt]);
#pragma unroll
        for (int np = 0; np < 4; np++) ldsm4(bF[np], bAddr[cb][np]);

#pragma unroll
        for (int mt = 0; mt < 2; mt++)
#pragma unroll
            for (int np = 0; np < 4; np++) {
                mma16h(acc[mt][np * 2],     aF[mt], bF[np][0], bF[np][1]);
                mma16h(acc[mt][np * 2 + 1], aF[mt], bF[np][2], bF[np][3]);
            }
        __syncthreads();
    }

#pragma unroll
    for (int mt = 0; mt < 2; mt++) {
        const int row0 = bm + wm + mt * 16 + gid;
#pragma unroll
        for (int nt = 0; nt < 8; nt++) {
            const int col = bn + wn + nt * 8 + tig * 2;
            *(float2*)&C[(size_t)row0 * N + col]       = make_float2(acc[mt][nt][0], acc[mt][nt][1]);
            *(float2*)&C[(size_t)(row0 + 8) * N + col] = make_float2(acc[mt][nt][2], acc[mt][nt][3]);
        }
    }
}

// ---------------------------------------------------------------------------
// RMSNorm + RoPE + gain for Q; emits split fp16 with 0.125*gain baked in.
// ---------------------------------------------------------------------------
__global__ void norm_rope_q_kernel(const float* __restrict__ qkv, const float* __restrict__ gain,
                                   __half* __restrict__ qh, __half* __restrict__ ql)
{
    const int row = blockIdx.x;
    const int h = blockIdx.y * blockDim.y + threadIdx.y;
    const int s = row & (SS - 1);
    const int d = threadIdx.x;

    const float* p = qkv + (size_t)row * QKVD + h * 64;
    float t1 = p[d];
    float t2 = p[d + 32];

    float ss = t1 * t1 + t2 * t2;
#pragma unroll
    for (int o = 16; o; o >>= 1) ss += __shfl_xor_sync(0xffffffffu, ss, o);
    float r = rsqrtf(ss * (1.0f / 64.0f) + 1e-6f);
    t1 *= r; t2 *= r;

    float inv_freq = exp2f(-(float)d * (13.287712379549449f / 32.0f));
    float th = (float)s * inv_freq;
    float c, sn;
    sincosf(th, &sn, &c);

    float g = gain[h] * 0.125f;
    float o1 = ( t1 * c + t2 * sn) * g;
    float o2 = (-t1 * sn + t2 * c) * g;

    size_t base = (size_t)row * DIMM + h * 64;
    __half h1 = __float2half_rn(o1);
    __half h2 = __float2half_rn(o2);
    qh[base + d]      = h1;  ql[base + d]      = __float2half_rn(o1 - __half2float(h1));
    qh[base + d + 32] = h2;  ql[base + d + 32] = __float2half_rn(o2 - __half2float(h2));
}

// ---------------------------------------------------------------------------
// RMSNorm + RoPE for K; emits split fp16.
// ---------------------------------------------------------------------------
__global__ void norm_rope_k_kernel(const float* __restrict__ qkv,
                                   __half* __restrict__ kh, __half* __restrict__ kl)
{
    const int row = blockIdx.x;
    const int h = blockIdx.y * blockDim.y + threadIdx.y;
    const int s = row & (SS - 1);
    const int d = threadIdx.x;

    const float* p = qkv + (size_t)row * QKVD + 1024 + h * 64;
    float t1 = p[d];
    float t2 = p[d + 32];

    float ss = t1 * t1 + t2 * t2;
#pragma unroll
    for (int o = 16; o; o >>= 1) ss += __shfl_xor_sync(0xffffffffu, ss, o);
    float r = rsqrtf(ss * (1.0f / 64.0f) + 1e-6f);
    t1 *= r; t2 *= r;

    float inv_freq = exp2f(-(float)d * (13.287712379549449f / 32.0f));
    float th = (float)s * inv_freq;
    float c, sn;
    sincosf(th, &sn, &c);

    float o1 =  t1 * c + t2 * sn;
    float o2 = -t1 * sn + t2 * c;

    size_t base = (size_t)row * KVD + h * 64;
    __half h1 = __float2half_rn(o1);
    __half h2 = __float2half_rn(o2);
    kh[base + d]      = h1;  kl[base + d]      = __float2half_rn(o1 - __half2float(h1));
    kh[base + d + 32] = h2;  kl[base + d + 32] = __float2half_rn(o2 - __half2float(h2));
}

// ---------------------------------------------------------------------------
// Causal GQA flash attention — split-fp16, 128-query CTAs, 3-stage cp.async,
// per-warp causal tile skip.  Output: fp16 hi only (feeds plain fp16 GEMM).
// ---------------------------------------------------------------------------
#define KHST 72
#define TROWS 32
#define TSZ (TROWS * KHST)

__global__ void __launch_bounds__(256)
attn_tc_kernel(const __half* __restrict__ gqh, const __half* __restrict__ gql,
               const __half* __restrict__ gkh, const __half* __restrict__ gkl,
               const __half* __restrict__ gvh, __half* __restrict__ gyh)
{
    __shared__ __half kh[3][TSZ], kl[3][TSZ], vh[3][TSZ];

    const int tid = threadIdx.x, lane = tid & 31, wid = tid >> 5;
    const int gid = lane >> 2, tig = lane & 3;
    const int qb = (gridDim.x - 1) - blockIdx.x;
    const int h = blockIdx.y, b = blockIdx.z;
    const int kvh = h >> 2;
    const int wm = wid * 16;
    const int qrow = qb * 128 + wm;

    uint32_t qh_[4][4], ql_[4][4];
    {
        const size_t r0 = (size_t)(b * SS + qrow + gid    ) * DIMM + h * 64 + 2 * tig;
        const size_t r1 = (size_t)(b * SS + qrow + gid + 8) * DIMM + h * 64 + 2 * tig;
#pragma unroll
        for (int kc = 0; kc < 4; kc++) {
            qh_[kc][0] = *(const uint32_t*)(gqh + r0 + kc * 16);
            qh_[kc][1] = *(const uint32_t*)(gqh + r1 + kc * 16);
            qh_[kc][2] = *(const uint32_t*)(gqh + r0 + kc * 16 + 8);
            qh_[kc][3] = *(const uint32_t*)(gqh + r1 + kc * 16 + 8);
            ql_[kc][0] = *(const uint32_t*)(gql + r0 + kc * 16);
            ql_[kc][1] = *(const uint32_t*)(gql + r1 + kc * 16);
            ql_[kc][2] = *(const uint32_t*)(gql + r0 + kc * 16 + 8);
            ql_[kc][3] = *(const uint32_t*)(gql + r1 + kc * 16 + 8);
        }
    }

    const int lrow = tid >> 3;
    const int lch  = (tid & 7) * 8;
    const int soff = lrow * KHST + lch;

    const uint32_t vrow = (lane & 7) + 8 * ((lane >> 3) & 1);
    const uint32_t vcolB = (lane >> 4) * 16;
    uint32_t vbase[3];
#pragma unroll
    for (int s = 0; s < 3; s++)
        vbase[s] = (uint32_t)__cvta_generic_to_shared(&vh[s][0]) + vrow * (KHST * 2) + vcolB;

    float m0 = -INFINITY, m1 = -INFINITY, l0 = 0.f, l1 = 0.f;
    float acc[8][4];
#pragma unroll
    for (int nd = 0; nd < 8; nd++)
#pragma unroll
        for (int c = 0; c < 4; c++) acc[nd][c] = 0.f;

    const int ntiles = 4 * qb + 4;
    const size_t kvbase = (size_t)(b * SS) * KVD + kvh * 64 + (size_t)lrow * KVD + lch;

    {
        size_t go = kvbase;
        cp16(&kh[0][soff], gkh + go);
        cp16(&kl[0][soff], gkl + go);
        cp16(&vh[0][soff], gvh + go);
        asm volatile("cp.async.commit_group;\n");
    }

    for (int kt = 0; kt < ntiles; kt++) {
        if (kt + 1 < ntiles) {
            const int s = (kt + 1) % 3;
            size_t go = kvbase + (size_t)(kt + 1) * TROWS * KVD;
            cp16(&kh[s][soff], gkh + go);
            cp16(&kl[s][soff], gkl + go);
            cp16(&vh[s][soff], gvh + go);
            asm volatile("cp.async.commit_group;\n");
            asm volatile("cp.async.wait_group 1;\n");
        } else {
            asm volatile("cp.async.wait_group 0;\n");
        }
        __syncthreads();

        const int keybase = kt * 32;
        if (keybase > qrow + 15) continue;

        const int cb = kt % 3;

        float sc[4][4];
#pragma unroll
        for (int nt = 0; nt < 4; nt++)
#pragma unroll
            for (int c = 0; c < 4; c++) sc[nt][c] = 0.f;

#pragma unroll
        for (int kc = 0; kc < 4; kc++) {
#pragma unroll
            for (int nt = 0; nt < 4; nt++) {
                const __half* krh = &kh[cb][(nt * 8 + gid) * KHST + kc * 16 + 2 * tig];
                const __half* krl = &kl[cb][(nt * 8 + gid) * KHST + kc * 16 + 2 * tig];
                uint32_t bh0 = *(const uint32_t*)krh;
                uint32_t bh1 = *(const uint32_t*)(krh + 8);
                uint32_t bl0 = *(const uint32_t*)krl;
                uint32_t bl1 = *(const uint32_t*)(krl + 8);
                mma16h(sc[nt], qh_[kc], bh0, bh1);
                mma16h(sc[nt], ql_[kc], bh0, bh1);
                mma16h(sc[nt], qh_[kc], bl0, bl1);
            }
        }

        if (keybase + 31 > qrow) {
            const int off = keybase - qrow;
#pragma unroll
            for (int nt = 0; nt < 4; nt++) {
                int c0 = off + nt * 8 + 2 * tig;
                if (c0     > gid)     sc[nt][0] = -INFINITY;
                if (c0 + 1 > gid)     sc[nt][1] = -INFINITY;
                if (c0     > gid + 8) sc[nt][2] = -INFINITY;
                if (c0 + 1 > gid + 8) sc[nt][3] = -INFINITY;
            }
        }

        float mt0 = m0, mt1 = m1;
#pragma unroll
        for (int nt = 0; nt < 4; nt++) {
            mt0 = fmaxf(mt0, fmaxf(sc[nt][0], sc[nt][1]));
            mt1 = fmaxf(mt1, fmaxf(sc[nt][2], sc[nt][3]));
        }
        mt0 = fmaxf(mt0, __shfl_xor_sync(0xffffffffu, mt0, 1));
        mt0 = fmaxf(mt0, __shfl_xor_sync(0xffffffffu, mt0, 2));
        mt1 = fmaxf(mt1, __shfl_xor_sync(0xffffffffu, mt1, 1));
        mt1 = fmaxf(mt1, __shfl_xor_sync(0xffffffffu, mt1, 2));

        float corr0 = __expf(m0 - mt0);
        float corr1 = __expf(m1 - mt1);
        m0 = mt0; m1 = mt1;
        l0 *= corr0; l1 *= corr1;
#pragma unroll
        for (int nd = 0; nd < 8; nd++) {
            acc[nd][0] *= corr0; acc[nd][1] *= corr0;
            acc[nd][2] *= corr1; acc[nd][3] *= corr1;
        }

#pragma unroll
        for (int nt = 0; nt < 4; nt++) {
            sc[nt][0] = __expf(sc[nt][0] - mt0);
            sc[nt][1] = __expf(sc[nt][1] - mt0);
            sc[nt][2] = __expf(sc[nt][2] - mt1);
            sc[nt][3] = __expf(sc[nt][3] - mt1);
            l0 += sc[nt][0] + sc[nt][1];
            l1 += sc[nt][2] + sc[nt][3];
        }

#pragma unroll
        for (int kc = 0; kc < 2; kc++) {
            uint32_t pfh[4], pfl[4];
            pfh[0] = pack2h(sc[2 * kc][0],     sc[2 * kc][1]);
            pfl[0] = pack2h_lo(sc[2 * kc][0],  sc[2 * kc][1],     pfh[0]);
            pfh[1] = pack2h(sc[2 * kc][2],     sc[2 * kc][3]);
            pfl[1] = pack2h_lo(sc[2 * kc][2],  sc[2 * kc][3],     pfh[1]);
            pfh[2] = pack2h(sc[2 * kc + 1][0], sc[2 * kc + 1][1]);
            pfl[2] = pack2h_lo(sc[2 * kc + 1][0], sc[2 * kc + 1][1], pfh[2]);
            pfh[3] = pack2h(sc[2 * kc + 1][2], sc[2 * kc + 1][3]);
            pfl[3] = pack2h_lo(sc[2 * kc + 1][2], sc[2 * kc + 1][3], pfh[3]);
#pragma unroll
            for (int ndp = 0; ndp < 4; ndp++) {
                uint32_t r0, r1, r2, r3;
                ldsm4t(r0, r1, r2, r3, vbase[cb] + (uint32_t)(kc * 16 * (KHST * 2) + ndp * 32));
                mma16h(acc[ndp * 2],     pfh, r0, r1);
                mma16h(acc[ndp * 2],     pfl, r0, r1);
                mma16h(acc[ndp * 2 + 1], pfh, r2, r3);
                mma16h(acc[ndp * 2 + 1], pfl, r2, r3);
            }
        }
    }

    l0 += __shfl_xor_sync(0xffffffffu, l0, 1);
    l0 += __shfl_xor_sync(0xffffffffu, l0, 2);
    l1 += __shfl_xor_sync(0xffffffffu, l1, 1);
    l1 += __shfl_xor_sync(0xffffffffu, l1, 2);
    const float inv0 = 1.f / l0;
    const float inv1 = 1.f / l1;

    const size_t o0 = (size_t)(b * SS + qrow + gid    ) * DIMM + h * 64 + 2 * tig;
    const size_t o1 = (size_t)(b * SS + qrow + gid + 8) * DIMM + h * 64 + 2 * tig;
#pragma unroll
    for (int nd = 0; nd < 8; nd++) {
        *(uint32_t*)(gyh + o0 + nd * 8) = pack2h(acc[nd][0] * inv0, acc[nd][1] * inv0);
        *(uint32_t*)(gyh + o1 + nd * 8) = pack2h(acc[nd][2] * inv1, acc[nd][3] * inv1);
    }
}

// ---------------------------------------------------------------------------
extern "C" void kernel_launch(void* const* d_in, const int* in_sizes, int n_in,
                              void* d_out, int out_size)
{
    const float* x  = (const float*)d_in[0];
    const float* Wq = (const float*)d_in[1];
    const float* Wk = (const float*)d_in[2];
    const float* Wv = (const float*)d_in[3];
    const float* Wo = (const float*)d_in[4];
    const float* qg = (const float*)d_in[5];
    float* out = (float*)d_out;

    float* qkv;
    __half *xh, *wqkvh, *woh, *yh, *qhp, *qlp, *khp, *klp, *vhp;
    cudaGetSymbolAddress((void**)&qkv,   g_qkv);
    cudaGetSymbolAddress((void**)&xh,    g_xh);
    cudaGetSymbolAddress((void**)&wqkvh, g_wqkvh);
    cudaGetSymbolAddress((void**)&woh,   g_woh);
    cudaGetSymbolAddress((void**)&yh,    g_yh);
    cudaGetSymbolAddress((void**)&qhp,   g_qh);
    cudaGetSymbolAddress((void**)&qlp,   g_ql);
    cudaGetSymbolAddress((void**)&khp,   g_kh);
    cudaGetSymbolAddress((void**)&klp,   g_kl);
    cudaGetSymbolAddress((void**)&vhp,   g_vh);

    // operand preparation (all fp16 hi only)
    conv_h_kernel<<<(MROWS * DIMM / 2 + 255) / 256, 256>>>(x, xh, MROWS * DIMM / 2);
    conv_h_kernel<<<(DIMM * DIMM / 2 + 255) / 256, 256>>>(Wq, wqkvh, DIMM * DIMM / 2);
    conv_h_kernel<<<(KVD  * DIMM / 2 + 255) / 256, 256>>>(Wk, wqkvh + (size_t)DIMM * DIMM, KVD * DIMM / 2);
    conv_h_kernel<<<(KVD  * DIMM / 2 + 255) / 256, 256>>>(Wv, wqkvh + (size_t)(DIMM + KVD) * DIMM, KVD * DIMM / 2);
    conv_h_kernel<<<(DIMM * DIMM / 2 + 255) / 256, 256>>>(Wo, woh, DIMM * DIMM / 2);

    // fused QKV projection (N = 1536), plain fp16
    gemm_fp16_kernel<<<dim3(QKVD / 128, MROWS / 128), 256>>>(xh, wqkvh, qkv, MROWS, QKVD, DIMM);

    // norm/rope -> split fp16; V -> fp16 hi
    norm_rope_q_kernel<<<dim3(MROWS, HH / 4),   dim3(32, 4)>>>(qkv, qg, qhp, qlp);
    norm_rope_k_kernel<<<dim3(MROWS, KVHH / 4), dim3(32, 4)>>>(qkv, khp, klp);
    conv_vh_kernel<<<(MROWS * KVD / 2 + 255) / 256, 256>>>(qkv, vhp, MROWS * KVD / 2);

    // attention (split-fp16 QK/PV; fp16-hi output)
    attn_tc_kernel<<<dim3(SS / 128, HH, BB), 256>>>(qhp, qlp, khp, klp, vhp, yh);

    // output projection, plain fp16
    gemm_fp16_kernel<<<dim3(DIMM / 128, MROWS / 128), 256>>>(yh, woh, out, MROWS, DIMM, DIMM);
}

// round 14
// speedup vs baseline: 6.6746x; 1.1534x over previous
#include <cuda_runtime.h>
#include <cuda_fp16.h>
#include <math.h>
#include <stdint.h>

#define BB   4
#define SS   2048
#define DIMM 1024
#define HH   16
#define KVHH 4
#define HDD  64
#define KVD  256
#define QKVD 1536
#define MROWS (BB*SS)   // 8192

// Scratch (device globals — no allocations allowed)
__device__ float  g_qkv  [(size_t)MROWS * QKVD];  // 48 MB fused q|k|v (fp32)
__device__ __half g_xh   [(size_t)MROWS * DIMM];  // 16 MB
__device__ __half g_wqkvh[(size_t)QKVD * DIMM];   //  3 MB
__device__ __half g_woh  [(size_t)DIMM * DIMM];   //  2 MB
__device__ __half g_yh   [(size_t)MROWS * DIMM];  // 16 MB
__device__ __half g_qh   [(size_t)MROWS * DIMM];  // 16 MB
__device__ __half g_kh   [(size_t)MROWS * KVD];   //  4 MB
__device__ __half g_kl   [(size_t)MROWS * KVD];
__device__ __half g_vh   [(size_t)MROWS * KVD];

__device__ __forceinline__ void mma16h(float* c, const uint32_t* a, uint32_t b0, uint32_t b1) {
    asm volatile(
        "mma.sync.aligned.m16n8k16.row.col.f32.f16.f16.f32 "
        "{%0,%1,%2,%3}, {%4,%5,%6,%7}, {%8,%9}, {%0,%1,%2,%3};\n"
        : "+f"(c[0]), "+f"(c[1]), "+f"(c[2]), "+f"(c[3])
        : "r"(a[0]), "r"(a[1]), "r"(a[2]), "r"(a[3]), "r"(b0), "r"(b1));
}

__device__ __forceinline__ void ldsm4(uint32_t* r, uint32_t addr) {
    asm volatile("ldmatrix.sync.aligned.m8n8.x4.shared.b16 {%0,%1,%2,%3}, [%4];"
                 : "=r"(r[0]), "=r"(r[1]), "=r"(r[2]), "=r"(r[3]) : "r"(addr));
}

__device__ __forceinline__ void ldsm4t(uint32_t& r0, uint32_t& r1, uint32_t& r2, uint32_t& r3,
                                       uint32_t addr) {
    asm volatile("ldmatrix.sync.aligned.m8n8.x4.trans.shared.b16 {%0,%1,%2,%3}, [%4];"
                 : "=r"(r0), "=r"(r1), "=r"(r2), "=r"(r3) : "r"(addr));
}

__device__ __forceinline__ uint32_t pack2h(float x, float y) {
    __half2 t = __floats2half2_rn(x, y);
    return *reinterpret_cast<uint32_t*>(&t);
}
__device__ __forceinline__ uint32_t pack2h_lo(float x, float y, uint32_t hi) {
    __half2 h = *reinterpret_cast<__half2*>(&hi);
    __half2 t = __floats2half2_rn(x - __low2float(h), y - __high2float(h));
    return *reinterpret_cast<uint32_t*>(&t);
}

__device__ __forceinline__ void cp16(void* smem, const void* g) {
    uint32_t s = (uint32_t)__cvta_generic_to_shared(smem);
    asm volatile("cp.async.cg.shared.global [%0], [%1], 16;\n" :: "r"(s), "l"(g));
}

// ---------------------------------------------------------------------------
// fp32 -> fp16 (round-to-nearest), float2 granularity
__global__ void conv_h_kernel(const float* __restrict__ in, __half* __restrict__ out, int n2)
{
    int i = blockIdx.x * blockDim.x + threadIdx.x;
    if (i < n2) {
        float2 f = ((const float2*)in)[i];
        ((uint32_t*)out)[i] = pack2h(f.x, f.y);
    }
}

__global__ void conv_vh_kernel(const float* __restrict__ qkv, __half* __restrict__ vh, int n2)
{
    int i = blockIdx.x * blockDim.x + threadIdx.x;
    if (i < n2) {
        int row = i >> 7, col = i & 127;
        float2 f = ((const float2*)qkv)[(size_t)row * (QKVD / 2) + 640 + col];
        ((uint32_t*)vh)[i] = pack2h(f.x, f.y);
    }
}

// ---------------------------------------------------------------------------
// Plain FP16 GEMM: C[M,N] = Ah[M,K] @ Bh[N,K]^T,  fp32 accum/output.
// CTA 128x128, BK=16, 256 thr, 8 warps (4m x 2n), warp tile 32x64.
// ---------------------------------------------------------------------------
#define GST 24

__global__ void __launch_bounds__(256)
gemm_fp16_kernel(const __half* __restrict__ Ahg, const __half* __restrict__ Bhg,
                 float* __restrict__ C, int M, int N, int K)
{
    __shared__ __half Ah[2][128 * GST], Bh[2][128 * GST];   // 24576 B

    const int tid  = threadIdx.x;
    const int lane = tid & 31;
    const int wid  = tid >> 5;
    const int wm   = (wid & 3) * 32;
    const int wn   = (wid >> 2) * 64;
    const int gid  = lane >> 2;
    const int tig  = lane & 3;
    const int bm   = blockIdx.y * 128;
    const int bn   = blockIdx.x * 128;

    const int lrow = tid >> 1;
    const int lch  = (tid & 1) * 8;
    const __half* Arow = Ahg + (size_t)(bm + lrow) * K + lch;
    const __half* Brow = Bhg + (size_t)(bn + lrow) * K + lch;
    const int soff = lrow * GST + lch;

    const int tl = lane >> 3, lr = lane & 7;
    const int a_row = lr + ((tl & 1) ? 8 : 0);
    const int a_kb  = (tl >= 2) ? 16 : 0;
    const int b_row = lr + ((tl >= 2) ? 8 : 0);
    const int b_kb  = (tl & 1) ? 16 : 0;

    uint32_t aAddr[2][2], bAddr[2][4];
#pragma unroll
    for (int s = 0; s < 2; s++) {
#pragma unroll
        for (int mt = 0; mt < 2; mt++) {
            int r = wm + mt * 16 + a_row;
            aAddr[s][mt] = (uint32_t)__cvta_generic_to_shared(&Ah[s][r * GST]) + a_kb;
        }
#pragma unroll
        for (int np = 0; np < 4; np++) {
            int r = wn + np * 16 + b_row;
            bAddr[s][np] = (uint32_t)__cvta_generic_to_shared(&Bh[s][r * GST]) + b_kb;
        }
    }

    float acc[2][8][4];
#pragma unroll
    for (int i = 0; i < 2; i++)
#pragma unroll
        for (int j = 0; j < 8; j++)
#pragma unroll
            for (int c = 0; c < 4; c++) acc[i][j][c] = 0.f;

    const int T = K / 16;

    cp16(&Ah[0][soff], Arow);
    cp16(&Bh[0][soff], Brow);
    asm volatile("cp.async.commit_group;\n");

    for (int t = 0; t < T; t++) {
        if (t + 1 < T) {
            const int s = (t + 1) & 1, k0 = (t + 1) * 16;
            cp16(&Ah[s][soff], Arow + k0);
            cp16(&Bh[s][soff], Brow + k0);
            asm volatile("cp.async.commit_group;\n");
            asm volatile("cp.async.wait_group 1;\n");
        } else {
            asm volatile("cp.async.wait_group 0;\n");
        }
        __syncthreads();

        const int cb = t & 1;
        uint32_t aF[2][4], bF[4][4];
#pragma unroll
        for (int mt = 0; mt < 2; mt++) ldsm4(aF[mt], aAddr[cb][mt]);
#pragma unroll
        for (int np = 0; np < 4; np++) ldsm4(bF[np], bAddr[cb][np]);

#pragma unroll
        for (int mt = 0; mt < 2; mt++)
#pragma unroll
            for (int np = 0; np < 4; np++) {
                mma16h(acc[mt][np * 2],     aF[mt], bF[np][0], bF[np][1]);
                mma16h(acc[mt][np * 2 + 1], aF[mt], bF[np][2], bF[np][3]);
            }
        __syncthreads();
    }

#pragma unroll
    for (int mt = 0; mt < 2; mt++) {
        const int row0 = bm + wm + mt * 16 + gid;
#pragma unroll
        for (int nt = 0; nt < 8; nt++) {
            const int col = bn + wn + nt * 8 + tig * 2;
            *(float2*)&C[(size_t)row0 * N + col]       = make_float2(acc[mt][nt][0], acc[mt][nt][1]);
            *(float2*)&C[(size_t)(row0 + 8) * N + col] = make_float2(acc[mt][nt][2], acc[mt][nt][3]);
        }
    }
}

// ---------------------------------------------------------------------------
// RMSNorm + RoPE + gain for Q; emits fp16 (hi only) with 0.125*gain baked in.
// ---------------------------------------------------------------------------
__global__ void norm_rope_q_kernel(const float* __restrict__ qkv, const float* __restrict__ gain,
                                   __half* __restrict__ qh)
{
    const int row = blockIdx.x;
    const int h = blockIdx.y * blockDim.y + threadIdx.y;
    const int s = row & (SS - 1);
    const int d = threadIdx.x;

    const float* p = qkv + (size_t)row * QKVD + h * 64;
    float t1 = p[d];
    float t2 = p[d + 32];

    float ss = t1 * t1 + t2 * t2;
#pragma unroll
    for (int o = 16; o; o >>= 1) ss += __shfl_xor_sync(0xffffffffu, ss, o);
    float r = rsqrtf(ss * (1.0f / 64.0f) + 1e-6f);
    t1 *= r; t2 *= r;

    float inv_freq = exp2f(-(float)d * (13.287712379549449f / 32.0f));
    float th = (float)s * inv_freq;
    float c, sn;
    sincosf(th, &sn, &c);

    float g = gain[h] * 0.125f;
    float o1 = ( t1 * c + t2 * sn) * g;
    float o2 = (-t1 * sn + t2 * c) * g;

    size_t base = (size_t)row * DIMM + h * 64;
    qh[base + d]      = __float2half_rn(o1);
    qh[base + d + 32] = __float2half_rn(o2);
}

// ---------------------------------------------------------------------------
// RMSNorm + RoPE for K; emits split fp16 (hi/lo — K stays near-exact).
// ---------------------------------------------------------------------------
__global__ void norm_rope_k_kernel(const float* __restrict__ qkv,
                                   __half* __restrict__ kh, __half* __restrict__ kl)
{
    const int row = blockIdx.x;
    const int h = blockIdx.y * blockDim.y + threadIdx.y;
    const int s = row & (SS - 1);
    const int d = threadIdx.x;

    const float* p = qkv + (size_t)row * QKVD + 1024 + h * 64;
    float t1 = p[d];
    float t2 = p[d + 32];

    float ss = t1 * t1 + t2 * t2;
#pragma unroll
    for (int o = 16; o; o >>= 1) ss += __shfl_xor_sync(0xffffffffu, ss, o);
    float r = rsqrtf(ss * (1.0f / 64.0f) + 1e-6f);
    t1 *= r; t2 *= r;

    float inv_freq = exp2f(-(float)d * (13.287712379549449f / 32.0f));
    float th = (float)s * inv_freq;
    float c, sn;
    sincosf(th, &sn, &c);

    float o1 =  t1 * c + t2 * sn;
    float o2 = -t1 * sn + t2 * c;

    size_t base = (size_t)row * KVD + h * 64;
    __half h1 = __float2half_rn(o1);
    __half h2 = __float2half_rn(o2);
    kh[base + d]      = h1;  kl[base + d]      = __float2half_rn(o1 - __half2float(h1));
    kh[base + d + 32] = h2;  kl[base + d + 32] = __float2half_rn(o2 - __half2float(h2));
}

// ---------------------------------------------------------------------------
// Causal GQA flash attention — 128-query CTAs, 3-stage cp.async,
// per-warp causal tile skip.
// QK^T = qh·kh + qh·kl (K compensated, Q plain fp16); PV = ph·vh.
// Output: fp16 hi only.
// ---------------------------------------------------------------------------
#define KHST 72
#define TROWS 32
#define TSZ (TROWS * KHST)

__global__ void __launch_bounds__(256)
attn_tc_kernel(const __half* __restrict__ gqh,
               const __half* __restrict__ gkh, const __half* __restrict__ gkl,
               const __half* __restrict__ gvh, __half* __restrict__ gyh)
{
    __shared__ __half kh[3][TSZ], kl[3][TSZ], vh[3][TSZ];

    const int tid = threadIdx.x, lane = tid & 31, wid = tid >> 5;
    const int gid = lane >> 2, tig = lane & 3;
    const int qb = (gridDim.x - 1) - blockIdx.x;
    const int h = blockIdx.y, b = blockIdx.z;
    const int kvh = h >> 2;
    const int wm = wid * 16;
    const int qrow = qb * 128 + wm;

    uint32_t qh_[4][4];
    {
        const size_t r0 = (size_t)(b * SS + qrow + gid    ) * DIMM + h * 64 + 2 * tig;
        const size_t r1 = (size_t)(b * SS + qrow + gid + 8) * DIMM + h * 64 + 2 * tig;
#pragma unroll
        for (int kc = 0; kc < 4; kc++) {
            qh_[kc][0] = *(const uint32_t*)(gqh + r0 + kc * 16);
            qh_[kc][1] = *(const uint32_t*)(gqh + r1 + kc * 16);
            qh_[kc][2] = *(const uint32_t*)(gqh + r0 + kc * 16 + 8);
            qh_[kc][3] = *(const uint32_t*)(gqh + r1 + kc * 16 + 8);
        }
    }

    const int lrow = tid >> 3;
    const int lch  = (tid & 7) * 8;
    const int soff = lrow * KHST + lch;

    const uint32_t vrow = (lane & 7) + 8 * ((lane >> 3) & 1);
    const uint32_t vcolB = (lane >> 4) * 16;
    uint32_t vbase[3];
#pragma unroll
    for (int s = 0; s < 3; s++)
        vbase[s] = (uint32_t)__cvta_generic_to_shared(&vh[s][0]) + vrow * (KHST * 2) + vcolB;

    float m0 = -INFINITY, m1 = -INFINITY, l0 = 0.f, l1 = 0.f;
    float acc[8][4];
#pragma unroll
    for (int nd = 0; nd < 8; nd++)
#pragma unroll
        for (int c = 0; c < 4; c++) acc[nd][c] = 0.f;

    const int ntiles = 4 * qb + 4;
    const size_t kvbase = (size_t)(b * SS) * KVD + kvh * 64 + (size_t)lrow * KVD + lch;

    {
        size_t go = kvbase;
        cp16(&kh[0][soff], gkh + go);
        cp16(&kl[0][soff], gkl + go);
        cp16(&vh[0][soff], gvh + go);
        asm volatile("cp.async.commit_group;\n");
    }

    for (int kt = 0; kt < ntiles; kt++) {
        if (kt + 1 < ntiles) {
            const int s = (kt + 1) % 3;
            size_t go = kvbase + (size_t)(kt + 1) * TROWS * KVD;
            cp16(&kh[s][soff], gkh + go);
            cp16(&kl[s][soff], gkl + go);
            cp16(&vh[s][soff], gvh + go);
            asm volatile("cp.async.commit_group;\n");
            asm volatile("cp.async.wait_group 1;\n");
        } else {
            asm volatile("cp.async.wait_group 0;\n");
        }
        __syncthreads();

        const int keybase = kt * 32;
        if (keybase > qrow + 15) continue;

        const int cb = kt % 3;

        float sc[4][4];
#pragma unroll
        for (int nt = 0; nt < 4; nt++)
#pragma unroll
            for (int c = 0; c < 4; c++) sc[nt][c] = 0.f;

#pragma unroll
        for (int kc = 0; kc < 4; kc++) {
#pragma unroll
            for (int nt = 0; nt < 4; nt++) {
                const __half* krh = &kh[cb][(nt * 8 + gid) * KHST + kc * 16 + 2 * tig];
                const __half* krl = &kl[cb][(nt * 8 + gid) * KHST + kc * 16 + 2 * tig];
                uint32_t bh0 = *(const uint32_t*)krh;
                uint32_t bh1 = *(const uint32_t*)(krh + 8);
                uint32_t bl0 = *(const uint32_t*)krl;
                uint32_t bl1 = *(const uint32_t*)(krl + 8);
                mma16h(sc[nt], qh_[kc], bh0, bh1);
                mma16h(sc[nt], qh_[kc], bl0, bl1);
            }
        }

        if (keybase + 31 > qrow) {
            const int off = keybase - qrow;
#pragma unroll
            for (int nt = 0; nt < 4; nt++) {
                int c0 = off + nt * 8 + 2 * tig;
                if (c0     > gid)     sc[nt][0] = -INFINITY;
                if (c0 + 1 > gid)     sc[nt][1] = -INFINITY;
                if (c0     > gid + 8) sc[nt][2] = -INFINITY;
                if (c0 + 1 > gid + 8) sc[nt][3] = -INFINITY;
            }
        }

        float mt0 = m0, mt1 = m1;
#pragma unroll
        for (int nt = 0; nt < 4; nt++) {
            mt0 = fmaxf(mt0, fmaxf(sc[nt][0], sc[nt][1]));
            mt1 = fmaxf(mt1, fmaxf(sc[nt][2], sc[nt][3]));
        }
        mt0 = fmaxf(mt0, __shfl_xor_sync(0xffffffffu, mt0, 1));
        mt0 = fmaxf(mt0, __shfl_xor_sync(0xffffffffu, mt0, 2));
        mt1 = fmaxf(mt1, __shfl_xor_sync(0xffffffffu, mt1, 1));
        mt1 = fmaxf(mt1, __shfl_xor_sync(0xffffffffu, mt1, 2));

        float corr0 = __expf(m0 - mt0);
        float corr1 = __expf(m1 - mt1);
        m0 = mt0; m1 = mt1;
        l0 *= corr0; l1 *= corr1;
#pragma unroll
        for (int nd = 0; nd < 8; nd++) {
            acc[nd][0] *= corr0; acc[nd][1] *= corr0;
            acc[nd][2] *= corr1; acc[nd][3] *= corr1;
        }

#pragma unroll
        for (int nt = 0; nt < 4; nt++) {
            sc[nt][0] = __expf(sc[nt][0] - mt0);
            sc[nt][1] = __expf(sc[nt][1] - mt0);
            sc[nt][2] = __expf(sc[nt][2] - mt1);
            sc[nt][3] = __expf(sc[nt][3] - mt1);
            l0 += sc[nt][0] + sc[nt][1];
            l1 += sc[nt][2] + sc[nt][3];
        }

        // ---- PV: Y += P_hi · V_hi ----
#pragma unroll
        for (int kc = 0; kc < 2; kc++) {
            uint32_t pfh[4];
            pfh[0] = pack2h(sc[2 * kc][0],     sc[2 * kc][1]);
            pfh[1] = pack2h(sc[2 * kc][2],     sc[2 * kc][3]);
            pfh[2] = pack2h(sc[2 * kc + 1][0], sc[2 * kc + 1][1]);
            pfh[3] = pack2h(sc[2 * kc + 1][2], sc[2 * kc + 1][3]);
#pragma unroll
            for (int ndp = 0; ndp < 4; ndp++) {
                uint32_t r0, r1, r2, r3;
                ldsm4t(r0, r1, r2, r3, vbase[cb] + (uint32_t)(kc * 16 * (KHST * 2) + ndp * 32));
                mma16h(acc[ndp * 2],     pfh, r0, r1);
                mma16h(acc[ndp * 2 + 1], pfh, r2, r3);
            }
        }
    }

    l0 += __shfl_xor_sync(0xffffffffu, l0, 1);
    l0 += __shfl_xor_sync(0xffffffffu, l0, 2);
    l1 += __shfl_xor_sync(0xffffffffu, l1, 1);
    l1 += __shfl_xor_sync(0xffffffffu, l1, 2);
    const float inv0 = 1.f / l0;
    const float inv1 = 1.f / l1;

    const size_t o0 = (size_t)(b * SS + qrow + gid    ) * DIMM + h * 64 + 2 * tig;
    const size_t o1 = (size_t)(b * SS + qrow + gid + 8) * DIMM + h * 64 + 2 * tig;
#pragma unroll
    for (int nd = 0; nd < 8; nd++) {
        *(uint32_t*)(gyh + o0 + nd * 8) = pack2h(acc[nd][0] * inv0, acc[nd][1] * inv0);
        *(uint32_t*)(gyh + o1 + nd * 8) = pack2h(acc[nd][2] * inv1, acc[nd][3] * inv1);
    }
}

// ---------------------------------------------------------------------------
extern "C" void kernel_launch(void* const* d_in, const int* in_sizes, int n_in,
                              void* d_out, int out_size)
{
    const float* x  = (const float*)d_in[0];
    const float* Wq = (const float*)d_in[1];
    const float* Wk = (const float*)d_in[2];
    const float* Wv = (const float*)d_in[3];
    const float* Wo = (const float*)d_in[4];
    const float* qg = (const float*)d_in[5];
    float* out = (float*)d_out;

    float* qkv;
    __half *xh, *wqkvh, *woh, *yh, *qhp, *khp, *klp, *vhp;
    cudaGetSymbolAddress((void**)&qkv,   g_qkv);
    cudaGetSymbolAddress((void**)&xh,    g_xh);
    cudaGetSymbolAddress((void**)&wqkvh, g_wqkvh);
    cudaGetSymbolAddress((void**)&woh,   g_woh);
    cudaGetSymbolAddress((void**)&yh,    g_yh);
    cudaGetSymbolAddress((void**)&qhp,   g_qh);
    cudaGetSymbolAddress((void**)&khp,   g_kh);
    cudaGetSymbolAddress((void**)&klp,   g_kl);
    cudaGetSymbolAddress((void**)&vhp,   g_vh);

    // operand preparation (all fp16 hi only)
    conv_h_kernel<<<(MROWS * DIMM / 2 + 255) / 256, 256>>>(x, xh, MROWS * DIMM / 2);
    conv_h_kernel<<<(DIMM * DIMM / 2 + 255) / 256, 256>>>(Wq, wqkvh, DIMM * DIMM / 2);
    conv_h_kernel<<<(KVD  * DIMM / 2 + 255) / 256, 256>>>(Wk, wqkvh + (size_t)DIMM * DIMM, KVD * DIMM / 2);
    conv_h_kernel<<<(KVD  * DIMM / 2 + 255) / 256, 256>>>(Wv, wqkvh + (size_t)(DIMM + KVD) * DIMM, KVD * DIMM / 2);
    conv_h_kernel<<<(DIMM * DIMM / 2 + 255) / 256, 256>>>(Wo, woh, DIMM * DIMM / 2);

    // fused QKV projection (N = 1536), plain fp16
    gemm_fp16_kernel<<<dim3(QKVD / 128, MROWS / 128), 256>>>(xh, wqkvh, qkv, MROWS, QKVD, DIMM);

    // norm/rope: Q -> fp16 hi; K -> split fp16; V -> fp16 hi
    norm_rope_q_kernel<<<dim3(MROWS, HH / 4),   dim3(32, 4)>>>(qkv, qg, qhp);
    norm_rope_k_kernel<<<dim3(MROWS, KVHH / 4), dim3(32, 4)>>>(qkv, khp, klp);
    conv_vh_kernel<<<(MROWS * KVD / 2 + 255) / 256, 256>>>(qkv, vhp, MROWS * KVD / 2);

    // attention (QK x2 K-compensated, PV x1; fp16-hi output)
    attn_tc_kernel<<<dim3(SS / 128, HH, BB), 256>>>(qhp, khp, klp, vhp, yh);

    // output projection, plain fp16
    gemm_fp16_kernel<<<dim3(DIMM / 128, MROWS / 128), 256>>>(yh, woh, out, MROWS, DIMM, DIMM);
}

// round 15
// speedup vs baseline: 7.3749x; 1.1049x over previous
#include <cuda_runtime.h>
#include <cuda_fp16.h>
#include <math.h>
#include <stdint.h>

#define BB   4
#define SS   2048
#define DIMM 1024
#define HH   16
#define KVHH 4
#define HDD  64
#define KVD  256
#define QKVD 1536
#define MROWS (BB*SS)   // 8192

// Scratch (device globals — no allocations allowed)
__device__ float  g_qkv  [(size_t)MROWS * QKVD];  // 48 MB fused q|k|v (fp32)
__device__ __half g_xh   [(size_t)MROWS * DIMM];  // 16 MB
__device__ __half g_wqkvh[(size_t)QKVD * DIMM];   //  3 MB
__device__ __half g_woh  [(size_t)DIMM * DIMM];   //  2 MB
__device__ __half g_yh   [(size_t)MROWS * DIMM];  // 16 MB
__device__ __half g_qh   [(size_t)MROWS * DIMM];  // 16 MB
__device__ __half g_kh   [(size_t)MROWS * KVD];   //  4 MB
__device__ __half g_vh   [(size_t)MROWS * KVD];

__device__ __forceinline__ void mma16h(float* c, const uint32_t* a, uint32_t b0, uint32_t b1) {
    asm volatile(
        "mma.sync.aligned.m16n8k16.row.col.f32.f16.f16.f32 "
        "{%0,%1,%2,%3}, {%4,%5,%6,%7}, {%8,%9}, {%0,%1,%2,%3};\n"
        : "+f"(c[0]), "+f"(c[1]), "+f"(c[2]), "+f"(c[3])
        : "r"(a[0]), "r"(a[1]), "r"(a[2]), "r"(a[3]), "r"(b0), "r"(b1));
}

__device__ __forceinline__ void ldsm4(uint32_t* r, uint32_t addr) {
    asm volatile("ldmatrix.sync.aligned.m8n8.x4.shared.b16 {%0,%1,%2,%3}, [%4];"
                 : "=r"(r[0]), "=r"(r[1]), "=r"(r[2]), "=r"(r[3]) : "r"(addr));
}

__device__ __forceinline__ void ldsm4t(uint32_t& r0, uint32_t& r1, uint32_t& r2, uint32_t& r3,
                                       uint32_t addr) {
    asm volatile("ldmatrix.sync.aligned.m8n8.x4.trans.shared.b16 {%0,%1,%2,%3}, [%4];"
                 : "=r"(r0), "=r"(r1), "=r"(r2), "=r"(r3) : "r"(addr));
}

__device__ __forceinline__ uint32_t pack2h(float x, float y) {
    __half2 t = __floats2half2_rn(x, y);
    return *reinterpret_cast<uint32_t*>(&t);
}

__device__ __forceinline__ void cp16(void* smem, const void* g) {
    uint32_t s = (uint32_t)__cvta_generic_to_shared(smem);
    asm volatile("cp.async.cg.shared.global [%0], [%1], 16;\n" :: "r"(s), "l"(g));
}

// ---------------------------------------------------------------------------
// fp32 -> fp16 (round-to-nearest), float2 granularity
__global__ void conv_h_kernel(const float* __restrict__ in, __half* __restrict__ out, int n2)
{
    int i = blockIdx.x * blockDim.x + threadIdx.x;
    if (i < n2) {
        float2 f = ((const float2*)in)[i];
        ((uint32_t*)out)[i] = pack2h(f.x, f.y);
    }
}

__global__ void conv_vh_kernel(const float* __restrict__ qkv, __half* __restrict__ vh, int n2)
{
    int i = blockIdx.x * blockDim.x + threadIdx.x;
    if (i < n2) {
        int row = i >> 7, col = i & 127;
        float2 f = ((const float2*)qkv)[(size_t)row * (QKVD / 2) + 640 + col];
        ((uint32_t*)vh)[i] = pack2h(f.x, f.y);
    }
}

// ---------------------------------------------------------------------------
// Plain FP16 GEMM: C[M,N] = Ah[M,K] @ Bh[N,K]^T,  fp32 accum/output.
// CTA 128x128, BK=16, 256 thr, 8 warps (4m x 2n), warp tile 32x64.
// ---------------------------------------------------------------------------
#define GST 24

__global__ void __launch_bounds__(256)
gemm_fp16_kernel(const __half* __restrict__ Ahg, const __half* __restrict__ Bhg,
                 float* __restrict__ C, int M, int N, int K)
{
    __shared__ __half Ah[2][128 * GST], Bh[2][128 * GST];   // 24576 B

    const int tid  = threadIdx.x;
    const int lane = tid & 31;
    const int wid  = tid >> 5;
    const int wm   = (wid & 3) * 32;
    const int wn   = (wid >> 2) * 64;
    const int gid  = lane >> 2;
    const int tig  = lane & 3;
    const int bm   = blockIdx.y * 128;
    const int bn   = blockIdx.x * 128;

    const int lrow = tid >> 1;
    const int lch  = (tid & 1) * 8;
    const __half* Arow = Ahg + (size_t)(bm + lrow) * K + lch;
    const __half* Brow = Bhg + (size_t)(bn + lrow) * K + lch;
    const int soff = lrow * GST + lch;

    const int tl = lane >> 3, lr = lane & 7;
    const int a_row = lr + ((tl & 1) ? 8 : 0);
    const int a_kb  = (tl >= 2) ? 16 : 0;
    const int b_row = lr + ((tl >= 2) ? 8 : 0);
    const int b_kb  = (tl & 1) ? 16 : 0;

    uint32_t aAddr[2][2], bAddr[2][4];
#pragma unroll
    for (int s = 0; s < 2; s++) {
#pragma unroll
        for (int mt = 0; mt < 2; mt++) {
            int r = wm + mt * 16 + a_row;
            aAddr[s][mt] = (uint32_t)__cvta_generic_to_shared(&Ah[s][r * GST]) + a_kb;
        }
#pragma unroll
        for (int np = 0; np < 4; np++) {
            int r = wn + np * 16 + b_row;
            bAddr[s][np] = (uint32_t)__cvta_generic_to_shared(&Bh[s][r * GST]) + b_kb;
        }
    }

    float acc[2][8][4];
#pragma unroll
    for (int i = 0; i < 2; i++)
#pragma unroll
        for (int j = 0; j < 8; j++)
#pragma unroll
            for (int c = 0; c < 4; c++) acc[i][j][c] = 0.f;

    const int T = K / 16;

    cp16(&Ah[0][soff], Arow);
    cp16(&Bh[0][soff], Brow);
    asm volatile("cp.async.commit_group;\n");

    for (int t = 0; t < T; t++) {
        if (t + 1 < T) {
            const int s = (t + 1) & 1, k0 = (t + 1) * 16;
            cp16(&Ah[s][soff], Arow + k0);
            cp16(&Bh[s][soff], Brow + k0);
            asm volatile("cp.async.commit_group;\n");
            asm volatile("cp.async.wait_group 1;\n");
        } else {
            asm volatile("cp.async.wait_group 0;\n");
        }
        __syncthreads();

        const int cb = t & 1;
        uint32_t aF[2][4], bF[4][4];
#pragma unroll
        for (int mt = 0; mt < 2; mt++) ldsm4(aF[mt], aAddr[cb][mt]);
#pragma unroll
        for (int np = 0; np < 4; np++) ldsm4(bF[np], bAddr[cb][np]);

#pragma unroll
        for (int mt = 0; mt < 2; mt++)
#pragma unroll
            for (int np = 0; np < 4; np++) {
                mma16h(acc[mt][np * 2],     aF[mt], bF[np][0], bF[np][1]);
                mma16h(acc[mt][np * 2 + 1], aF[mt], bF[np][2], bF[np][3]);
            }
        __syncthreads();
    }

#pragma unroll
    for (int mt = 0; mt < 2; mt++) {
        const int row0 = bm + wm + mt * 16 + gid;
#pragma unroll
        for (int nt = 0; nt < 8; nt++) {
            const int col = bn + wn + nt * 8 + tig * 2;
            *(float2*)&C[(size_t)row0 * N + col]       = make_float2(acc[mt][nt][0], acc[mt][nt][1]);
            *(float2*)&C[(size_t)(row0 + 8) * N + col] = make_float2(acc[mt][nt][2], acc[mt][nt][3]);
        }
    }
}

// ---------------------------------------------------------------------------
// RMSNorm + RoPE + gain for Q; emits fp16 with 0.125*gain baked in.
// ---------------------------------------------------------------------------
__global__ void norm_rope_q_kernel(const float* __restrict__ qkv, const float* __restrict__ gain,
                                   __half* __restrict__ qh)
{
    const int row = blockIdx.x;
    const int h = blockIdx.y * blockDim.y + threadIdx.y;
    const int s = row & (SS - 1);
    const int d = threadIdx.x;

    const float* p = qkv + (size_t)row * QKVD + h * 64;
    float t1 = p[d];
    float t2 = p[d + 32];

    float ss = t1 * t1 + t2 * t2;
#pragma unroll
    for (int o = 16; o; o >>= 1) ss += __shfl_xor_sync(0xffffffffu, ss, o);
    float r = rsqrtf(ss * (1.0f / 64.0f) + 1e-6f);
    t1 *= r; t2 *= r;

    float inv_freq = exp2f(-(float)d * (13.287712379549449f / 32.0f));
    float th = (float)s * inv_freq;
    float c, sn;
    sincosf(th, &sn, &c);

    float g = gain[h] * 0.125f;
    float o1 = ( t1 * c + t2 * sn) * g;
    float o2 = (-t1 * sn + t2 * c) * g;

    size_t base = (size_t)row * DIMM + h * 64;
    qh[base + d]      = __float2half_rn(o1);
    qh[base + d + 32] = __float2half_rn(o2);
}

// ---------------------------------------------------------------------------
// RMSNorm + RoPE for K; emits fp16 (hi only).
// ---------------------------------------------------------------------------
__global__ void norm_rope_k_kernel(const float* __restrict__ qkv, __half* __restrict__ kh)
{
    const int row = blockIdx.x;
    const int h = blockIdx.y * blockDim.y + threadIdx.y;
    const int s = row & (SS - 1);
    const int d = threadIdx.x;

    const float* p = qkv + (size_t)row * QKVD + 1024 + h * 64;
    float t1 = p[d];
    float t2 = p[d + 32];

    float ss = t1 * t1 + t2 * t2;
#pragma unroll
    for (int o = 16; o; o >>= 1) ss += __shfl_xor_sync(0xffffffffu, ss, o);
    float r = rsqrtf(ss * (1.0f / 64.0f) + 1e-6f);
    t1 *= r; t2 *= r;

    float inv_freq = exp2f(-(float)d * (13.287712379549449f / 32.0f));
    float th = (float)s * inv_freq;
    float c, sn;
    sincosf(th, &sn, &c);

    float o1 =  t1 * c + t2 * sn;
    float o2 = -t1 * sn + t2 * c;

    size_t base = (size_t)row * KVD + h * 64;
    kh[base + d]      = __float2half_rn(o1);
    kh[base + d + 32] = __float2half_rn(o2);
}

// ---------------------------------------------------------------------------
// Causal GQA flash attention — 128-query CTAs, 3-stage cp.async,
// per-warp causal tile skip.  QK^T = qh·kh; PV = ph·vh.  All plain fp16.
// ---------------------------------------------------------------------------
#define KHST 72
#define TROWS 32
#define TSZ (TROWS * KHST)

__global__ void __launch_bounds__(256)
attn_tc_kernel(const __half* __restrict__ gqh, const __half* __restrict__ gkh,
               const __half* __restrict__ gvh, __half* __restrict__ gyh)
{
    __shared__ __half kh[3][TSZ], vh[3][TSZ];   // 27648 B

    const int tid = threadIdx.x, lane = tid & 31, wid = tid >> 5;
    const int gid = lane >> 2, tig = lane & 3;
    const int qb = (gridDim.x - 1) - blockIdx.x;
    const int h = blockIdx.y, b = blockIdx.z;
    const int kvh = h >> 2;
    const int wm = wid * 16;
    const int qrow = qb * 128 + wm;

    uint32_t qh_[4][4];
    {
        const size_t r0 = (size_t)(b * SS + qrow + gid    ) * DIMM + h * 64 + 2 * tig;
        const size_t r1 = (size_t)(b * SS + qrow + gid + 8) * DIMM + h * 64 + 2 * tig;
#pragma unroll
        for (int kc = 0; kc < 4; kc++) {
            qh_[kc][0] = *(const uint32_t*)(gqh + r0 + kc * 16);
            qh_[kc][1] = *(const uint32_t*)(gqh + r1 + kc * 16);
            qh_[kc][2] = *(const uint32_t*)(gqh + r0 + kc * 16 + 8);
            qh_[kc][3] = *(const uint32_t*)(gqh + r1 + kc * 16 + 8);
        }
    }

    const int lrow = tid >> 3;
    const int lch  = (tid & 7) * 8;
    const int soff = lrow * KHST + lch;

    const uint32_t vrow = (lane & 7) + 8 * ((lane >> 3) & 1);
    const uint32_t vcolB = (lane >> 4) * 16;
    uint32_t vbase[3];
#pragma unroll
    for (int s = 0; s < 3; s++)
        vbase[s] = (uint32_t)__cvta_generic_to_shared(&vh[s][0]) + vrow * (KHST * 2) + vcolB;

    float m0 = -INFINITY, m1 = -INFINITY, l0 = 0.f, l1 = 0.f;
    float acc[8][4];
#pragma unroll
    for (int nd = 0; nd < 8; nd++)
#pragma unroll
        for (int c = 0; c < 4; c++) acc[nd][c] = 0.f;

    const int ntiles = 4 * qb + 4;
    const size_t kvbase = (size_t)(b * SS) * KVD + kvh * 64 + (size_t)lrow * KVD + lch;

    {
        size_t go = kvbase;
        cp16(&kh[0][soff], gkh + go);
        cp16(&vh[0][soff], gvh + go);
        asm volatile("cp.async.commit_group;\n");
    }

    for (int kt = 0; kt < ntiles; kt++) {
        if (kt + 1 < ntiles) {
            const int s = (kt + 1) % 3;
            size_t go = kvbase + (size_t)(kt + 1) * TROWS * KVD;
            cp16(&kh[s][soff], gkh + go);
            cp16(&vh[s][soff], gvh + go);
            asm volatile("cp.async.commit_group;\n");
            asm volatile("cp.async.wait_group 1;\n");
        } else {
            asm volatile("cp.async.wait_group 0;\n");
        }
        __syncthreads();

        const int keybase = kt * 32;
        if (keybase > qrow + 15) continue;

        const int cb = kt % 3;

        float sc[4][4];
#pragma unroll
        for (int nt = 0; nt < 4; nt++)
#pragma unroll
            for (int c = 0; c < 4; c++) sc[nt][c] = 0.f;

#pragma unroll
        for (int kc = 0; kc < 4; kc++) {
#pragma unroll
            for (int nt = 0; nt < 4; nt++) {
                const __half* krh = &kh[cb][(nt * 8 + gid) * KHST + kc * 16 + 2 * tig];
                uint32_t bh0 = *(const uint32_t*)krh;
                uint32_t bh1 = *(const uint32_t*)(krh + 8);
                mma16h(sc[nt], qh_[kc], bh0, bh1);
            }
        }

        if (keybase + 31 > qrow) {
            const int off = keybase - qrow;
#pragma unroll
            for (int nt = 0; nt < 4; nt++) {
                int c0 = off + nt * 8 + 2 * tig;
                if (c0     > gid)     sc[nt][0] = -INFINITY;
                if (c0 + 1 > gid)     sc[nt][1] = -INFINITY;
                if (c0     > gid + 8) sc[nt][2] = -INFINITY;
                if (c0 + 1 > gid + 8) sc[nt][3] = -INFINITY;
            }
        }

        float mt0 = m0, mt1 = m1;
#pragma unroll
        for (int nt = 0; nt < 4; nt++) {
            mt0 = fmaxf(mt0, fmaxf(sc[nt][0], sc[nt][1]));
            mt1 = fmaxf(mt1, fmaxf(sc[nt][2], sc[nt][3]));
        }
        mt0 = fmaxf(mt0, __shfl_xor_sync(0xffffffffu, mt0, 1));
        mt0 = fmaxf(mt0, __shfl_xor_sync(0xffffffffu, mt0, 2));
        mt1 = fmaxf(mt1, __shfl_xor_sync(0xffffffffu, mt1, 1));
        mt1 = fmaxf(mt1, __shfl_xor_sync(0xffffffffu, mt1, 2));

        float corr0 = __expf(m0 - mt0);
        float corr1 = __expf(m1 - mt1);
        m0 = mt0; m1 = mt1;
        l0 *= corr0; l1 *= corr1;
#pragma unroll
        for (int nd = 0; nd < 8; nd++) {
            acc[nd][0] *= corr0; acc[nd][1] *= corr0;
            acc[nd][2] *= corr1; acc[nd][3] *= corr1;
        }

#pragma unroll
        for (int nt = 0; nt < 4; nt++) {
            sc[nt][0] = __expf(sc[nt][0] - mt0);
            sc[nt][1] = __expf(sc[nt][1] - mt0);
            sc[nt][2] = __expf(sc[nt][2] - mt1);
            sc[nt][3] = __expf(sc[nt][3] - mt1);
            l0 += sc[nt][0] + sc[nt][1];
            l1 += sc[nt][2] + sc[nt][3];
        }

        // ---- PV: Y += P_hi · V_hi ----
#pragma unroll
        for (int kc = 0; kc < 2; kc++) {
            uint32_t pfh[4];
            pfh[0] = pack2h(sc[2 * kc][0],     sc[2 * kc][1]);
            pfh[1] = pack2h(sc[2 * kc][2],     sc[2 * kc][3]);
            pfh[2] = pack2h(sc[2 * kc + 1][0], sc[2 * kc + 1][1]);
            pfh[3] = pack2h(sc[2 * kc + 1][2], sc[2 * kc + 1][3]);
#pragma unroll
            for (int ndp = 0; ndp < 4; ndp++) {
                uint32_t r0, r1, r2, r3;
                ldsm4t(r0, r1, r2, r3, vbase[cb] + (uint32_t)(kc * 16 * (KHST * 2) + ndp * 32));
                mma16h(acc[ndp * 2],     pfh, r0, r1);
                mma16h(acc[ndp * 2 + 1], pfh, r2, r3);
            }
        }
    }

    l0 += __shfl_xor_sync(0xffffffffu, l0, 1);
    l0 += __shfl_xor_sync(0xffffffffu, l0, 2);
    l1 += __shfl_xor_sync(0xffffffffu, l1, 1);
    l1 += __shfl_xor_sync(0xffffffffu, l1, 2);
    const float inv0 = 1.f / l0;
    const float inv1 = 1.f / l1;

    const size_t o0 = (size_t)(b * SS + qrow + gid    ) * DIMM + h * 64 + 2 * tig;
    const size_t o1 = (size_t)(b * SS + qrow + gid + 8) * DIMM + h * 64 + 2 * tig;
#pragma unroll
    for (int nd = 0; nd < 8; nd++) {
        *(uint32_t*)(gyh + o0 + nd * 8) = pack2h(acc[nd][0] * inv0, acc[nd][1] * inv0);
        *(uint32_t*)(gyh + o1 + nd * 8) = pack2h(acc[nd][2] * inv1, acc[nd][3] * inv1);
    }
}

// ---------------------------------------------------------------------------
extern "C" void kernel_launch(void* const* d_in, const int* in_sizes, int n_in,
                              void* d_out, int out_size)
{
    const float* x  = (const float*)d_in[0];
    const float* Wq = (const float*)d_in[1];
    const float* Wk = (const float*)d_in[2];
    const float* Wv = (const float*)d_in[3];
    const float* Wo = (const float*)d_in[4];
    const float* qg = (const float*)d_in[5];
    float* out = (float*)d_out;

    float* qkv;
    __half *xh, *wqkvh, *woh, *yh, *qhp, *khp, *vhp;
    cudaGetSymbolAddress((void**)&qkv,   g_qkv);
    cudaGetSymbolAddress((void**)&xh,    g_xh);
    cudaGetSymbolAddress((void**)&wqkvh, g_wqkvh);
    cudaGetSymbolAddress((void**)&woh,   g_woh);
    cudaGetSymbolAddress((void**)&yh,    g_yh);
    cudaGetSymbolAddress((void**)&qhp,   g_qh);
    cudaGetSymbolAddress((void**)&khp,   g_kh);
    cudaGetSymbolAddress((void**)&vhp,   g_vh);

    // operand preparation (all fp16 hi only)
    conv_h_kernel<<<(MROWS * DIMM / 2 + 255) / 256, 256>>>(x, xh, MROWS * DIMM / 2);
    conv_h_kernel<<<(DIMM * DIMM / 2 + 255) / 256, 256>>>(Wq, wqkvh, DIMM * DIMM / 2);
    conv_h_kernel<<<(KVD  * DIMM / 2 + 255) / 256, 256>>>(Wk, wqkvh + (size_t)DIMM * DIMM, KVD * DIMM / 2);
    conv_h_kernel<<<(KVD  * DIMM / 2 + 255) / 256, 256>>>(Wv, wqkvh + (size_t)(DIMM + KVD) * DIMM, KVD * DIMM / 2);
    conv_h_kernel<<<(DIMM * DIMM / 2 + 255) / 256, 256>>>(Wo, woh, DIMM * DIMM / 2);

    // fused QKV projection (N = 1536), plain fp16
    gemm_fp16_kernel<<<dim3(QKVD / 128, MROWS / 128), 256>>>(xh, wqkvh, qkv, MROWS, QKVD, DIMM);

    // norm/rope: Q -> fp16; K -> fp16; V -> fp16
    norm_rope_q_kernel<<<dim3(MROWS, HH / 4),   dim3(32, 4)>>>(qkv, qg, qhp);
    norm_rope_k_kernel<<<dim3(MROWS, KVHH / 4), dim3(32, 4)>>>(qkv, khp);
    conv_vh_kernel<<<(MROWS * KVD / 2 + 255) / 256, 256>>>(qkv, vhp, MROWS * KVD / 2);

    // attention (plain fp16 QK and PV)
    attn_tc_kernel<<<dim3(SS / 128, HH, BB), 256>>>(qhp, khp, vhp, yh);

    // output projection, plain fp16
    gemm_fp16_kernel<<<dim3(DIMM / 128, MROWS / 128), 256>>>(yh, woh, out, MROWS, DIMM, DIMM);
}

// round 16
// speedup vs baseline: 7.9799x; 1.0820x over previous
#include <cuda_runtime.h>
#include <cuda_fp16.h>
#include <math.h>
#include <stdint.h>

#define BB   4
#define SS   2048
#define DIMM 1024
#define HH   16
#define KVHH 4
#define HDD  64
#define KVD  256
#define QKVD 1536
#define MROWS (BB*SS)   // 8192

// Scratch (device globals — no allocations allowed)
__device__ __half g_xh   [(size_t)MROWS * DIMM];  // 16 MB
__device__ __half g_wqkvh[(size_t)QKVD * DIMM];   //  3 MB
__device__ __half g_woh  [(size_t)DIMM * DIMM];   //  2 MB
__device__ __half g_yh   [(size_t)MROWS * DIMM];  // 16 MB
__device__ __half g_qh   [(size_t)MROWS * DIMM];  // 16 MB
__device__ __half g_kh   [(size_t)MROWS * KVD];   //  4 MB
__device__ __half g_vh   [(size_t)MROWS * KVD];

#define ROPE_L2 (13.287712379549449f / 32.0f)   // log2(10000)/32

__device__ __forceinline__ void mma16h(float* c, const uint32_t* a, uint32_t b0, uint32_t b1) {
    asm volatile(
        "mma.sync.aligned.m16n8k16.row.col.f32.f16.f16.f32 "
        "{%0,%1,%2,%3}, {%4,%5,%6,%7}, {%8,%9}, {%0,%1,%2,%3};\n"
        : "+f"(c[0]), "+f"(c[1]), "+f"(c[2]), "+f"(c[3])
        : "r"(a[0]), "r"(a[1]), "r"(a[2]), "r"(a[3]), "r"(b0), "r"(b1));
}

__device__ __forceinline__ void ldsm4(uint32_t* r, uint32_t addr) {
    asm volatile("ldmatrix.sync.aligned.m8n8.x4.shared.b16 {%0,%1,%2,%3}, [%4];"
                 : "=r"(r[0]), "=r"(r[1]), "=r"(r[2]), "=r"(r[3]) : "r"(addr));
}

__device__ __forceinline__ void ldsm4t(uint32_t& r0, uint32_t& r1, uint32_t& r2, uint32_t& r3,
                                       uint32_t addr) {
    asm volatile("ldmatrix.sync.aligned.m8n8.x4.trans.shared.b16 {%0,%1,%2,%3}, [%4];"
                 : "=r"(r0), "=r"(r1), "=r"(r2), "=r"(r3) : "r"(addr));
}

__device__ __forceinline__ uint32_t pack2h(float x, float y) {
    __half2 t = __floats2half2_rn(x, y);
    return *reinterpret_cast<uint32_t*>(&t);
}

__device__ __forceinline__ void cp16(void* smem, const void* g) {
    uint32_t s = (uint32_t)__cvta_generic_to_shared(smem);
    asm volatile("cp.async.cg.shared.global [%0], [%1], 16;\n" :: "r"(s), "l"(g));
}

// ---------------------------------------------------------------------------
__global__ void conv_h_kernel(const float* __restrict__ in, __half* __restrict__ out, int n2)
{
    int i = blockIdx.x * blockDim.x + threadIdx.x;
    if (i < n2) {
        float2 f = ((const float2*)in)[i];
        ((uint32_t*)out)[i] = pack2h(f.x, f.y);
    }
}

// ---------------------------------------------------------------------------
// Fused QKV GEMM: C = Xh @ Wqkv^T with per-warp epilogue:
//   cols [0,1024):   Q -> rmsnorm + rope + gain*0.125 -> g_qh fp16
//   cols [1024,1280): K -> rmsnorm + rope            -> g_kh fp16
//   cols [1280,1536): V -> plain fp16                -> g_vh
// CTA 128x128, BK=16, 256 thr, warp tile 32x64 (= one head wide).
// ---------------------------------------------------------------------------
#define GST 24

__global__ void __launch_bounds__(256)
gemm_qkv_fused_kernel(const __half* __restrict__ Ahg, const __half* __restrict__ Bhg,
                      const float* __restrict__ gain,
                      __half* __restrict__ gqh, __half* __restrict__ gkh,
                      __half* __restrict__ gvh)
{
    const int K = DIMM;
    __shared__ __half Ah[2][128 * GST], Bh[2][128 * GST];

    const int tid  = threadIdx.x;
    const int lane = tid & 31;
    const int wid  = tid >> 5;
    const int wm   = (wid & 3) * 32;
    const int wn   = (wid >> 2) * 64;
    const int gid  = lane >> 2;
    const int tig  = lane & 3;
    const int bm   = blockIdx.y * 128;
    const int bn   = blockIdx.x * 128;

    const int lrow = tid >> 1;
    const int lch  = (tid & 1) * 8;
    const __half* Arow = Ahg + (size_t)(bm + lrow) * K + lch;
    const __half* Brow = Bhg + (size_t)(bn + lrow) * K + lch;
    const int soff = lrow * GST + lch;

    const int tl = lane >> 3, lr = lane & 7;
    const int a_row = lr + ((tl & 1) ? 8 : 0);
    const int a_kb  = (tl >= 2) ? 16 : 0;
    const int b_row = lr + ((tl >= 2) ? 8 : 0);
    const int b_kb  = (tl & 1) ? 16 : 0;

    uint32_t aAddr[2][2], bAddr[2][4];
#pragma unroll
    for (int s = 0; s < 2; s++) {
#pragma unroll
        for (int mt = 0; mt < 2; mt++) {
            int r = wm + mt * 16 + a_row;
            aAddr[s][mt] = (uint32_t)__cvta_generic_to_shared(&Ah[s][r * GST]) + a_kb;
        }
#pragma unroll
        for (int np = 0; np < 4; np++) {
            int r = wn + np * 16 + b_row;
            bAddr[s][np] = (uint32_t)__cvta_generic_to_shared(&Bh[s][r * GST]) + b_kb;
        }
    }

    float acc[2][8][4];
#pragma unroll
    for (int i = 0; i < 2; i++)
#pragma unroll
        for (int j = 0; j < 8; j++)
#pragma unroll
            for (int c = 0; c < 4; c++) acc[i][j][c] = 0.f;

    const int T = K / 16;

    cp16(&Ah[0][soff], Arow);
    cp16(&Bh[0][soff], Brow);
    asm volatile("cp.async.commit_group;\n");

    for (int t = 0; t < T; t++) {
        if (t + 1 < T) {
            const int s = (t + 1) & 1, k0 = (t + 1) * 16;
            cp16(&Ah[s][soff], Arow + k0);
            cp16(&Bh[s][soff], Brow + k0);
            asm volatile("cp.async.commit_group;\n");
            asm volatile("cp.async.wait_group 1;\n");
        } else {
            asm volatile("cp.async.wait_group 0;\n");
        }
        __syncthreads();

        const int cb = t & 1;
        uint32_t aF[2][4], bF[4][4];
#pragma unroll
        for (int mt = 0; mt < 2; mt++) ldsm4(aF[mt], aAddr[cb][mt]);
#pragma unroll
        for (int np = 0; np < 4; np++) ldsm4(bF[np], bAddr[cb][np]);

#pragma unroll
        for (int mt = 0; mt < 2; mt++)
#pragma unroll
            for (int np = 0; np < 4; np++) {
                mma16h(acc[mt][np * 2],     aF[mt], bF[np][0], bF[np][1]);
                mma16h(acc[mt][np * 2 + 1], aF[mt], bF[np][2], bF[np][3]);
            }
        __syncthreads();
    }

    // ---- fused epilogue ----
    const int colbase = bn + wn;   // multiple of 64 == head boundary

    if (colbase < DIMM + KVD) {
        // Q or K: rmsnorm + rope (+ gain for Q)
        const float g = (colbase < DIMM) ? gain[colbase >> 6] * 0.125f : 1.0f;
        __half* outp  = (colbase < DIMM) ? gqh : gkh;
        const int ost = (colbase < DIMM) ? DIMM : KVD;
        const int oc  = (colbase < DIMM) ? colbase : colbase - DIMM;

        float invf[8];
#pragma unroll
        for (int nt = 0; nt < 4; nt++) {
            int d0 = nt * 8 + 2 * tig;
            invf[2 * nt]     = exp2f(-(float)d0 * ROPE_L2);
            invf[2 * nt + 1] = exp2f(-(float)(d0 + 1) * ROPE_L2);
        }

#pragma unroll
        for (int mt = 0; mt < 2; mt++) {
            const int r0 = bm + wm + mt * 16 + gid;
            const float s0 = (float)(r0 & (SS - 1));
            const float s1 = s0 + 8.0f;

            float ss0 = 0.f, ss1 = 0.f;
#pragma unroll
            for (int nt = 0; nt < 8; nt++) {
                ss0 += acc[mt][nt][0] * acc[mt][nt][0] + acc[mt][nt][1] * acc[mt][nt][1];
                ss1 += acc[mt][nt][2] * acc[mt][nt][2] + acc[mt][nt][3] * acc[mt][nt][3];
            }
            ss0 += __shfl_xor_sync(0xffffffffu, ss0, 1);
            ss0 += __shfl_xor_sync(0xffffffffu, ss0, 2);
            ss1 += __shfl_xor_sync(0xffffffffu, ss1, 1);
            ss1 += __shfl_xor_sync(0xffffffffu, ss1, 2);
            const float rn0 = rsqrtf(ss0 * (1.0f / 64.0f) + 1e-6f);
            const float rn1 = rsqrtf(ss1 * (1.0f / 64.0f) + 1e-6f);

            __half* row0 = outp + (size_t)r0 * ost + oc;
            __half* row1 = row0 + (size_t)8 * ost;

#pragma unroll
            for (int nt = 0; nt < 4; nt++) {
                float c00, sn00, c01, sn01, c10, sn10, c11, sn11;
                sincosf(s0 * invf[2 * nt],     &sn00, &c00);
                sincosf(s0 * invf[2 * nt + 1], &sn01, &c01);
                sincosf(s1 * invf[2 * nt],     &sn10, &c10);
                sincosf(s1 * invf[2 * nt + 1], &sn11, &c11);

                // row r0
                float t1 = acc[mt][nt][0] * rn0, t2 = acc[mt][nt + 4][0] * rn0;
                float u1 = acc[mt][nt][1] * rn0, u2 = acc[mt][nt + 4][1] * rn0;
                float lo0 = ( t1 * c00 + t2 * sn00) * g;
                float hi0 = (-t1 * sn00 + t2 * c00) * g;
                float lo1 = ( u1 * c01 + u2 * sn01) * g;
                float hi1 = (-u1 * sn01 + u2 * c01) * g;
                *(uint32_t*)(row0 + nt * 8 + 2 * tig)       = pack2h(lo0, lo1);
                *(uint32_t*)(row0 + (nt + 4) * 8 + 2 * tig) = pack2h(hi0, hi1);

                // row r0+8
                float v1 = acc[mt][nt][2] * rn1, v2 = acc[mt][nt + 4][2] * rn1;
                float w1 = acc[mt][nt][3] * rn1, w2 = acc[mt][nt + 4][3] * rn1;
                float lo2 = ( v1 * c10 + v2 * sn10) * g;
                float hi2 = (-v1 * sn10 + v2 * c10) * g;
                float lo3 = ( w1 * c11 + w2 * sn11) * g;
                float hi3 = (-w1 * sn11 + w2 * c11) * g;
                *(uint32_t*)(row1 + nt * 8 + 2 * tig)       = pack2h(lo2, lo3);
                *(uint32_t*)(row1 + (nt + 4) * 8 + 2 * tig) = pack2h(hi2, hi3);
            }
        }
    } else {
        // V: plain fp16 store
        const int oc = colbase - (DIMM + KVD);
#pragma unroll
        for (int mt = 0; mt < 2; mt++) {
            const int r0 = bm + wm + mt * 16 + gid;
            __half* row0 = gvh + (size_t)r0 * KVD + oc;
            __half* row1 = row0 + (size_t)8 * KVD;
#pragma unroll
            for (int nt = 0; nt < 8; nt++) {
                *(uint32_t*)(row0 + nt * 8 + 2 * tig) = pack2h(acc[mt][nt][0], acc[mt][nt][1]);
                *(uint32_t*)(row1 + nt * 8 + 2 * tig) = pack2h(acc[mt][nt][2], acc[mt][nt][3]);
            }
        }
    }
}

// ---------------------------------------------------------------------------
// Plain FP16 GEMM (fp32 out) — output projection.
// ---------------------------------------------------------------------------
__global__ void __launch_bounds__(256)
gemm_fp16_kernel(const __half* __restrict__ Ahg, const __half* __restrict__ Bhg,
                 float* __restrict__ C, int M, int N, int K)
{
    __shared__ __half Ah[2][128 * GST], Bh[2][128 * GST];

    const int tid  = threadIdx.x;
    const int lane = tid & 31;
    const int wid  = tid >> 5;
    const int wm   = (wid & 3) * 32;
    const int wn   = (wid >> 2) * 64;
    const int gid  = lane >> 2;
    const int tig  = lane & 3;
    const int bm   = blockIdx.y * 128;
    const int bn   = blockIdx.x * 128;

    const int lrow = tid >> 1;
    const int lch  = (tid & 1) * 8;
    const __half* Arow = Ahg + (size_t)(bm + lrow) * K + lch;
    const __half* Brow = Bhg + (size_t)(bn + lrow) * K + lch;
    const int soff = lrow * GST + lch;

    const int tl = lane >> 3, lr = lane & 7;
    const int a_row = lr + ((tl & 1) ? 8 : 0);
    const int a_kb  = (tl >= 2) ? 16 : 0;
    const int b_row = lr + ((tl >= 2) ? 8 : 0);
    const int b_kb  = (tl & 1) ? 16 : 0;

    uint32_t aAddr[2][2], bAddr[2][4];
#pragma unroll
    for (int s = 0; s < 2; s++) {
#pragma unroll
        for (int mt = 0; mt < 2; mt++) {
            int r = wm + mt * 16 + a_row;
            aAddr[s][mt] = (uint32_t)__cvta_generic_to_shared(&Ah[s][r * GST]) + a_kb;
        }
#pragma unroll
        for (int np = 0; np < 4; np++) {
            int r = wn + np * 16 + b_row;
            bAddr[s][np] = (uint32_t)__cvta_generic_to_shared(&Bh[s][r * GST]) + b_kb;
        }
    }

    float acc[2][8][4];
#pragma unroll
    for (int i = 0; i < 2; i++)
#pragma unroll
        for (int j = 0; j < 8; j++)
#pragma unroll
            for (int c = 0; c < 4; c++) acc[i][j][c] = 0.f;

    const int T = K / 16;

    cp16(&Ah[0][soff], Arow);
    cp16(&Bh[0][soff], Brow);
    asm volatile("cp.async.commit_group;\n");

    for (int t = 0; t < T; t++) {
        if (t + 1 < T) {
            const int s = (t + 1) & 1, k0 = (t + 1) * 16;
            cp16(&Ah[s][soff], Arow + k0);
            cp16(&Bh[s][soff], Brow + k0);
            asm volatile("cp.async.commit_group;\n");
            asm volatile("cp.async.wait_group 1;\n");
        } else {
            asm volatile("cp.async.wait_group 0;\n");
        }
        __syncthreads();

        const int cb = t & 1;
        uint32_t aF[2][4], bF[4][4];
#pragma unroll
        for (int mt = 0; mt < 2; mt++) ldsm4(aF[mt], aAddr[cb][mt]);
#pragma unroll
        for (int np = 0; np < 4; np++) ldsm4(bF[np], bAddr[cb][np]);

#pragma unroll
        for (int mt = 0; mt < 2; mt++)
#pragma unroll
            for (int np = 0; np < 4; np++) {
                mma16h(acc[mt][np * 2],     aF[mt], bF[np][0], bF[np][1]);
                mma16h(acc[mt][np * 2 + 1], aF[mt], bF[np][2], bF[np][3]);
            }
        __syncthreads();
    }

#pragma unroll
    for (int mt = 0; mt < 2; mt++) {
        const int row0 = bm + wm + mt * 16 + gid;
#pragma unroll
        for (int nt = 0; nt < 8; nt++) {
            const int col = bn + wn + nt * 8 + tig * 2;
            *(float2*)&C[(size_t)row0 * N + col]       = make_float2(acc[mt][nt][0], acc[mt][nt][1]);
            *(float2*)&C[(size_t)(row0 + 8) * N + col] = make_float2(acc[mt][nt][2], acc[mt][nt][3]);
        }
    }
}

// ---------------------------------------------------------------------------
// Causal GQA flash attention — 128-query CTAs, 3-stage cp.async,
// per-warp causal tile skip.  Plain fp16 QK and PV.
// ---------------------------------------------------------------------------
#define KHST 72
#define TROWS 32
#define TSZ (TROWS * KHST)

__global__ void __launch_bounds__(256)
attn_tc_kernel(const __half* __restrict__ gqh, const __half* __restrict__ gkh,
               const __half* __restrict__ gvh, __half* __restrict__ gyh)
{
    __shared__ __half kh[3][TSZ], vh[3][TSZ];

    const int tid = threadIdx.x, lane = tid & 31, wid = tid >> 5;
    const int gid = lane >> 2, tig = lane & 3;
    const int qb = (gridDim.x - 1) - blockIdx.x;
    const int h = blockIdx.y, b = blockIdx.z;
    const int kvh = h >> 2;
    const int wm = wid * 16;
    const int qrow = qb * 128 + wm;

    uint32_t qh_[4][4];
    {
        const size_t r0 = (size_t)(b * SS + qrow + gid    ) * DIMM + h * 64 + 2 * tig;
        const size_t r1 = (size_t)(b * SS + qrow + gid + 8) * DIMM + h * 64 + 2 * tig;
#pragma unroll
        for (int kc = 0; kc < 4; kc++) {
            qh_[kc][0] = *(const uint32_t*)(gqh + r0 + kc * 16);
            qh_[kc][1] = *(const uint32_t*)(gqh + r1 + kc * 16);
            qh_[kc][2] = *(const uint32_t*)(gqh + r0 + kc * 16 + 8);
            qh_[kc][3] = *(const uint32_t*)(gqh + r1 + kc * 16 + 8);
        }
    }

    const int lrow = tid >> 3;
    const int lch  = (tid & 7) * 8;
    const int soff = lrow * KHST + lch;

    const uint32_t vrow = (lane & 7) + 8 * ((lane >> 3) & 1);
    const uint32_t vcolB = (lane >> 4) * 16;
    uint32_t vbase[3];
#pragma unroll
    for (int s = 0; s < 3; s++)
        vbase[s] = (uint32_t)__cvta_generic_to_shared(&vh[s][0]) + vrow * (KHST * 2) + vcolB;

    float m0 = -INFINITY, m1 = -INFINITY, l0 = 0.f, l1 = 0.f;
    float acc[8][4];
#pragma unroll
    for (int nd = 0; nd < 8; nd++)
#pragma unroll
        for (int c = 0; c < 4; c++) acc[nd][c] = 0.f;

    const int ntiles = 4 * qb + 4;
    const size_t kvbase = (size_t)(b * SS) * KVD + kvh * 64 + (size_t)lrow * KVD + lch;

    {
        size_t go = kvbase;
        cp16(&kh[0][soff], gkh + go);
        cp16(&vh[0][soff], gvh + go);
        asm volatile("cp.async.commit_group;\n");
    }

    for (int kt = 0; kt < ntiles; kt++) {
        if (kt + 1 < ntiles) {
            const int s = (kt + 1) % 3;
            size_t go = kvbase + (size_t)(kt + 1) * TROWS * KVD;
            cp16(&kh[s][soff], gkh + go);
            cp16(&vh[s][soff], gvh + go);
            asm volatile("cp.async.commit_group;\n");
            asm volatile("cp.async.wait_group 1;\n");
        } else {
            asm volatile("cp.async.wait_group 0;\n");
        }
        __syncthreads();

        const int keybase = kt * 32;
        if (keybase > qrow + 15) continue;

        const int cb = kt % 3;

        float sc[4][4];
#pragma unroll
        for (int nt = 0; nt < 4; nt++)
#pragma unroll
            for (int c = 0; c < 4; c++) sc[nt][c] = 0.f;

#pragma unroll
        for (int kc = 0; kc < 4; kc++) {
#pragma unroll
            for (int nt = 0; nt < 4; nt++) {
                const __half* krh = &kh[cb][(nt * 8 + gid) * KHST + kc * 16 + 2 * tig];
                uint32_t bh0 = *(const uint32_t*)krh;
                uint32_t bh1 = *(const uint32_t*)(krh + 8);
                mma16h(sc[nt], qh_[kc], bh0, bh1);
            }
        }

        if (keybase + 31 > qrow) {
            const int off = keybase - qrow;
#pragma unroll
            for (int nt = 0; nt < 4; nt++) {
                int c0 = off + nt * 8 + 2 * tig;
                if (c0     > gid)     sc[nt][0] = -INFINITY;
                if (c0 + 1 > gid)     sc[nt][1] = -INFINITY;
                if (c0     > gid + 8) sc[nt][2] = -INFINITY;
                if (c0 + 1 > gid + 8) sc[nt][3] = -INFINITY;
            }
        }

        float mt0 = m0, mt1 = m1;
#pragma unroll
        for (int nt = 0; nt < 4; nt++) {
            mt0 = fmaxf(mt0, fmaxf(sc[nt][0], sc[nt][1]));
            mt1 = fmaxf(mt1, fmaxf(sc[nt][2], sc[nt][3]));
        }
        mt0 = fmaxf(mt0, __shfl_xor_sync(0xffffffffu, mt0, 1));
        mt0 = fmaxf(mt0, __shfl_xor_sync(0xffffffffu, mt0, 2));
        mt1 = fmaxf(mt1, __shfl_xor_sync(0xffffffffu, mt1, 1));
        mt1 = fmaxf(mt1, __shfl_xor_sync(0xffffffffu, mt1, 2));

        float corr0 = __expf(m0 - mt0);
        float corr1 = __expf(m1 - mt1);
        m0 = mt0; m1 = mt1;
        l0 *= corr0; l1 *= corr1;
#pragma unroll
        for (int nd = 0; nd < 8; nd++) {
            acc[nd][0] *= corr0; acc[nd][1] *= corr0;
            acc[nd][2] *= corr1; acc[nd][3] *= corr1;
        }

#pragma unroll
        for (int nt = 0; nt < 4; nt++) {
            sc[nt][0] = __expf(sc[nt][0] - mt0);
            sc[nt][1] = __expf(sc[nt][1] - mt0);
            sc[nt][2] = __expf(sc[nt][2] - mt1);
            sc[nt][3] = __expf(sc[nt][3] - mt1);
            l0 += sc[nt][0] + sc[nt][1];
            l1 += sc[nt][2] + sc[nt][3];
        }

#pragma unroll
        for (int kc = 0; kc < 2; kc++) {
            uint32_t pfh[4];
            pfh[0] = pack2h(sc[2 * kc][0],     sc[2 * kc][1]);
            pfh[1] = pack2h(sc[2 * kc][2],     sc[2 * kc][3]);
            pfh[2] = pack2h(sc[2 * kc + 1][0], sc[2 * kc + 1][1]);
            pfh[3] = pack2h(sc[2 * kc + 1][2], sc[2 * kc + 1][3]);
#pragma unroll
            for (int ndp = 0; ndp < 4; ndp++) {
                uint32_t r0, r1, r2, r3;
                ldsm4t(r0, r1, r2, r3, vbase[cb] + (uint32_t)(kc * 16 * (KHST * 2) + ndp * 32));
                mma16h(acc[ndp * 2],     pfh, r0, r1);
                mma16h(acc[ndp * 2 + 1], pfh, r2, r3);
            }
        }
    }

    l0 += __shfl_xor_sync(0xffffffffu, l0, 1);
    l0 += __shfl_xor_sync(0xffffffffu, l0, 2);
    l1 += __shfl_xor_sync(0xffffffffu, l1, 1);
    l1 += __shfl_xor_sync(0xffffffffu, l1, 2);
    const float inv0 = 1.f / l0;
    const float inv1 = 1.f / l1;

    const size_t o0 = (size_t)(b * SS + qrow + gid    ) * DIMM + h * 64 + 2 * tig;
    const size_t o1 = (size_t)(b * SS + qrow + gid + 8) * DIMM + h * 64 + 2 * tig;
#pragma unroll
    for (int nd = 0; nd < 8; nd++) {
        *(uint32_t*)(gyh + o0 + nd * 8) = pack2h(acc[nd][0] * inv0, acc[nd][1] * inv0);
        *(uint32_t*)(gyh + o1 + nd * 8) = pack2h(acc[nd][2] * inv1, acc[nd][3] * inv1);
    }
}

// ---------------------------------------------------------------------------
extern "C" void kernel_launch(void* const* d_in, const int* in_sizes, int n_in,
                              void* d_out, int out_size)
{
    const float* x  = (const float*)d_in[0];
    const float* Wq = (const float*)d_in[1];
    const float* Wk = (const float*)d_in[2];
    const float* Wv = (const float*)d_in[3];
    const float* Wo = (const float*)d_in[4];
    const float* qg = (const float*)d_in[5];
    float* out = (float*)d_out;

    __half *xh, *wqkvh, *woh, *yh, *qhp, *khp, *vhp;
    cudaGetSymbolAddress((void**)&xh,    g_xh);
    cudaGetSymbolAddress((void**)&wqkvh, g_wqkvh);
    cudaGetSymbolAddress((void**)&woh,   g_woh);
    cudaGetSymbolAddress((void**)&yh,    g_yh);
    cudaGetSymbolAddress((void**)&qhp,   g_qh);
    cudaGetSymbolAddress((void**)&khp,   g_kh);
    cudaGetSymbolAddress((void**)&vhp,   g_vh);

    // operand preparation (fp16)
    conv_h_kernel<<<(MROWS * DIMM / 2 + 255) / 256, 256>>>(x, xh, MROWS * DIMM / 2);
    conv_h_kernel<<<(DIMM * DIMM / 2 + 255) / 256, 256>>>(Wq, wqkvh, DIMM * DIMM / 2);
    conv_h_kernel<<<(KVD  * DIMM / 2 + 255) / 256, 256>>>(Wk, wqkvh + (size_t)DIMM * DIMM, KVD * DIMM / 2);
    conv_h_kernel<<<(KVD  * DIMM / 2 + 255) / 256, 256>>>(Wv, wqkvh + (size_t)(DIMM + KVD) * DIMM, KVD * DIMM / 2);
    conv_h_kernel<<<(DIMM * DIMM / 2 + 255) / 256, 256>>>(Wo, woh, DIMM * DIMM / 2);

    // fused QKV projection + norm/rope/convert epilogue
    gemm_qkv_fused_kernel<<<dim3(QKVD / 128, MROWS / 128), 256>>>(xh, wqkvh, qg, qhp, khp, vhp);

    // attention (plain fp16 QK and PV)
    attn_tc_kernel<<<dim3(SS / 128, HH, BB), 256>>>(qhp, khp, vhp, yh);

    // output projection
    gemm_fp16_kernel<<<dim3(DIMM / 128, MROWS / 128), 256>>>(yh, woh, out, MROWS, DIMM, DIMM);
}

// round 17
// speedup vs baseline: 8.9875x; 1.1263x over previous
#include <cuda_runtime.h>
#include <cuda_fp16.h>
#include <math.h>
#include <stdint.h>

#define BB   4
#define SS   2048
#define DIMM 1024
#define HH   16
#define KVHH 4
#define HDD  64
#define KVD  256
#define QKVD 1536
#define MROWS (BB*SS)   // 8192

// Scratch (device globals — no allocations allowed)
__device__ __half g_xh   [(size_t)MROWS * DIMM];  // 16 MB
__device__ __half g_wqkvh[(size_t)QKVD * DIMM];   //  3 MB
__device__ __half g_woh  [(size_t)DIMM * DIMM];   //  2 MB
__device__ __half g_yh   [(size_t)MROWS * DIMM];  // 16 MB
__device__ __half g_qh   [(size_t)MROWS * DIMM];  // 16 MB
__device__ __half g_kh   [(size_t)MROWS * KVD];   //  4 MB
__device__ __half g_vh   [(size_t)MROWS * KVD];

#define ROPE_L2 (13.287712379549449f / 32.0f)   // log2(10000)/32

__device__ __forceinline__ void mma16h(float* c, const uint32_t* a, uint32_t b0, uint32_t b1) {
    asm volatile(
        "mma.sync.aligned.m16n8k16.row.col.f32.f16.f16.f32 "
        "{%0,%1,%2,%3}, {%4,%5,%6,%7}, {%8,%9}, {%0,%1,%2,%3};\n"
        : "+f"(c[0]), "+f"(c[1]), "+f"(c[2]), "+f"(c[3])
        : "r"(a[0]), "r"(a[1]), "r"(a[2]), "r"(a[3]), "r"(b0), "r"(b1));
}

__device__ __forceinline__ void ldsm4(uint32_t* r, uint32_t addr) {
    asm volatile("ldmatrix.sync.aligned.m8n8.x4.shared.b16 {%0,%1,%2,%3}, [%4];"
                 : "=r"(r[0]), "=r"(r[1]), "=r"(r[2]), "=r"(r[3]) : "r"(addr));
}

__device__ __forceinline__ void ldsm4t(uint32_t& r0, uint32_t& r1, uint32_t& r2, uint32_t& r3,
                                       uint32_t addr) {
    asm volatile("ldmatrix.sync.aligned.m8n8.x4.trans.shared.b16 {%0,%1,%2,%3}, [%4];"
                 : "=r"(r0), "=r"(r1), "=r"(r2), "=r"(r3) : "r"(addr));
}

__device__ __forceinline__ uint32_t pack2h(float x, float y) {
    __half2 t = __floats2half2_rn(x, y);
    return *reinterpret_cast<uint32_t*>(&t);
}

__device__ __forceinline__ void cp16(void* smem, const void* g) {
    uint32_t s = (uint32_t)__cvta_generic_to_shared(smem);
    asm volatile("cp.async.cg.shared.global [%0], [%1], 16;\n" :: "r"(s), "l"(g));
}

// ---------------------------------------------------------------------------
__global__ void conv_h_kernel(const float* __restrict__ in, __half* __restrict__ out, int n2)
{
    int i = blockIdx.x * blockDim.x + threadIdx.x;
    if (i < n2) {
        float2 f = ((const float2*)in)[i];
        ((uint32_t*)out)[i] = pack2h(f.x, f.y);
    }
}

// all four weight matrices in one launch
__global__ void conv_w_all_kernel(const float* __restrict__ Wq, const float* __restrict__ Wk,
                                  const float* __restrict__ Wv, const float* __restrict__ Wo,
                                  __half* __restrict__ wqkvh, __half* __restrict__ woh)
{
    const int NQ = DIMM * DIMM / 2;
    const int NK = KVD * DIMM / 2;
    const int NQKV = NQ + 2 * NK;
    const int NO = DIMM * DIMM / 2;
    int i = blockIdx.x * blockDim.x + threadIdx.x;
    if (i < NQKV) {
        float2 f;
        if (i < NQ)           f = ((const float2*)Wq)[i];
        else if (i < NQ + NK) f = ((const float2*)Wk)[i - NQ];
        else                  f = ((const float2*)Wv)[i - NQ - NK];
        ((uint32_t*)wqkvh)[i] = pack2h(f.x, f.y);
    } else if (i < NQKV + NO) {
        float2 f = ((const float2*)Wo)[i - NQKV];
        ((uint32_t*)woh)[i - NQKV] = pack2h(f.x, f.y);
    }
}

// ---------------------------------------------------------------------------
// Shared GEMM mainloop pieces (BK=32, row stride 40 halves, double-buffered).
// ---------------------------------------------------------------------------
#define GST2 40   // halves per smem row (32 + 8 pad; row*80B spans 8 phases mod 128)

// ---------------------------------------------------------------------------
// Fused QKV GEMM + norm/rope/convert epilogue.  BK=32.
// ---------------------------------------------------------------------------
__global__ void __launch_bounds__(256)
gemm_qkv_fused_kernel(const __half* __restrict__ Ahg, const __half* __restrict__ Bhg,
                      const float* __restrict__ gain,
                      __half* __restrict__ gqh, __half* __restrict__ gkh,
                      __half* __restrict__ gvh)
{
    const int K = DIMM;
    __shared__ __half Ah[2][128 * GST2], Bh[2][128 * GST2];   // 40960 B

    const int tid  = threadIdx.x;
    const int lane = tid & 31;
    const int wid  = tid >> 5;
    const int wm   = (wid & 3) * 32;
    const int wn   = (wid >> 2) * 64;
    const int gid  = lane >> 2;
    const int tig  = lane & 3;
    const int bm   = blockIdx.y * 128;
    const int bn   = blockIdx.x * 128;

    // loader: 512 chunks of 16B per array; 2 per thread
    const int lrow0 = tid >> 2;                 // 0..63
    const int lch0  = (tid & 3) * 8;            // 0,8,16,24
    const int lrow1 = lrow0 + 64;

    const __half* ArowA = Ahg + (size_t)(bm + lrow0) * K + lch0;
    const __half* ArowB = Ahg + (size_t)(bm + lrow1) * K + lch0;
    const __half* BrowA = Bhg + (size_t)(bn + lrow0) * K + lch0;
    const __half* BrowB = Bhg + (size_t)(bn + lrow1) * K + lch0;
    const int soffA = lrow0 * GST2 + lch0;
    const int soffB = lrow1 * GST2 + lch0;

    const int tl = lane >> 3, lr = lane & 7;
    const int a_row = lr + ((tl & 1) ? 8 : 0);
    const int a_kb  = (tl >= 2) ? 16 : 0;
    const int b_row = lr + ((tl >= 2) ? 8 : 0);
    const int b_kb  = (tl & 1) ? 16 : 0;

    uint32_t aAddr[2][2], bAddr[2][4];
#pragma unroll
    for (int s = 0; s < 2; s++) {
#pragma unroll
        for (int mt = 0; mt < 2; mt++) {
            int r = wm + mt * 16 + a_row;
            aAddr[s][mt] = (uint32_t)__cvta_generic_to_shared(&Ah[s][r * GST2]) + a_kb;
        }
#pragma unroll
        for (int np = 0; np < 4; np++) {
            int r = wn + np * 16 + b_row;
            bAddr[s][np] = (uint32_t)__cvta_generic_to_shared(&Bh[s][r * GST2]) + b_kb;
        }
    }

    float acc[2][8][4];
#pragma unroll
    for (int i = 0; i < 2; i++)
#pragma unroll
        for (int j = 0; j < 8; j++)
#pragma unroll
            for (int c = 0; c < 4; c++) acc[i][j][c] = 0.f;

    const int T = K / 32;

    cp16(&Ah[0][soffA], ArowA);
    cp16(&Ah[0][soffB], ArowB);
    cp16(&Bh[0][soffA], BrowA);
    cp16(&Bh[0][soffB], BrowB);
    asm volatile("cp.async.commit_group;\n");

    for (int t = 0; t < T; t++) {
        if (t + 1 < T) {
            const int s = (t + 1) & 1, k0 = (t + 1) * 32;
            cp16(&Ah[s][soffA], ArowA + k0);
            cp16(&Ah[s][soffB], ArowB + k0);
            cp16(&Bh[s][soffA], BrowA + k0);
            cp16(&Bh[s][soffB], BrowB + k0);
            asm volatile("cp.async.commit_group;\n");
            asm volatile("cp.async.wait_group 1;\n");
        } else {
            asm volatile("cp.async.wait_group 0;\n");
        }
        __syncthreads();

        const int cb = t & 1;
#pragma unroll
        for (int ks = 0; ks < 2; ks++) {
            const uint32_t kofs = (uint32_t)(ks * 32);
            uint32_t aF[2][4], bF[4][4];
#pragma unroll
            for (int mt = 0; mt < 2; mt++) ldsm4(aF[mt], aAddr[cb][mt] + kofs);
#pragma unroll
            for (int np = 0; np < 4; np++) ldsm4(bF[np], bAddr[cb][np] + kofs);
#pragma unroll
            for (int mt = 0; mt < 2; mt++)
#pragma unroll
                for (int np = 0; np < 4; np++) {
                    mma16h(acc[mt][np * 2],     aF[mt], bF[np][0], bF[np][1]);
                    mma16h(acc[mt][np * 2 + 1], aF[mt], bF[np][2], bF[np][3]);
                }
        }
        __syncthreads();
    }

    // ---- fused epilogue (unchanged) ----
    const int colbase = bn + wn;

    if (colbase < DIMM + KVD) {
        const float g = (colbase < DIMM) ? gain[colbase >> 6] * 0.125f : 1.0f;
        __half* outp  = (colbase < DIMM) ? gqh : gkh;
        const int ost = (colbase < DIMM) ? DIMM : KVD;
        const int oc  = (colbase < DIMM) ? colbase : colbase - DIMM;

        float invf[8];
#pragma unroll
        for (int nt = 0; nt < 4; nt++) {
            int d0 = nt * 8 + 2 * tig;
            invf[2 * nt]     = exp2f(-(float)d0 * ROPE_L2);
            invf[2 * nt + 1] = exp2f(-(float)(d0 + 1) * ROPE_L2);
        }

#pragma unroll
        for (int mt = 0; mt < 2; mt++) {
            const int r0 = bm + wm + mt * 16 + gid;
            const float s0 = (float)(r0 & (SS - 1));
            const float s1 = s0 + 8.0f;

            float ss0 = 0.f, ss1 = 0.f;
#pragma unroll
            for (int nt = 0; nt < 8; nt++) {
                ss0 += acc[mt][nt][0] * acc[mt][nt][0] + acc[mt][nt][1] * acc[mt][nt][1];
                ss1 += acc[mt][nt][2] * acc[mt][nt][2] + acc[mt][nt][3] * acc[mt][nt][3];
            }
            ss0 += __shfl_xor_sync(0xffffffffu, ss0, 1);
            ss0 += __shfl_xor_sync(0xffffffffu, ss0, 2);
            ss1 += __shfl_xor_sync(0xffffffffu, ss1, 1);
            ss1 += __shfl_xor_sync(0xffffffffu, ss1, 2);
            const float rn0 = rsqrtf(ss0 * (1.0f / 64.0f) + 1e-6f);
            const float rn1 = rsqrtf(ss1 * (1.0f / 64.0f) + 1e-6f);

            __half* row0 = outp + (size_t)r0 * ost + oc;
            __half* row1 = row0 + (size_t)8 * ost;

#pragma unroll
            for (int nt = 0; nt < 4; nt++) {
                float c00, sn00, c01, sn01, c10, sn10, c11, sn11;
                sincosf(s0 * invf[2 * nt],     &sn00, &c00);
                sincosf(s0 * invf[2 * nt + 1], &sn01, &c01);
                sincosf(s1 * invf[2 * nt],     &sn10, &c10);
                sincosf(s1 * invf[2 * nt + 1], &sn11, &c11);

                float t1 = acc[mt][nt][0] * rn0, t2 = acc[mt][nt + 4][0] * rn0;
                float u1 = acc[mt][nt][1] * rn0, u2 = acc[mt][nt + 4][1] * rn0;
                float lo0 = ( t1 * c00 + t2 * sn00) * g;
                float hi0 = (-t1 * sn00 + t2 * c00) * g;
                float lo1 = ( u1 * c01 + u2 * sn01) * g;
                float hi1 = (-u1 * sn01 + u2 * c01) * g;
                *(uint32_t*)(row0 + nt * 8 + 2 * tig)       = pack2h(lo0, lo1);
                *(uint32_t*)(row0 + (nt + 4) * 8 + 2 * tig) = pack2h(hi0, hi1);

                float v1 = acc[mt][nt][2] * rn1, v2 = acc[mt][nt + 4][2] * rn1;
                float w1 = acc[mt][nt][3] * rn1, w2 = acc[mt][nt + 4][3] * rn1;
                float lo2 = ( v1 * c10 + v2 * sn10) * g;
                float hi2 = (-v1 * sn10 + v2 * c10) * g;
                float lo3 = ( w1 * c11 + w2 * sn11) * g;
                float hi3 = (-w1 * sn11 + w2 * c11) * g;
                *(uint32_t*)(row1 + nt * 8 + 2 * tig)       = pack2h(lo2, lo3);
                *(uint32_t*)(row1 + (nt + 4) * 8 + 2 * tig) = pack2h(hi2, hi3);
            }
        }
    } else {
        const int oc = colbase - (DIMM + KVD);
#pragma unroll
        for (int mt = 0; mt < 2; mt++) {
            const int r0 = bm + wm + mt * 16 + gid;
            __half* row0 = gvh + (size_t)r0 * KVD + oc;
            __half* row1 = row0 + (size_t)8 * KVD;
#pragma unroll
            for (int nt = 0; nt < 8; nt++) {
                *(uint32_t*)(row0 + nt * 8 + 2 * tig) = pack2h(acc[mt][nt][0], acc[mt][nt][1]);
                *(uint32_t*)(row1 + nt * 8 + 2 * tig) = pack2h(acc[mt][nt][2], acc[mt][nt][3]);
            }
        }
    }
}

// ---------------------------------------------------------------------------
// Plain FP16 GEMM (fp32 out), BK=32 — output projection.
// ---------------------------------------------------------------------------
__global__ void __launch_bounds__(256)
gemm_fp16_kernel(const __half* __restrict__ Ahg, const __half* __restrict__ Bhg,
                 float* __restrict__ C, int M, int N, int K)
{
    __shared__ __half Ah[2][128 * GST2], Bh[2][128 * GST2];   // 40960 B

    const int tid  = threadIdx.x;
    const int lane = tid & 31;
    const int wid  = tid >> 5;
    const int wm   = (wid & 3) * 32;
    const int wn   = (wid >> 2) * 64;
    const int gid  = lane >> 2;
    const int tig  = lane & 3;
    const int bm   = blockIdx.y * 128;
    const int bn   = blockIdx.x * 128;

    const int lrow0 = tid >> 2;
    const int lch0  = (tid & 3) * 8;
    const int lrow1 = lrow0 + 64;

    const __half* ArowA = Ahg + (size_t)(bm + lrow0) * K + lch0;
    const __half* ArowB = Ahg + (size_t)(bm + lrow1) * K + lch0;
    const __half* BrowA = Bhg + (size_t)(bn + lrow0) * K + lch0;
    const __half* BrowB = Bhg + (size_t)(bn + lrow1) * K + lch0;
    const int soffA = lrow0 * GST2 + lch0;
    const int soffB = lrow1 * GST2 + lch0;

    const int tl = lane >> 3, lr = lane & 7;
    const int a_row = lr + ((tl & 1) ? 8 : 0);
    const int a_kb  = (tl >= 2) ? 16 : 0;
    const int b_row = lr + ((tl >= 2) ? 8 : 0);
    const int b_kb  = (tl & 1) ? 16 : 0;

    uint32_t aAddr[2][2], bAddr[2][4];
#pragma unroll
    for (int s = 0; s < 2; s++) {
#pragma unroll
        for (int mt = 0; mt < 2; mt++) {
            int r = wm + mt * 16 + a_row;
            aAddr[s][mt] = (uint32_t)__cvta_generic_to_shared(&Ah[s][r * GST2]) + a_kb;
        }
#pragma unroll
        for (int np = 0; np < 4; np++) {
            int r = wn + np * 16 + b_row;
            bAddr[s][np] = (uint32_t)__cvta_generic_to_shared(&Bh[s][r * GST2]) + b_kb;
        }
    }

    float acc[2][8][4];
#pragma unroll
    for (int i = 0; i < 2; i++)
#pragma unroll
        for (int j = 0; j < 8; j++)
#pragma unroll
            for (int c = 0; c < 4; c++) acc[i][j][c] = 0.f;

    const int T = K / 32;

    cp16(&Ah[0][soffA], ArowA);
    cp16(&Ah[0][soffB], ArowB);
    cp16(&Bh[0][soffA], BrowA);
    cp16(&Bh[0][soffB], BrowB);
    asm volatile("cp.async.commit_group;\n");

    for (int t = 0; t < T; t++) {
        if (t + 1 < T) {
            const int s = (t + 1) & 1, k0 = (t + 1) * 32;
            cp16(&Ah[s][soffA], ArowA + k0);
            cp16(&Ah[s][soffB], ArowB + k0);
            cp16(&Bh[s][soffA], BrowA + k0);
            cp16(&Bh[s][soffB], BrowB + k0);
            asm volatile("cp.async.commit_group;\n");
            asm volatile("cp.async.wait_group 1;\n");
        } else {
            asm volatile("cp.async.wait_group 0;\n");
        }
        __syncthreads();

        const int cb = t & 1;
#pragma unroll
        for (int ks = 0; ks < 2; ks++) {
            const uint32_t kofs = (uint32_t)(ks * 32);
            uint32_t aF[2][4], bF[4][4];
#pragma unroll
            for (int mt = 0; mt < 2; mt++) ldsm4(aF[mt], aAddr[cb][mt] + kofs);
#pragma unroll
            for (int np = 0; np < 4; np++) ldsm4(bF[np], bAddr[cb][np] + kofs);
#pragma unroll
            for (int mt = 0; mt < 2; mt++)
#pragma unroll
                for (int np = 0; np < 4; np++) {
                    mma16h(acc[mt][np * 2],     aF[mt], bF[np][0], bF[np][1]);
                    mma16h(acc[mt][np * 2 + 1], aF[mt], bF[np][2], bF[np][3]);
                }
        }
        __syncthreads();
    }

#pragma unroll
    for (int mt = 0; mt < 2; mt++) {
        const int row0 = bm + wm + mt * 16 + gid;
#pragma unroll
        for (int nt = 0; nt < 8; nt++) {
            const int col = bn + wn + nt * 8 + tig * 2;
            *(float2*)&C[(size_t)row0 * N + col]       = make_float2(acc[mt][nt][0], acc[mt][nt][1]);
            *(float2*)&C[(size_t)(row0 + 8) * N + col] = make_float2(acc[mt][nt][2], acc[mt][nt][3]);
        }
    }
}

// ---------------------------------------------------------------------------
// Causal GQA flash attention — unchanged from R15 best.
// ---------------------------------------------------------------------------
#define KHST 72
#define TROWS 32
#define TSZ (TROWS * KHST)

__global__ void __launch_bounds__(256)
attn_tc_kernel(const __half* __restrict__ gqh, const __half* __restrict__ gkh,
               const __half* __restrict__ gvh, __half* __restrict__ gyh)
{
    __shared__ __half kh[3][TSZ], vh[3][TSZ];

    const int tid = threadIdx.x, lane = tid & 31, wid = tid >> 5;
    const int gid = lane >> 2, tig = lane & 3;
    const int qb = (gridDim.x - 1) - blockIdx.x;
    const int h = blockIdx.y, b = blockIdx.z;
    const int kvh = h >> 2;
    const int wm = wid * 16;
    const int qrow = qb * 128 + wm;

    uint32_t qh_[4][4];
    {
        const size_t r0 = (size_t)(b * SS + qrow + gid    ) * DIMM + h * 64 + 2 * tig;
        const size_t r1 = (size_t)(b * SS + qrow + gid + 8) * DIMM + h * 64 + 2 * tig;
#pragma unroll
        for (int kc = 0; kc < 4; kc++) {
            qh_[kc][0] = *(const uint32_t*)(gqh + r0 + kc * 16);
            qh_[kc][1] = *(const uint32_t*)(gqh + r1 + kc * 16);
            qh_[kc][2] = *(const uint32_t*)(gqh + r0 + kc * 16 + 8);
            qh_[kc][3] = *(const uint32_t*)(gqh + r1 + kc * 16 + 8);
        }
    }

    const int lrow = tid >> 3;
    const int lch  = (tid & 7) * 8;
    const int soff = lrow * KHST + lch;

    const uint32_t vrow = (lane & 7) + 8 * ((lane >> 3) & 1);
    const uint32_t vcolB = (lane >> 4) * 16;
    uint32_t vbase[3];
#pragma unroll
    for (int s = 0; s < 3; s++)
        vbase[s] = (uint32_t)__cvta_generic_to_shared(&vh[s][0]) + vrow * (KHST * 2) + vcolB;

    float m0 = -INFINITY, m1 = -INFINITY, l0 = 0.f, l1 = 0.f;
    float acc[8][4];
#pragma unroll
    for (int nd = 0; nd < 8; nd++)
#pragma unroll
        for (int c = 0; c < 4; c++) acc[nd][c] = 0.f;

    const int ntiles = 4 * qb + 4;
    const size_t kvbase = (size_t)(b * SS) * KVD + kvh * 64 + (size_t)lrow * KVD + lch;

    {
        size_t go = kvbase;
        cp16(&kh[0][soff], gkh + go);
        cp16(&vh[0][soff], gvh + go);
        asm volatile("cp.async.commit_group;\n");
    }

    for (int kt = 0; kt < ntiles; kt++) {
        if (kt + 1 < ntiles) {
            const int s = (kt + 1) % 3;
            size_t go = kvbase + (size_t)(kt + 1) * TROWS * KVD;
            cp16(&kh[s][soff], gkh + go);
            cp16(&vh[s][soff], gvh + go);
            asm volatile("cp.async.commit_group;\n");
            asm volatile("cp.async.wait_group 1;\n");
        } else {
            asm volatile("cp.async.wait_group 0;\n");
        }
        __syncthreads();

        const int keybase = kt * 32;
        if (keybase > qrow + 15) continue;

        const int cb = kt % 3;

        float sc[4][4];
#pragma unroll
        for (int nt = 0; nt < 4; nt++)
#pragma unroll
            for (int c = 0; c < 4; c++) sc[nt][c] = 0.f;

#pragma unroll
        for (int kc = 0; kc < 4; kc++) {
#pragma unroll
            for (int nt = 0; nt < 4; nt++) {
                const __half* krh = &kh[cb][(nt * 8 + gid) * KHST + kc * 16 + 2 * tig];
                uint32_t bh0 = *(const uint32_t*)krh;
                uint32_t bh1 = *(const uint32_t*)(krh + 8);
                mma16h(sc[nt], qh_[kc], bh0, bh1);
            }
        }

        if (keybase + 31 > qrow) {
            const int off = keybase - qrow;
#pragma unroll
            for (int nt = 0; nt < 4; nt++) {
                int c0 = off + nt * 8 + 2 * tig;
                if (c0     > gid)     sc[nt][0] = -INFINITY;
                if (c0 + 1 > gid)     sc[nt][1] = -INFINITY;
                if (c0     > gid + 8) sc[nt][2] = -INFINITY;
                if (c0 + 1 > gid + 8) sc[nt][3] = -INFINITY;
            }
        }

        float mt0 = m0, mt1 = m1;
#pragma unroll
        for (int nt = 0; nt < 4; nt++) {
            mt0 = fmaxf(mt0, fmaxf(sc[nt][0], sc[nt][1]));
            mt1 = fmaxf(mt1, fmaxf(sc[nt][2], sc[nt][3]));
        }
        mt0 = fmaxf(mt0, __shfl_xor_sync(0xffffffffu, mt0, 1));
        mt0 = fmaxf(mt0, __shfl_xor_sync(0xffffffffu, mt0, 2));
        mt1 = fmaxf(mt1, __shfl_xor_sync(0xffffffffu, mt1, 1));
        mt1 = fmaxf(mt1, __shfl_xor_sync(0xffffffffu, mt1, 2));

        float corr0 = __expf(m0 - mt0);
        float corr1 = __expf(m1 - mt1);
        m0 = mt0; m1 = mt1;
        l0 *= corr0; l1 *= corr1;
#pragma unroll
        for (int nd = 0; nd < 8; nd++) {
            acc[nd][0] *= corr0; acc[nd][1] *= corr0;
            acc[nd][2] *= corr1; acc[nd][3] *= corr1;
        }

#pragma unroll
        for (int nt = 0; nt < 4; nt++) {
            sc[nt][0] = __expf(sc[nt][0] - mt0);
            sc[nt][1] = __expf(sc[nt][1] - mt0);
            sc[nt][2] = __expf(sc[nt][2] - mt1);
            sc[nt][3] = __expf(sc[nt][3] - mt1);
            l0 += sc[nt][0] + sc[nt][1];
            l1 += sc[nt][2] + sc[nt][3];
        }

#pragma unroll
        for (int kc = 0; kc < 2; kc++) {
            uint32_t pfh[4];
            pfh[0] = pack2h(sc[2 * kc][0],     sc[2 * kc][1]);
            pfh[1] = pack2h(sc[2 * kc][2],     sc[2 * kc][3]);
            pfh[2] = pack2h(sc[2 * kc + 1][0], sc[2 * kc + 1][1]);
            pfh[3] = pack2h(sc[2 * kc + 1][2], sc[2 * kc + 1][3]);
#pragma unroll
            for (int ndp = 0; ndp < 4; ndp++) {
                uint32_t r0, r1, r2, r3;
                ldsm4t(r0, r1, r2, r3, vbase[cb] + (uint32_t)(kc * 16 * (KHST * 2) + ndp * 32));
                mma16h(acc[ndp * 2],     pfh, r0, r1);
                mma16h(acc[ndp * 2 + 1], pfh, r2, r3);
            }
        }
    }

    l0 += __shfl_xor_sync(0xffffffffu, l0, 1);
    l0 += __shfl_xor_sync(0xffffffffu, l0, 2);
    l1 += __shfl_xor_sync(0xffffffffu, l1, 1);
    l1 += __shfl_xor_sync(0xffffffffu, l1, 2);
    const float inv0 = 1.f / l0;
    const float inv1 = 1.f / l1;

    const size_t o0 = (size_t)(b * SS + qrow + gid    ) * DIMM + h * 64 + 2 * tig;
    const size_t o1 = (size_t)(b * SS + qrow + gid + 8) * DIMM + h * 64 + 2 * tig;
#pragma unroll
    for (int nd = 0; nd < 8; nd++) {
        *(uint32_t*)(gyh + o0 + nd * 8) = pack2h(acc[nd][0] * inv0, acc[nd][1] * inv0);
        *(uint32_t*)(gyh + o1 + nd * 8) = pack2h(acc[nd][2] * inv1, acc[nd][3] * inv1);
    }
}

// ---------------------------------------------------------------------------
extern "C" void kernel_launch(void* const* d_in, const int* in_sizes, int n_in,
                              void* d_out, int out_size)
{
    const float* x  = (const float*)d_in[0];
    const float* Wq = (const float*)d_in[1];
    const float* Wk = (const float*)d_in[2];
    const float* Wv = (const float*)d_in[3];
    const float* Wo = (const float*)d_in[4];
    const float* qg = (const float*)d_in[5];
    float* out = (float*)d_out;

    __half *xh, *wqkvh, *woh, *yh, *qhp, *khp, *vhp;
    cudaGetSymbolAddress((void**)&xh,    g_xh);
    cudaGetSymbolAddress((void**)&wqkvh, g_wqkvh);
    cudaGetSymbolAddress((void**)&woh,   g_woh);
    cudaGetSymbolAddress((void**)&yh,    g_yh);
    cudaGetSymbolAddress((void**)&qhp,   g_qh);
    cudaGetSymbolAddress((void**)&khp,   g_kh);
    cudaGetSymbolAddress((void**)&vhp,   g_vh);

    // operand preparation (fp16)
    conv_h_kernel<<<(MROWS * DIMM / 2 + 255) / 256, 256>>>(x, xh, MROWS * DIMM / 2);
    {
        const int tot = QKVD * DIMM / 2 + DIMM * DIMM / 2;
        conv_w_all_kernel<<<(tot + 255) / 256, 256>>>(Wq, Wk, Wv, Wo, wqkvh, woh);
    }

    // fused QKV projection + norm/rope/convert epilogue (BK=32)
    gemm_qkv_fused_kernel<<<dim3(QKVD / 128, MROWS / 128), 256>>>(xh, wqkvh, qg, qhp, khp, vhp);

    // attention (plain fp16 QK and PV)
    attn_tc_kernel<<<dim3(SS / 128, HH, BB), 256>>>(qhp, khp, vhp, yh);

    // output projection (BK=32)
    gemm_fp16_kernel<<<dim3(DIMM / 128, MROWS / 128), 256>>>(yh, woh, out, MROWS, DIMM, DIMM);
}